// round 1
// baseline (speedup 1.0000x reference)
#include <cuda_runtime.h>
#include <math.h>

// ---------------------------------------------------------------------------
// StandardTransformerModel: sliding-window transformer, restructured:
//   * layer-0 QKV computed once per global token (window-invariant)
//   * layer-1 computes only K,V for all tokens; Q/attn_out/FFN/head only for
//     the last token of each window (the only one the output depends on)
// All math fp32. Tensor-core (tcgen05) path planned for later rounds.
// ---------------------------------------------------------------------------

#define BATCH 2
#define SEQ   1024
#define E     256
#define FIN   64
#define FF    1024
#define WCTX  64
#define NW    (BATCH*SEQ)        /* 2048 windows  */
#define PADS  (SEQ + WCTX - 1)   /* 1087 padded positions per batch */
#define NT    (NW*WCTX)          /* 131072 window-tokens */

#define ATTN_SCALE 0.17677669529663687f  /* 1/sqrt(32) */

// ---------------- scratch (static device globals; no runtime allocation) ----
__device__ float g_emb [BATCH*PADS*E];     //  ~2.2 MB (zero-padded embeddings)
__device__ float g_qkv0[BATCH*PADS*3*E];   //  ~6.7 MB
__device__ float g_octx[NT*E];             //  134 MB attn-0 context
__device__ float g_x1a [NT*E];             //  134 MB (pre-LN1, reused as pre-LN2)
__device__ float g_x1  [NT*E];             //  134 MB
__device__ float g_hbuf[134217728];        //  537 MB FFN hidden (NT*FF)
__device__ float g_x2  [NT*E];             //  134 MB layer-0 output
__device__ float g_kv1 [NT*2*E];           //  268 MB layer-1 K,V
__device__ float g_q1  [NW*E];
__device__ float g_o1  [NW*E];
__device__ float g_t1a [NW*E];
__device__ float g_t1  [NW*E];
__device__ float g_th  [NW*FF];
__device__ float g_t2  [NW*E];

// ---------------- zero the left-pad rows of the embedding buffer ------------
__global__ void zero_pad_k(float* emb) {
    int i = blockIdx.x * 256 + threadIdx.x;
    if (i < (WCTX - 1) * E) {
        emb[i] = 0.f;
        emb[(size_t)PADS * E + i] = 0.f;
    }
}

// ---------------- generic register-blocked SGEMM ----------------------------
// C[M,N] = act( A[M,K] @ W[N,K]^T + bias + residual )
// ACT: 0 none, 1 silu.  RES: 0 none, 1 res[m*ldres+n], 2 window->emb gather.
template<int ACT, int RES>
__global__ void __launch_bounds__(256) gemm_k(
    const float* __restrict__ A, int lda,
    const float* __restrict__ Wt, int K,
    const float* __restrict__ bias,
    float* __restrict__ C, int ldc,
    const float* __restrict__ res, int ldres,
    int M, int N)
{
    __shared__ float As[16][68];
    __shared__ float Bs[16][68];
    const int tid = threadIdx.x;
    const int m0 = blockIdx.y * 64;
    const int n0 = blockIdx.x * 64;
    const int lr = tid >> 2;          // 0..63 row within tile
    const int lc = (tid & 3) << 2;    // 0,4,8,12
    const int ty = tid >> 4;          // 0..15
    const int tx = tid & 15;          // 0..15

    float acc[4][4];
#pragma unroll
    for (int i = 0; i < 4; i++)
#pragma unroll
        for (int j = 0; j < 4; j++) acc[i][j] = 0.f;

    const int am = m0 + lr;
    const int bn = n0 + lr;
    const float* Aptr = A + (size_t)am * lda + lc;
    const float* Wptr = Wt + (size_t)bn * K + lc;
    const bool avalid = (am < M);
    const bool bvalid = (bn < N);

    for (int k0 = 0; k0 < K; k0 += 16) {
        float4 av = make_float4(0.f, 0.f, 0.f, 0.f);
        float4 bv = make_float4(0.f, 0.f, 0.f, 0.f);
        if (avalid) av = *(const float4*)(Aptr + k0);
        if (bvalid) bv = *(const float4*)(Wptr + k0);
        As[lc+0][lr] = av.x; As[lc+1][lr] = av.y;
        As[lc+2][lr] = av.z; As[lc+3][lr] = av.w;
        Bs[lc+0][lr] = bv.x; Bs[lc+1][lr] = bv.y;
        Bs[lc+2][lr] = bv.z; Bs[lc+3][lr] = bv.w;
        __syncthreads();
#pragma unroll
        for (int kk = 0; kk < 16; kk++) {
            float4 a4 = *(const float4*)&As[kk][ty << 2];
            float4 b4 = *(const float4*)&Bs[kk][tx << 2];
            float ar[4] = {a4.x, a4.y, a4.z, a4.w};
            float br[4] = {b4.x, b4.y, b4.z, b4.w};
#pragma unroll
            for (int i = 0; i < 4; i++)
#pragma unroll
                for (int j = 0; j < 4; j++)
                    acc[i][j] = fmaf(ar[i], br[j], acc[i][j]);
        }
        __syncthreads();
    }

#pragma unroll
    for (int i = 0; i < 4; i++) {
        int m = m0 + (ty << 2) + i;
        if (m >= M) continue;
#pragma unroll
        for (int j = 0; j < 4; j++) {
            int n = n0 + (tx << 2) + j;
            if (n >= N) continue;
            float v = acc[i][j] + bias[n];
            if (RES == 1) v += res[(size_t)m * ldres + n];
            if (RES == 2) {
                int nw = m >> 6, w = m & 63;
                int b  = nw >> 10, s = nw & 1023;
                v += res[((size_t)(b * PADS + s + w)) * ldres + n];
            }
            if (ACT == 1) v = v / (1.f + __expf(-v));
            C[(size_t)m * ldc + n] = v;
        }
    }
}

// ---------------- layer-0 attention: one block per (head, window) -----------
// 64 threads = 64 query rows. K,V head-slices staged in shared memory.
__global__ void __launch_bounds__(64) attn0_k(const float* __restrict__ qkv0,
                                              float* __restrict__ octx) {
    const int h = blockIdx.x;
    const int n = blockIdx.y;
    const int b = n >> 10, s = n & 1023;
    const int t = threadIdx.x;             // query index in window
    __shared__ float Ks[64][33];
    __shared__ float Vs[64][33];

    const float* row = qkv0 + ((size_t)(b * PADS + s + t)) * (3 * E) + h * 32;
    float q[32];
#pragma unroll
    for (int i = 0; i < 8; i++) {
        float4 qv = *(const float4*)(row + i * 4);
        q[i*4+0] = qv.x; q[i*4+1] = qv.y; q[i*4+2] = qv.z; q[i*4+3] = qv.w;
        float4 kv = *(const float4*)(row + E + i * 4);
        Ks[t][i*4+0] = kv.x; Ks[t][i*4+1] = kv.y;
        Ks[t][i*4+2] = kv.z; Ks[t][i*4+3] = kv.w;
        float4 vv = *(const float4*)(row + 2 * E + i * 4);
        Vs[t][i*4+0] = vv.x; Vs[t][i*4+1] = vv.y;
        Vs[t][i*4+2] = vv.z; Vs[t][i*4+3] = vv.w;
    }
    __syncthreads();

    float sc[64];
    float mx = -1e30f;
#pragma unroll 4
    for (int k = 0; k < 64; k++) {
        float a = 0.f;
#pragma unroll
        for (int d = 0; d < 32; d++) a = fmaf(q[d], Ks[k][d], a);
        a *= ATTN_SCALE;
        sc[k] = a;
        mx = fmaxf(mx, a);
    }
    float sum = 0.f;
#pragma unroll 4
    for (int k = 0; k < 64; k++) { sc[k] = __expf(sc[k] - mx); sum += sc[k]; }
    const float inv = 1.f / sum;

    float* out = octx + ((size_t)n * 64 + t) * E + h * 32;
#pragma unroll
    for (int d = 0; d < 32; d++) {
        float a = 0.f;
#pragma unroll 8
        for (int k = 0; k < 64; k++) a = fmaf(sc[k], Vs[k][d], a);
        out[d] = a * inv;
    }
}

// ---------------- layer-1 attention: single query (last token) per window ---
// One block per window; warp h handles head h; lane l covers keys {l, l+32}
// for scores and output dim l for the PV contraction.
__global__ void __launch_bounds__(256) attn1_k(const float* __restrict__ q1,
                                               const float* __restrict__ kv1,
                                               float* __restrict__ o1) {
    const int n = blockIdx.x;
    const int h = threadIdx.x >> 5, l = threadIdx.x & 31;
    __shared__ float qs[256];
    __shared__ float ps[8][64];
    qs[threadIdx.x] = q1[(size_t)n * E + threadIdx.x];
    __syncthreads();

    const float* kvb = kv1 + (size_t)n * 64 * (2 * E);
    const float* qh  = &qs[h * 32];
    const float* k0p = kvb + (size_t)l * (2 * E) + h * 32;
    const float* k1p = kvb + (size_t)(l + 32) * (2 * E) + h * 32;
    float s0 = 0.f, s1 = 0.f;
#pragma unroll
    for (int d = 0; d < 32; d++) {
        s0 = fmaf(qh[d], k0p[d], s0);
        s1 = fmaf(qh[d], k1p[d], s1);
    }
    s0 *= ATTN_SCALE; s1 *= ATTN_SCALE;
    float m = fmaxf(s0, s1);
#pragma unroll
    for (int o = 16; o; o >>= 1) m = fmaxf(m, __shfl_xor_sync(0xffffffffu, m, o));
    float e0 = __expf(s0 - m), e1 = __expf(s1 - m);
    float sum = e0 + e1;
#pragma unroll
    for (int o = 16; o; o >>= 1) sum += __shfl_xor_sync(0xffffffffu, sum, o);
    const float inv = 1.f / sum;
    ps[h][l] = e0 * inv;
    ps[h][l + 32] = e1 * inv;
    __syncwarp();

    float acc = 0.f;
#pragma unroll 4
    for (int k = 0; k < 64; k++)
        acc = fmaf(ps[h][k], kvb[(size_t)k * (2 * E) + E + h * 32 + l], acc);
    o1[(size_t)n * E + h * 32 + l] = acc;
}

// ---------------- LayerNorm over E=256, one warp per row --------------------
__global__ void __launch_bounds__(256) ln_k(const float* __restrict__ X,
                                            const float* __restrict__ g,
                                            const float* __restrict__ bb,
                                            float* __restrict__ Y, int M) {
    const int warp = threadIdx.x >> 5, lane = threadIdx.x & 31;
    const int row = blockIdx.x * 8 + warp;
    if (row >= M) return;
    const float* x = X + (size_t)row * E;
    float v[8];
    float s = 0.f;
#pragma unroll
    for (int i = 0; i < 8; i++) { v[i] = x[lane + i * 32]; s += v[i]; }
#pragma unroll
    for (int o = 16; o; o >>= 1) s += __shfl_xor_sync(0xffffffffu, s, o);
    const float mean = s * (1.f / E);
    float var = 0.f;
#pragma unroll
    for (int i = 0; i < 8; i++) { float d = v[i] - mean; var = fmaf(d, d, var); }
#pragma unroll
    for (int o = 16; o; o >>= 1) var += __shfl_xor_sync(0xffffffffu, var, o);
    const float inv = rsqrtf(var * (1.f / E) + 1e-5f);
    float* y = Y + (size_t)row * E;
#pragma unroll
    for (int i = 0; i < 8; i++) {
        int c = lane + i * 32;
        y[c] = (v[i] - mean) * inv * g[c] + bb[c];
    }
}

// ---------------------------------------------------------------------------
extern "C" void kernel_launch(void* const* d_in, const int* in_sizes, int n_in,
                              void* d_out, int out_size) {
    (void)in_sizes; (void)n_in; (void)out_size;
    const float* inputs     = (const float*)d_in[0];
    const float* embed_w    = (const float*)d_in[1];
    const float* embed_b    = (const float*)d_in[2];
    const float* qkv_w      = (const float*)d_in[3];
    const float* qkv_b      = (const float*)d_in[4];
    const float* attn_out_w = (const float*)d_in[5];
    const float* attn_out_b = (const float*)d_in[6];
    const float* ln1_g      = (const float*)d_in[7];
    const float* ln1_b      = (const float*)d_in[8];
    const float* ffn1_w     = (const float*)d_in[9];
    const float* ffn1_b     = (const float*)d_in[10];
    const float* ffn2_w     = (const float*)d_in[11];
    const float* ffn2_b     = (const float*)d_in[12];
    const float* ln2_g      = (const float*)d_in[13];
    const float* ln2_b      = (const float*)d_in[14];
    const float* head_w     = (const float*)d_in[15];
    const float* head_b     = (const float*)d_in[16];
    float* out = (float*)d_out;

    float *emb, *qkv0, *octx, *x1a, *x1, *hbuf, *x2, *kv1;
    float *q1, *o1, *t1a, *t1, *th, *t2;
    cudaGetSymbolAddress((void**)&emb,  g_emb);
    cudaGetSymbolAddress((void**)&qkv0, g_qkv0);
    cudaGetSymbolAddress((void**)&octx, g_octx);
    cudaGetSymbolAddress((void**)&x1a,  g_x1a);
    cudaGetSymbolAddress((void**)&x1,   g_x1);
    cudaGetSymbolAddress((void**)&hbuf, g_hbuf);
    cudaGetSymbolAddress((void**)&x2,   g_x2);
    cudaGetSymbolAddress((void**)&kv1,  g_kv1);
    cudaGetSymbolAddress((void**)&q1,   g_q1);
    cudaGetSymbolAddress((void**)&o1,   g_o1);
    cudaGetSymbolAddress((void**)&t1a,  g_t1a);
    cudaGetSymbolAddress((void**)&t1,   g_t1);
    cudaGetSymbolAddress((void**)&th,   g_th);
    cudaGetSymbolAddress((void**)&t2,   g_t2);

    // --- embeddings (zero-padded on the left by W-1) ---
    zero_pad_k<<<63, 256>>>(emb);
    for (int b = 0; b < BATCH; b++) {
        gemm_k<0,0><<<dim3(E / 64, SEQ / 64), 256>>>(
            inputs + (size_t)b * SEQ * FIN, FIN, embed_w, FIN, embed_b,
            emb + ((size_t)b * PADS + (WCTX - 1)) * E, E,
            nullptr, 0, SEQ, E);
    }

    // --- layer-0 QKV, once per global (padded) token ---
    gemm_k<0,0><<<dim3(3 * E / 64, (BATCH * PADS + 63) / 64), 256>>>(
        emb, E, qkv_w, E, qkv_b, qkv0, 3 * E, nullptr, 0, BATCH * PADS, 3 * E);

    // --- layer-0 attention per window ---
    attn0_k<<<dim3(8, NW), 64>>>(qkv0, octx);

    // --- layer-0 attn-out + residual(emb gather) -> LN1 ---
    gemm_k<0,2><<<dim3(E / 64, NT / 64), 256>>>(
        octx, E, attn_out_w, E, attn_out_b, x1a, E, emb, E, NT, E);
    ln_k<<<NT / 8, 256>>>(x1a, ln1_g, ln1_b, x1, NT);

    // --- layer-0 FFN (dominant: ~137 GFLOP) ---
    gemm_k<1,0><<<dim3(FF / 64, NT / 64), 256>>>(
        x1, E, ffn1_w, E, ffn1_b, hbuf, FF, nullptr, 0, NT, FF);
    gemm_k<0,1><<<dim3(E / 64, NT / 64), 256>>>(
        hbuf, FF, ffn2_w, FF, ffn2_b, x1a, E, x1, E, NT, E);
    ln_k<<<NT / 8, 256>>>(x1a, ln2_g, ln2_b, x2, NT);

    // --- layer-1: K,V for all tokens; Q only for last token of each window ---
    gemm_k<0,0><<<dim3(2 * E / 64, NT / 64), 256>>>(
        x2, E, qkv_w + (size_t)3 * E * E + (size_t)E * E, E,
        qkv_b + 3 * E + E, kv1, 2 * E, nullptr, 0, NT, 2 * E);
    gemm_k<0,0><<<dim3(E / 64, NW / 64), 256>>>(
        x2 + (size_t)(WCTX - 1) * E, WCTX * E,
        qkv_w + (size_t)3 * E * E, E, qkv_b + 3 * E,
        q1, E, nullptr, 0, NW, E);

    attn1_k<<<NW, 256>>>(q1, kv1, o1);

    // --- layer-1 tail (last tokens only) ---
    gemm_k<0,1><<<dim3(E / 64, NW / 64), 256>>>(
        o1, E, attn_out_w + (size_t)E * E, E, attn_out_b + E,
        t1a, E, x2 + (size_t)(WCTX - 1) * E, WCTX * E, NW, E);
    ln_k<<<NW / 8, 256>>>(t1a, ln1_g + E, ln1_b + E, t1, NW);
    gemm_k<1,0><<<dim3(FF / 64, NW / 64), 256>>>(
        t1, E, ffn1_w + (size_t)FF * E, E, ffn1_b + FF, th, FF,
        nullptr, 0, NW, FF);
    gemm_k<0,1><<<dim3(E / 64, NW / 64), 256>>>(
        th, FF, ffn2_w + (size_t)E * FF, FF, ffn2_b + E, t1a, E, t1, E, NW, E);
    ln_k<<<NW / 8, 256>>>(t1a, ln2_g + E, ln2_b + E, t2, NW);

    // --- head ---
    gemm_k<0,0><<<dim3(1, NW / 64), 256>>>(
        t2, E, head_w, E, head_b, out, 10, nullptr, 0, NW, 10);
}

// round 3
// speedup vs baseline: 2.3870x; 2.3870x over previous
#include <cuda_runtime.h>
#include <math.h>
#include <stdint.h>

// ---------------------------------------------------------------------------
// Round 3: tf32 tensor-core GEMMs (mma.sync m16n8k8), lambda-free (R2 failed
// to compile due to nvcc lambda/array-decl issue). Structure from R1:
// layer-0 QKV per global token; layer-1 last-token-only tail.
// ---------------------------------------------------------------------------

#define BATCH 2
#define SEQ   1024
#define E     256
#define FIN   64
#define FF    1024
#define WCTX  64
#define NW    (BATCH*SEQ)
#define PADS  (SEQ + WCTX - 1)
#define NT    (NW*WCTX)

#define ATTN_SCALE 0.17677669529663687f

// ---------------- scratch ----------------------------------------------------
__device__ __align__(128) float g_emb [BATCH*PADS*E];
__device__ __align__(128) float g_qkv0[BATCH*PADS*3*E];
__device__ __align__(128) float g_octx[NT*E];
__device__ __align__(128) float g_x1a [NT*E];
__device__ __align__(128) float g_x1  [NT*E];
__device__ __align__(128) float g_hbuf[134217728];
__device__ __align__(128) float g_x2  [NT*E];
__device__ __align__(128) float g_kv1 [NT*2*E];
__device__ __align__(128) float g_q1  [NW*E];
__device__ __align__(128) float g_o1  [NW*E];
__device__ __align__(128) float g_t1a [NW*E];
__device__ __align__(128) float g_t1  [NW*E];
__device__ __align__(128) float g_th  [NW*FF];
__device__ __align__(128) float g_t2  [NW*E];

__global__ void zero_pad_k(float* emb) {
    int i = blockIdx.x * 256 + threadIdx.x;
    if (i < (WCTX - 1) * E) {
        emb[i] = 0.f;
        emb[(size_t)PADS * E + i] = 0.f;
    }
}

// ---------------- tf32 tensor-core GEMM --------------------------------------
// C[M,N] = act( A[M,K] @ W[N,K]^T + bias + residual )
// BM=128, BN=128, BK=32, 256 threads, 2-stage cp.async pipeline.
// Requires N%128==0, K%32==0. M guarded.

#define SMLD 36                      /* smem row stride (floats): conflict-free */
#define TS   (128*SMLD)              /* floats per tile stage */
#define TSB  (TS*4)                  /* bytes  per tile stage */
#define GEMM_SMEM (4*TSB)            /* A0,A1,B0,B1 = 73728 bytes */

#define MMA_TF32(d, a0, a1, a2, a3, b0, b1) \
  asm volatile("mma.sync.aligned.m16n8k8.row.col.f32.tf32.tf32.f32 " \
    "{%0,%1,%2,%3}, {%4,%5,%6,%7}, {%8,%9}, {%0,%1,%2,%3};" \
    : "+f"(d[0]), "+f"(d[1]), "+f"(d[2]), "+f"(d[3]) \
    : "r"(a0), "r"(a1), "r"(a2), "r"(a3), "r"(b0), "r"(b1))

#define LOAD_TILE(KT_IDX, ST) do {                                            \
    const unsigned abase_ = smbase + (unsigned)(ST) * TSB;                    \
    const unsigned bbase_ = smbase + 2u * TSB + (unsigned)(ST) * TSB;         \
    const float* Ak_ = A + (KT_IDX) * 32;                                     \
    const float* Bk_ = Wt + (KT_IDX) * 32;                                    \
    _Pragma("unroll")                                                         \
    for (int i_ = 0; i_ < 4; i_++) {                                          \
        const int c_   = tid + 256 * i_;                                      \
        const int row_ = c_ >> 3;                                             \
        const int col_ = (c_ & 7) << 2;                                       \
        const int am_  = bm0 + row_;                                          \
        const float* sa_ = Ak_ + (size_t)(am_ < M ? am_ : 0) * lda + col_;    \
        const int sz_    = (am_ < M) ? 16 : 0;                                \
        asm volatile("cp.async.cg.shared.global [%0], [%1], 16, %2;" ::       \
            "r"(abase_ + (unsigned)(row_ * SMLD + col_) * 4), "l"(sa_), "r"(sz_)); \
        const float* sb_ = Bk_ + (size_t)(bn0 + row_) * K + col_;             \
        asm volatile("cp.async.cg.shared.global [%0], [%1], 16;" ::           \
            "r"(bbase_ + (unsigned)(row_ * SMLD + col_) * 4), "l"(sb_));      \
    }                                                                         \
    asm volatile("cp.async.commit_group;");                                   \
} while (0)

#define COMPUTE_TILE(ST) do {                                                 \
    const float* Asf_ = smf + (ST) * TS;                                      \
    const float* Bsf_ = smf + 2 * TS + (ST) * TS;                             \
    _Pragma("unroll")                                                         \
    for (int kk_ = 0; kk_ < 4; kk_++) {                                       \
        const int k0_ = kk_ * 8;                                              \
        unsigned Areg[4][4];                                                  \
        unsigned Breg[4][2];                                                  \
        _Pragma("unroll")                                                     \
        for (int mt_ = 0; mt_ < 4; mt_++) {                                   \
            const float* p_ = Asf_ + (wm + mt_ * 16 + gid) * SMLD + k0_ + tig;\
            Areg[mt_][0] = __float_as_uint(p_[0]);                            \
            Areg[mt_][1] = __float_as_uint(p_[8 * SMLD]);                     \
            Areg[mt_][2] = __float_as_uint(p_[4]);                            \
            Areg[mt_][3] = __float_as_uint(p_[8 * SMLD + 4]);                 \
        }                                                                     \
        _Pragma("unroll")                                                     \
        for (int nt_ = 0; nt_ < 4; nt_++) {                                   \
            const float* p_ = Bsf_ + (wn + nt_ * 8 + gid) * SMLD + k0_ + tig; \
            Breg[nt_][0] = __float_as_uint(p_[0]);                            \
            Breg[nt_][1] = __float_as_uint(p_[4]);                            \
        }                                                                     \
        _Pragma("unroll")                                                     \
        for (int mt_ = 0; mt_ < 4; mt_++)                                     \
            _Pragma("unroll")                                                 \
            for (int nt_ = 0; nt_ < 4; nt_++)                                 \
                MMA_TF32(acc[mt_][nt_], Areg[mt_][0], Areg[mt_][1],           \
                         Areg[mt_][2], Areg[mt_][3], Breg[nt_][0], Breg[nt_][1]); \
    }                                                                         \
} while (0)

template<int ACT, int RES>
__global__ void __launch_bounds__(256) gemm_tf32(
    const float* __restrict__ A, int lda,
    const float* __restrict__ Wt, int K,
    const float* __restrict__ bias,
    float* __restrict__ C, int ldc,
    const float* __restrict__ res, int ldres,
    int M, int N)
{
    extern __shared__ float smf[];
    const int tid  = threadIdx.x;
    const int bm0  = blockIdx.y * 128;
    const int bn0  = blockIdx.x * 128;
    const int lane = tid & 31, warp = tid >> 5;
    const int wm = (warp & 1) * 64;        // 2 warps along M (64 rows each)
    const int wn = (warp >> 1) * 32;       // 4 warps along N (32 cols each)
    const int gid = lane >> 2, tig = lane & 3;

    const unsigned smbase = (unsigned)__cvta_generic_to_shared(smf);

    float acc[4][4][4];
#pragma unroll
    for (int i = 0; i < 4; i++)
#pragma unroll
        for (int j = 0; j < 4; j++)
#pragma unroll
            for (int r = 0; r < 4; r++) acc[i][j][r] = 0.f;

    const int KT = K >> 5;

    LOAD_TILE(0, 0);
    for (int kt = 0; kt < KT; kt++) {
        if (kt + 1 < KT) {
            LOAD_TILE(kt + 1, (kt + 1) & 1);
            asm volatile("cp.async.wait_group 1;");
        } else {
            asm volatile("cp.async.wait_group 0;");
        }
        __syncthreads();
        COMPUTE_TILE(kt & 1);
        __syncthreads();
    }

    // epilogue
#pragma unroll
    for (int mt = 0; mt < 4; mt++) {
        const int mbase = bm0 + wm + mt * 16 + gid;
#pragma unroll
        for (int half = 0; half < 2; half++) {
            const int m = mbase + half * 8;
            if (m >= M) continue;
#pragma unroll
            for (int nt = 0; nt < 4; nt++) {
                const int n = bn0 + wn + nt * 8 + tig * 2;
                const float2 bv = *(const float2*)(bias + n);
                float v0 = acc[mt][nt][half * 2 + 0] + bv.x;
                float v1 = acc[mt][nt][half * 2 + 1] + bv.y;
                if (RES == 1) {
                    const float2 r = *(const float2*)(res + (size_t)m * ldres + n);
                    v0 += r.x; v1 += r.y;
                }
                if (RES == 2) {
                    const int nw = m >> 6, w = m & 63;
                    const int b = nw >> 10, s = nw & 1023;
                    const float* rp = res + ((size_t)(b * PADS + s + w)) * ldres + n;
                    v0 += rp[0]; v1 += rp[1];
                }
                if (ACT == 1) {
                    v0 = v0 / (1.f + __expf(-v0));
                    v1 = v1 / (1.f + __expf(-v1));
                }
                *(float2*)(C + (size_t)m * ldc + n) = make_float2(v0, v1);
            }
        }
    }
}

// ---------------- small fp32 GEMM (head only, N=10) --------------------------
template<int ACT, int RES>
__global__ void __launch_bounds__(256) gemm_k(
    const float* __restrict__ A, int lda,
    const float* __restrict__ Wt, int K,
    const float* __restrict__ bias,
    float* __restrict__ C, int ldc,
    const float* __restrict__ res, int ldres,
    int M, int N)
{
    __shared__ float As[16][68];
    __shared__ float Bs[16][68];
    const int tid = threadIdx.x;
    const int m0 = blockIdx.y * 64;
    const int n0 = blockIdx.x * 64;
    const int lr = tid >> 2;
    const int lc = (tid & 3) << 2;
    const int ty = tid >> 4;
    const int tx = tid & 15;

    float acc[4][4];
#pragma unroll
    for (int i = 0; i < 4; i++)
#pragma unroll
        for (int j = 0; j < 4; j++) acc[i][j] = 0.f;

    const int am = m0 + lr;
    const int bn = n0 + lr;
    const float* Aptr = A + (size_t)am * lda + lc;
    const float* Wptr = Wt + (size_t)bn * K + lc;
    const bool avalid = (am < M);
    const bool bvalid = (bn < N);

    for (int k0 = 0; k0 < K; k0 += 16) {
        float4 av = make_float4(0.f, 0.f, 0.f, 0.f);
        float4 bv = make_float4(0.f, 0.f, 0.f, 0.f);
        if (avalid) av = *(const float4*)(Aptr + k0);
        if (bvalid) bv = *(const float4*)(Wptr + k0);
        As[lc+0][lr] = av.x; As[lc+1][lr] = av.y;
        As[lc+2][lr] = av.z; As[lc+3][lr] = av.w;
        Bs[lc+0][lr] = bv.x; Bs[lc+1][lr] = bv.y;
        Bs[lc+2][lr] = bv.z; Bs[lc+3][lr] = bv.w;
        __syncthreads();
#pragma unroll
        for (int kk = 0; kk < 16; kk++) {
            float4 a4 = *(const float4*)&As[kk][ty << 2];
            float4 b4 = *(const float4*)&Bs[kk][tx << 2];
            float ar[4] = {a4.x, a4.y, a4.z, a4.w};
            float br[4] = {b4.x, b4.y, b4.z, b4.w};
#pragma unroll
            for (int i = 0; i < 4; i++)
#pragma unroll
                for (int j = 0; j < 4; j++)
                    acc[i][j] = fmaf(ar[i], br[j], acc[i][j]);
        }
        __syncthreads();
    }

#pragma unroll
    for (int i = 0; i < 4; i++) {
        int m = m0 + (ty << 2) + i;
        if (m >= M) continue;
#pragma unroll
        for (int j = 0; j < 4; j++) {
            int n = n0 + (tx << 2) + j;
            if (n >= N) continue;
            float v = acc[i][j] + bias[n];
            if (RES == 1) v += res[(size_t)m * ldres + n];
            if (ACT == 1) v = v / (1.f + __expf(-v));
            C[(size_t)m * ldc + n] = v;
        }
    }
}

// ---------------- layer-0 attention ------------------------------------------
__global__ void __launch_bounds__(64) attn0_k(const float* __restrict__ qkv0,
                                              float* __restrict__ octx) {
    const int h = blockIdx.x;
    const int n = blockIdx.y;
    const int b = n >> 10, s = n & 1023;
    const int t = threadIdx.x;
    __shared__ float Ks[64][33];
    __shared__ float Vs[64][33];

    const float* row = qkv0 + ((size_t)(b * PADS + s + t)) * (3 * E) + h * 32;
    float q[32];
#pragma unroll
    for (int i = 0; i < 8; i++) {
        float4 qv = *(const float4*)(row + i * 4);
        q[i*4+0] = qv.x; q[i*4+1] = qv.y; q[i*4+2] = qv.z; q[i*4+3] = qv.w;
        float4 kv = *(const float4*)(row + E + i * 4);
        Ks[t][i*4+0] = kv.x; Ks[t][i*4+1] = kv.y;
        Ks[t][i*4+2] = kv.z; Ks[t][i*4+3] = kv.w;
        float4 vv = *(const float4*)(row + 2 * E + i * 4);
        Vs[t][i*4+0] = vv.x; Vs[t][i*4+1] = vv.y;
        Vs[t][i*4+2] = vv.z; Vs[t][i*4+3] = vv.w;
    }
    __syncthreads();

    float sc[64];
    float mx = -1e30f;
#pragma unroll 4
    for (int k = 0; k < 64; k++) {
        float a = 0.f;
#pragma unroll
        for (int d = 0; d < 32; d++) a = fmaf(q[d], Ks[k][d], a);
        a *= ATTN_SCALE;
        sc[k] = a;
        mx = fmaxf(mx, a);
    }
    float sum = 0.f;
#pragma unroll 4
    for (int k = 0; k < 64; k++) { sc[k] = __expf(sc[k] - mx); sum += sc[k]; }
    const float inv = 1.f / sum;

    float* out = octx + ((size_t)n * 64 + t) * E + h * 32;
#pragma unroll
    for (int d = 0; d < 32; d++) {
        float a = 0.f;
#pragma unroll 8
        for (int k = 0; k < 64; k++) a = fmaf(sc[k], Vs[k][d], a);
        out[d] = a * inv;
    }
}

// ---------------- layer-1 attention (single query per window) ----------------
__global__ void __launch_bounds__(256) attn1_k(const float* __restrict__ q1,
                                               const float* __restrict__ kv1,
                                               float* __restrict__ o1) {
    const int n = blockIdx.x;
    const int h = threadIdx.x >> 5, l = threadIdx.x & 31;
    __shared__ float qs[256];
    __shared__ float ps[8][64];
    qs[threadIdx.x] = q1[(size_t)n * E + threadIdx.x];
    __syncthreads();

    const float* kvb = kv1 + (size_t)n * 64 * (2 * E);
    const float* qh  = &qs[h * 32];
    const float* k0p = kvb + (size_t)l * (2 * E) + h * 32;
    const float* k1p = kvb + (size_t)(l + 32) * (2 * E) + h * 32;
    float s0 = 0.f, s1 = 0.f;
#pragma unroll
    for (int d = 0; d < 32; d++) {
        s0 = fmaf(qh[d], k0p[d], s0);
        s1 = fmaf(qh[d], k1p[d], s1);
    }
    s0 *= ATTN_SCALE; s1 *= ATTN_SCALE;
    float m = fmaxf(s0, s1);
#pragma unroll
    for (int o = 16; o; o >>= 1) m = fmaxf(m, __shfl_xor_sync(0xffffffffu, m, o));
    float e0 = __expf(s0 - m), e1 = __expf(s1 - m);
    float sum = e0 + e1;
#pragma unroll
    for (int o = 16; o; o >>= 1) sum += __shfl_xor_sync(0xffffffffu, sum, o);
    const float inv = 1.f / sum;
    ps[h][l] = e0 * inv;
    ps[h][l + 32] = e1 * inv;
    __syncwarp();

    float acc = 0.f;
#pragma unroll 4
    for (int k = 0; k < 64; k++)
        acc = fmaf(ps[h][k], kvb[(size_t)k * (2 * E) + E + h * 32 + l], acc);
    o1[(size_t)n * E + h * 32 + l] = acc;
}

// ---------------- LayerNorm --------------------------------------------------
__global__ void __launch_bounds__(256) ln_k(const float* __restrict__ X,
                                            const float* __restrict__ g,
                                            const float* __restrict__ bb,
                                            float* __restrict__ Y, int M) {
    const int warp = threadIdx.x >> 5, lane = threadIdx.x & 31;
    const int row = blockIdx.x * 8 + warp;
    if (row >= M) return;
    const float* x = X + (size_t)row * E;
    float v[8];
    float s = 0.f;
#pragma unroll
    for (int i = 0; i < 8; i++) { v[i] = x[lane + i * 32]; s += v[i]; }
#pragma unroll
    for (int o = 16; o; o >>= 1) s += __shfl_xor_sync(0xffffffffu, s, o);
    const float mean = s * (1.f / E);
    float var = 0.f;
#pragma unroll
    for (int i = 0; i < 8; i++) { float d = v[i] - mean; var = fmaf(d, d, var); }
#pragma unroll
    for (int o = 16; o; o >>= 1) var += __shfl_xor_sync(0xffffffffu, var, o);
    const float inv = rsqrtf(var * (1.f / E) + 1e-5f);
    float* y = Y + (size_t)row * E;
#pragma unroll
    for (int i = 0; i < 8; i++) {
        int c = lane + i * 32;
        y[c] = (v[i] - mean) * inv * g[c] + bb[c];
    }
}

// ---------------------------------------------------------------------------
extern "C" void kernel_launch(void* const* d_in, const int* in_sizes, int n_in,
                              void* d_out, int out_size) {
    (void)in_sizes; (void)n_in; (void)out_size;
    const float* inputs     = (const float*)d_in[0];
    const float* embed_w    = (const float*)d_in[1];
    const float* embed_b    = (const float*)d_in[2];
    const float* qkv_w      = (const float*)d_in[3];
    const float* qkv_b      = (const float*)d_in[4];
    const float* attn_out_w = (const float*)d_in[5];
    const float* attn_out_b = (const float*)d_in[6];
    const float* ln1_g      = (const float*)d_in[7];
    const float* ln1_b      = (const float*)d_in[8];
    const float* ffn1_w     = (const float*)d_in[9];
    const float* ffn1_b     = (const float*)d_in[10];
    const float* ffn2_w     = (const float*)d_in[11];
    const float* ffn2_b     = (const float*)d_in[12];
    const float* ln2_g      = (const float*)d_in[13];
    const float* ln2_b      = (const float*)d_in[14];
    const float* head_w     = (const float*)d_in[15];
    const float* head_b     = (const float*)d_in[16];
    float* out = (float*)d_out;

    float *emb, *qkv0, *octx, *x1a, *x1, *hbuf, *x2, *kv1;
    float *q1, *o1, *t1a, *t1, *th, *t2;
    cudaGetSymbolAddress((void**)&emb,  g_emb);
    cudaGetSymbolAddress((void**)&qkv0, g_qkv0);
    cudaGetSymbolAddress((void**)&octx, g_octx);
    cudaGetSymbolAddress((void**)&x1a,  g_x1a);
    cudaGetSymbolAddress((void**)&x1,   g_x1);
    cudaGetSymbolAddress((void**)&hbuf, g_hbuf);
    cudaGetSymbolAddress((void**)&x2,   g_x2);
    cudaGetSymbolAddress((void**)&kv1,  g_kv1);
    cudaGetSymbolAddress((void**)&q1,   g_q1);
    cudaGetSymbolAddress((void**)&o1,   g_o1);
    cudaGetSymbolAddress((void**)&t1a,  g_t1a);
    cudaGetSymbolAddress((void**)&t1,   g_t1);
    cudaGetSymbolAddress((void**)&th,   g_th);
    cudaGetSymbolAddress((void**)&t2,   g_t2);

    cudaFuncSetAttribute(gemm_tf32<0,0>, cudaFuncAttributeMaxDynamicSharedMemorySize, GEMM_SMEM);
    cudaFuncSetAttribute(gemm_tf32<0,1>, cudaFuncAttributeMaxDynamicSharedMemorySize, GEMM_SMEM);
    cudaFuncSetAttribute(gemm_tf32<0,2>, cudaFuncAttributeMaxDynamicSharedMemorySize, GEMM_SMEM);
    cudaFuncSetAttribute(gemm_tf32<1,0>, cudaFuncAttributeMaxDynamicSharedMemorySize, GEMM_SMEM);

    // --- embeddings (zero-padded left by W-1) ---
    zero_pad_k<<<63, 256>>>(emb);
    for (int b = 0; b < BATCH; b++) {
        gemm_tf32<0,0><<<dim3(E/128, SEQ/128), 256, GEMM_SMEM>>>(
            inputs + (size_t)b * SEQ * FIN, FIN, embed_w, FIN, embed_b,
            emb + ((size_t)b * PADS + (WCTX - 1)) * E, E,
            nullptr, 0, SEQ, E);
    }

    // --- layer-0 QKV per global token ---
    gemm_tf32<0,0><<<dim3(3*E/128, (BATCH*PADS + 127)/128), 256, GEMM_SMEM>>>(
        emb, E, qkv_w, E, qkv_b, qkv0, 3*E, nullptr, 0, BATCH*PADS, 3*E);

    // --- layer-0 attention ---
    attn0_k<<<dim3(8, NW), 64>>>(qkv0, octx);

    // --- layer-0 attn-out + residual gather -> LN1 ---
    gemm_tf32<0,2><<<dim3(E/128, NT/128), 256, GEMM_SMEM>>>(
        octx, E, attn_out_w, E, attn_out_b, x1a, E, emb, E, NT, E);
    ln_k<<<NT / 8, 256>>>(x1a, ln1_g, ln1_b, x1, NT);

    // --- layer-0 FFN ---
    gemm_tf32<1,0><<<dim3(FF/128, NT/128), 256, GEMM_SMEM>>>(
        x1, E, ffn1_w, E, ffn1_b, hbuf, FF, nullptr, 0, NT, FF);
    gemm_tf32<0,1><<<dim3(E/128, NT/128), 256, GEMM_SMEM>>>(
        hbuf, FF, ffn2_w, FF, ffn2_b, x1a, E, x1, E, NT, E);
    ln_k<<<NT / 8, 256>>>(x1a, ln2_g, ln2_b, x2, NT);

    // --- layer-1: K,V all tokens; Q last tokens only ---
    gemm_tf32<0,0><<<dim3(2*E/128, NT/128), 256, GEMM_SMEM>>>(
        x2, E, qkv_w + (size_t)3*E*E + (size_t)E*E, E,
        qkv_b + 3*E + E, kv1, 2*E, nullptr, 0, NT, 2*E);
    gemm_tf32<0,0><<<dim3(E/128, NW/128), 256, GEMM_SMEM>>>(
        x2 + (size_t)(WCTX-1)*E, WCTX*E,
        qkv_w + (size_t)3*E*E, E, qkv_b + 3*E,
        q1, E, nullptr, 0, NW, E);

    attn1_k<<<NW, 256>>>(q1, kv1, o1);

    // --- layer-1 tail ---
    gemm_tf32<0,1><<<dim3(E/128, NW/128), 256, GEMM_SMEM>>>(
        o1, E, attn_out_w + (size_t)E*E, E, attn_out_b + E,
        t1a, E, x2 + (size_t)(WCTX-1)*E, WCTX*E, NW, E);
    ln_k<<<NW / 8, 256>>>(t1a, ln1_g + E, ln1_b + E, t1, NW);
    gemm_tf32<1,0><<<dim3(FF/128, NW/128), 256, GEMM_SMEM>>>(
        t1, E, ffn1_w + (size_t)FF*E, E, ffn1_b + FF, th, FF,
        nullptr, 0, NW, FF);
    gemm_tf32<0,1><<<dim3(E/128, NW/128), 256, GEMM_SMEM>>>(
        th, FF, ffn2_w + (size_t)E*FF, FF, ffn2_b + E, t1a, E, t1, E, NW, E);
    ln_k<<<NW / 8, 256>>>(t1a, ln2_g + E, ln2_b + E, t2, NW);

    // --- head (N=10, fp32) ---
    gemm_k<0,0><<<dim3(1, NW/64), 256>>>(
        t2, E, head_w, E, head_b, out, 10, nullptr, 0, NW, 10);
}

// round 4
// speedup vs baseline: 2.5831x; 1.0822x over previous
#include <cuda_runtime.h>
#include <math.h>
#include <stdint.h>

// ---------------------------------------------------------------------------
// Round 4: tf32 GEMM mainloop rework — k-slot permutation lets fragment loads
// be float2 (LDS.64) instead of scalar LDS.32 (2x fewer smem issues), SMLD=40
// for conflict-free phases, launch_bounds(256,2) for 2 CTAs/SM.
// ---------------------------------------------------------------------------

#define BATCH 2
#define SEQ   1024
#define E     256
#define FIN   64
#define FF    1024
#define WCTX  64
#define NW    (BATCH*SEQ)
#define PADS  (SEQ + WCTX - 1)
#define NT    (NW*WCTX)

#define ATTN_SCALE 0.17677669529663687f

// ---------------- scratch ----------------------------------------------------
__device__ __align__(128) float g_emb [BATCH*PADS*E];
__device__ __align__(128) float g_qkv0[BATCH*PADS*3*E];
__device__ __align__(128) float g_octx[NT*E];
__device__ __align__(128) float g_x1a [NT*E];
__device__ __align__(128) float g_x1  [NT*E];
__device__ __align__(128) float g_hbuf[134217728];
__device__ __align__(128) float g_x2  [NT*E];
__device__ __align__(128) float g_kv1 [NT*2*E];
__device__ __align__(128) float g_q1  [NW*E];
__device__ __align__(128) float g_o1  [NW*E];
__device__ __align__(128) float g_t1a [NW*E];
__device__ __align__(128) float g_t1  [NW*E];
__device__ __align__(128) float g_th  [NW*FF];
__device__ __align__(128) float g_t2  [NW*E];

__global__ void zero_pad_k(float* emb) {
    int i = blockIdx.x * 256 + threadIdx.x;
    if (i < (WCTX - 1) * E) {
        emb[i] = 0.f;
        emb[(size_t)PADS * E + i] = 0.f;
    }
}

// ---------------- tf32 tensor-core GEMM --------------------------------------
// C[M,N] = act( A[M,K] @ W[N,K]^T + bias + residual )
// BM=128, BN=128, BK=32, 256 threads, 2-stage cp.async, 2 CTAs/SM.
// k-slot permutation: MMA group kk, slot tig <- k=8kk+2tig, slot tig+4 <- k=8kk+2tig+1.

#define SMLD 40                      /* smem row stride (floats) */
#define TS   (128*SMLD)              /* floats per tile stage */
#define TSB  (TS*4)                  /* bytes  per tile stage  (20480) */
#define GEMM_SMEM (4*TSB)            /* A0,A1,B0,B1 = 81920 bytes */

#define MMA_TF32(d, a0, a1, a2, a3, b0, b1) \
  asm volatile("mma.sync.aligned.m16n8k8.row.col.f32.tf32.tf32.f32 " \
    "{%0,%1,%2,%3}, {%4,%5,%6,%7}, {%8,%9}, {%0,%1,%2,%3};" \
    : "+f"(d[0]), "+f"(d[1]), "+f"(d[2]), "+f"(d[3]) \
    : "r"(a0), "r"(a1), "r"(a2), "r"(a3), "r"(b0), "r"(b1))

#define LOAD_TILE(KT_IDX, ST) do {                                            \
    const unsigned abase_ = smbase + (unsigned)(ST) * TSB;                    \
    const unsigned bbase_ = smbase + 2u * TSB + (unsigned)(ST) * TSB;         \
    const float* Ak_ = A + (KT_IDX) * 32;                                     \
    const float* Bk_ = Wt + (KT_IDX) * 32;                                    \
    _Pragma("unroll")                                                         \
    for (int i_ = 0; i_ < 4; i_++) {                                          \
        const int c_   = tid + 256 * i_;                                      \
        const int row_ = c_ >> 3;                                             \
        const int col_ = (c_ & 7) << 2;                                       \
        const int am_  = bm0 + row_;                                          \
        const float* sa_ = Ak_ + (size_t)(am_ < M ? am_ : 0) * lda + col_;    \
        const int sz_    = (am_ < M) ? 16 : 0;                                \
        asm volatile("cp.async.cg.shared.global [%0], [%1], 16, %2;" ::       \
            "r"(abase_ + (unsigned)(row_ * SMLD + col_) * 4), "l"(sa_), "r"(sz_)); \
        const float* sb_ = Bk_ + (size_t)(bn0 + row_) * K + col_;             \
        asm volatile("cp.async.cg.shared.global [%0], [%1], 16;" ::           \
            "r"(bbase_ + (unsigned)(row_ * SMLD + col_) * 4), "l"(sb_));      \
    }                                                                         \
    asm volatile("cp.async.commit_group;");                                   \
} while (0)

// Fragment loads use the permuted slot assignment: for MMA group kk_ a thread
// supplies k = 8*kk_+2*tig (slot tig) and k = 8*kk_+2*tig+1 (slot tig+4):
// one float2 per row. B likewise. A and B share the permutation -> correct.
#define COMPUTE_TILE(ST) do {                                                 \
    const float* Asf_ = smf + (ST) * TS;                                      \
    const float* Bsf_ = smf + 2 * TS + (ST) * TS;                             \
    _Pragma("unroll")                                                         \
    for (int kk_ = 0; kk_ < 4; kk_++) {                                       \
        const int kb_ = 8 * kk_ + 2 * tig;                                    \
        unsigned Areg[4][4];                                                  \
        unsigned Breg[4][2];                                                  \
        _Pragma("unroll")                                                     \
        for (int mt_ = 0; mt_ < 4; mt_++) {                                   \
            const float* p_ = Asf_ + (wm + mt_ * 16 + gid) * SMLD + kb_;      \
            const float2 lo_ = *(const float2*)(p_);                          \
            const float2 hi_ = *(const float2*)(p_ + 8 * SMLD);               \
            Areg[mt_][0] = __float_as_uint(lo_.x);                            \
            Areg[mt_][1] = __float_as_uint(hi_.x);                            \
            Areg[mt_][2] = __float_as_uint(lo_.y);                            \
            Areg[mt_][3] = __float_as_uint(hi_.y);                            \
        }                                                                     \
        _Pragma("unroll")                                                     \
        for (int nt_ = 0; nt_ < 4; nt_++) {                                   \
            const float2 bv_ = *(const float2*)(Bsf_ + (wn + nt_ * 8 + gid) * SMLD + kb_); \
            Breg[nt_][0] = __float_as_uint(bv_.x);                            \
            Breg[nt_][1] = __float_as_uint(bv_.y);                            \
        }                                                                     \
        _Pragma("unroll")                                                     \
        for (int mt_ = 0; mt_ < 4; mt_++)                                     \
            _Pragma("unroll")                                                 \
            for (int nt_ = 0; nt_ < 4; nt_++)                                 \
                MMA_TF32(acc[mt_][nt_], Areg[mt_][0], Areg[mt_][1],           \
                         Areg[mt_][2], Areg[mt_][3], Breg[nt_][0], Breg[nt_][1]); \
    }                                                                         \
} while (0)

template<int ACT, int RES>
__global__ void __launch_bounds__(256, 2) gemm_tf32(
    const float* __restrict__ A, int lda,
    const float* __restrict__ Wt, int K,
    const float* __restrict__ bias,
    float* __restrict__ C, int ldc,
    const float* __restrict__ res, int ldres,
    int M, int N)
{
    extern __shared__ float smf[];
    const int tid  = threadIdx.x;
    const int bm0  = blockIdx.y * 128;
    const int bn0  = blockIdx.x * 128;
    const int lane = tid & 31, warp = tid >> 5;
    const int wm = (warp & 1) * 64;        // 2 warps along M (64 rows each)
    const int wn = (warp >> 1) * 32;       // 4 warps along N (32 cols each)
    const int gid = lane >> 2, tig = lane & 3;

    const unsigned smbase = (unsigned)__cvta_generic_to_shared(smf);

    float acc[4][4][4];
#pragma unroll
    for (int i = 0; i < 4; i++)
#pragma unroll
        for (int j = 0; j < 4; j++)
#pragma unroll
            for (int r = 0; r < 4; r++) acc[i][j][r] = 0.f;

    const int KT = K >> 5;

    LOAD_TILE(0, 0);
    for (int kt = 0; kt < KT; kt++) {
        if (kt + 1 < KT) {
            LOAD_TILE(kt + 1, (kt + 1) & 1);
            asm volatile("cp.async.wait_group 1;");
        } else {
            asm volatile("cp.async.wait_group 0;");
        }
        __syncthreads();
        COMPUTE_TILE(kt & 1);
        __syncthreads();
    }

    // epilogue
#pragma unroll
    for (int mt = 0; mt < 4; mt++) {
        const int mbase = bm0 + wm + mt * 16 + gid;
#pragma unroll
        for (int half = 0; half < 2; half++) {
            const int m = mbase + half * 8;
            if (m >= M) continue;
#pragma unroll
            for (int nt = 0; nt < 4; nt++) {
                const int n = bn0 + wn + nt * 8 + tig * 2;
                const float2 bv = *(const float2*)(bias + n);
                float v0 = acc[mt][nt][half * 2 + 0] + bv.x;
                float v1 = acc[mt][nt][half * 2 + 1] + bv.y;
                if (RES == 1) {
                    const float2 r = *(const float2*)(res + (size_t)m * ldres + n);
                    v0 += r.x; v1 += r.y;
                }
                if (RES == 2) {
                    const int nw = m >> 6, w = m & 63;
                    const int b = nw >> 10, s = nw & 1023;
                    const float* rp = res + ((size_t)(b * PADS + s + w)) * ldres + n;
                    v0 += rp[0]; v1 += rp[1];
                }
                if (ACT == 1) {
                    v0 = v0 / (1.f + __expf(-v0));
                    v1 = v1 / (1.f + __expf(-v1));
                }
                *(float2*)(C + (size_t)m * ldc + n) = make_float2(v0, v1);
            }
        }
    }
}

// ---------------- small fp32 GEMM (head only, N=10) --------------------------
template<int ACT, int RES>
__global__ void __launch_bounds__(256) gemm_k(
    const float* __restrict__ A, int lda,
    const float* __restrict__ Wt, int K,
    const float* __restrict__ bias,
    float* __restrict__ C, int ldc,
    const float* __restrict__ res, int ldres,
    int M, int N)
{
    __shared__ float As[16][68];
    __shared__ float Bs[16][68];
    const int tid = threadIdx.x;
    const int m0 = blockIdx.y * 64;
    const int n0 = blockIdx.x * 64;
    const int lr = tid >> 2;
    const int lc = (tid & 3) << 2;
    const int ty = tid >> 4;
    const int tx = tid & 15;

    float acc[4][4];
#pragma unroll
    for (int i = 0; i < 4; i++)
#pragma unroll
        for (int j = 0; j < 4; j++) acc[i][j] = 0.f;

    const int am = m0 + lr;
    const int bn = n0 + lr;
    const float* Aptr = A + (size_t)am * lda + lc;
    const float* Wptr = Wt + (size_t)bn * K + lc;
    const bool avalid = (am < M);
    const bool bvalid = (bn < N);

    for (int k0 = 0; k0 < K; k0 += 16) {
        float4 av = make_float4(0.f, 0.f, 0.f, 0.f);
        float4 bv = make_float4(0.f, 0.f, 0.f, 0.f);
        if (avalid) av = *(const float4*)(Aptr + k0);
        if (bvalid) bv = *(const float4*)(Wptr + k0);
        As[lc+0][lr] = av.x; As[lc+1][lr] = av.y;
        As[lc+2][lr] = av.z; As[lc+3][lr] = av.w;
        Bs[lc+0][lr] = bv.x; Bs[lc+1][lr] = bv.y;
        Bs[lc+2][lr] = bv.z; Bs[lc+3][lr] = bv.w;
        __syncthreads();
#pragma unroll
        for (int kk = 0; kk < 16; kk++) {
            float4 a4 = *(const float4*)&As[kk][ty << 2];
            float4 b4 = *(const float4*)&Bs[kk][tx << 2];
            float ar[4] = {a4.x, a4.y, a4.z, a4.w};
            float br[4] = {b4.x, b4.y, b4.z, b4.w};
#pragma unroll
            for (int i = 0; i < 4; i++)
#pragma unroll
                for (int j = 0; j < 4; j++)
                    acc[i][j] = fmaf(ar[i], br[j], acc[i][j]);
        }
        __syncthreads();
    }

#pragma unroll
    for (int i = 0; i < 4; i++) {
        int m = m0 + (ty << 2) + i;
        if (m >= M) continue;
#pragma unroll
        for (int j = 0; j < 4; j++) {
            int n = n0 + (tx << 2) + j;
            if (n >= N) continue;
            float v = acc[i][j] + bias[n];
            if (RES == 1) v += res[(size_t)m * ldres + n];
            if (ACT == 1) v = v / (1.f + __expf(-v));
            C[(size_t)m * ldc + n] = v;
        }
    }
}

// ---------------- layer-0 attention ------------------------------------------
__global__ void __launch_bounds__(64) attn0_k(const float* __restrict__ qkv0,
                                              float* __restrict__ octx) {
    const int h = blockIdx.x;
    const int n = blockIdx.y;
    const int b = n >> 10, s = n & 1023;
    const int t = threadIdx.x;
    __shared__ float Ks[64][33];
    __shared__ float Vs[64][33];

    const float* row = qkv0 + ((size_t)(b * PADS + s + t)) * (3 * E) + h * 32;
    float q[32];
#pragma unroll
    for (int i = 0; i < 8; i++) {
        float4 qv = *(const float4*)(row + i * 4);
        q[i*4+0] = qv.x; q[i*4+1] = qv.y; q[i*4+2] = qv.z; q[i*4+3] = qv.w;
        float4 kv = *(const float4*)(row + E + i * 4);
        Ks[t][i*4+0] = kv.x; Ks[t][i*4+1] = kv.y;
        Ks[t][i*4+2] = kv.z; Ks[t][i*4+3] = kv.w;
        float4 vv = *(const float4*)(row + 2 * E + i * 4);
        Vs[t][i*4+0] = vv.x; Vs[t][i*4+1] = vv.y;
        Vs[t][i*4+2] = vv.z; Vs[t][i*4+3] = vv.w;
    }
    __syncthreads();

    float sc[64];
    float mx = -1e30f;
#pragma unroll 4
    for (int k = 0; k < 64; k++) {
        float a = 0.f;
#pragma unroll
        for (int d = 0; d < 32; d++) a = fmaf(q[d], Ks[k][d], a);
        a *= ATTN_SCALE;
        sc[k] = a;
        mx = fmaxf(mx, a);
    }
    float sum = 0.f;
#pragma unroll 4
    for (int k = 0; k < 64; k++) { sc[k] = __expf(sc[k] - mx); sum += sc[k]; }
    const float inv = 1.f / sum;

    float* out = octx + ((size_t)n * 64 + t) * E + h * 32;
#pragma unroll
    for (int d = 0; d < 32; d++) {
        float a = 0.f;
#pragma unroll 8
        for (int k = 0; k < 64; k++) a = fmaf(sc[k], Vs[k][d], a);
        out[d] = a * inv;
    }
}

// ---------------- layer-1 attention (single query per window) ----------------
__global__ void __launch_bounds__(256) attn1_k(const float* __restrict__ q1,
                                               const float* __restrict__ kv1,
                                               float* __restrict__ o1) {
    const int n = blockIdx.x;
    const int h = threadIdx.x >> 5, l = threadIdx.x & 31;
    __shared__ float qs[256];
    __shared__ float ps[8][64];
    qs[threadIdx.x] = q1[(size_t)n * E + threadIdx.x];
    __syncthreads();

    const float* kvb = kv1 + (size_t)n * 64 * (2 * E);
    const float* qh  = &qs[h * 32];
    const float* k0p = kvb + (size_t)l * (2 * E) + h * 32;
    const float* k1p = kvb + (size_t)(l + 32) * (2 * E) + h * 32;
    float s0 = 0.f, s1 = 0.f;
#pragma unroll
    for (int d = 0; d < 32; d++) {
        s0 = fmaf(qh[d], k0p[d], s0);
        s1 = fmaf(qh[d], k1p[d], s1);
    }
    s0 *= ATTN_SCALE; s1 *= ATTN_SCALE;
    float m = fmaxf(s0, s1);
#pragma unroll
    for (int o = 16; o; o >>= 1) m = fmaxf(m, __shfl_xor_sync(0xffffffffu, m, o));
    float e0 = __expf(s0 - m), e1 = __expf(s1 - m);
    float sum = e0 + e1;
#pragma unroll
    for (int o = 16; o; o >>= 1) sum += __shfl_xor_sync(0xffffffffu, sum, o);
    const float inv = 1.f / sum;
    ps[h][l] = e0 * inv;
    ps[h][l + 32] = e1 * inv;
    __syncwarp();

    float acc = 0.f;
#pragma unroll 4
    for (int k = 0; k < 64; k++)
        acc = fmaf(ps[h][k], kvb[(size_t)k * (2 * E) + E + h * 32 + l], acc);
    o1[(size_t)n * E + h * 32 + l] = acc;
}

// ---------------- LayerNorm --------------------------------------------------
__global__ void __launch_bounds__(256) ln_k(const float* __restrict__ X,
                                            const float* __restrict__ g,
                                            const float* __restrict__ bb,
                                            float* __restrict__ Y, int M) {
    const int warp = threadIdx.x >> 5, lane = threadIdx.x & 31;
    const int row = blockIdx.x * 8 + warp;
    if (row >= M) return;
    const float* x = X + (size_t)row * E;
    float v[8];
    float s = 0.f;
#pragma unroll
    for (int i = 0; i < 8; i++) { v[i] = x[lane + i * 32]; s += v[i]; }
#pragma unroll
    for (int o = 16; o; o >>= 1) s += __shfl_xor_sync(0xffffffffu, s, o);
    const float mean = s * (1.f / E);
    float var = 0.f;
#pragma unroll
    for (int i = 0; i < 8; i++) { float d = v[i] - mean; var = fmaf(d, d, var); }
#pragma unroll
    for (int o = 16; o; o >>= 1) var += __shfl_xor_sync(0xffffffffu, var, o);
    const float inv = rsqrtf(var * (1.f / E) + 1e-5f);
    float* y = Y + (size_t)row * E;
#pragma unroll
    for (int i = 0; i < 8; i++) {
        int c = lane + i * 32;
        y[c] = (v[i] - mean) * inv * g[c] + bb[c];
    }
}

// ---------------------------------------------------------------------------
extern "C" void kernel_launch(void* const* d_in, const int* in_sizes, int n_in,
                              void* d_out, int out_size) {
    (void)in_sizes; (void)n_in; (void)out_size;
    const float* inputs     = (const float*)d_in[0];
    const float* embed_w    = (const float*)d_in[1];
    const float* embed_b    = (const float*)d_in[2];
    const float* qkv_w      = (const float*)d_in[3];
    const float* qkv_b      = (const float*)d_in[4];
    const float* attn_out_w = (const float*)d_in[5];
    const float* attn_out_b = (const float*)d_in[6];
    const float* ln1_g      = (const float*)d_in[7];
    const float* ln1_b      = (const float*)d_in[8];
    const float* ffn1_w     = (const float*)d_in[9];
    const float* ffn1_b     = (const float*)d_in[10];
    const float* ffn2_w     = (const float*)d_in[11];
    const float* ffn2_b     = (const float*)d_in[12];
    const float* ln2_g      = (const float*)d_in[13];
    const float* ln2_b      = (const float*)d_in[14];
    const float* head_w     = (const float*)d_in[15];
    const float* head_b     = (const float*)d_in[16];
    float* out = (float*)d_out;

    float *emb, *qkv0, *octx, *x1a, *x1, *hbuf, *x2, *kv1;
    float *q1, *o1, *t1a, *t1, *th, *t2;
    cudaGetSymbolAddress((void**)&emb,  g_emb);
    cudaGetSymbolAddress((void**)&qkv0, g_qkv0);
    cudaGetSymbolAddress((void**)&octx, g_octx);
    cudaGetSymbolAddress((void**)&x1a,  g_x1a);
    cudaGetSymbolAddress((void**)&x1,   g_x1);
    cudaGetSymbolAddress((void**)&hbuf, g_hbuf);
    cudaGetSymbolAddress((void**)&x2,   g_x2);
    cudaGetSymbolAddress((void**)&kv1,  g_kv1);
    cudaGetSymbolAddress((void**)&q1,   g_q1);
    cudaGetSymbolAddress((void**)&o1,   g_o1);
    cudaGetSymbolAddress((void**)&t1a,  g_t1a);
    cudaGetSymbolAddress((void**)&t1,   g_t1);
    cudaGetSymbolAddress((void**)&th,   g_th);
    cudaGetSymbolAddress((void**)&t2,   g_t2);

    cudaFuncSetAttribute(gemm_tf32<0,0>, cudaFuncAttributeMaxDynamicSharedMemorySize, GEMM_SMEM);
    cudaFuncSetAttribute(gemm_tf32<0,1>, cudaFuncAttributeMaxDynamicSharedMemorySize, GEMM_SMEM);
    cudaFuncSetAttribute(gemm_tf32<0,2>, cudaFuncAttributeMaxDynamicSharedMemorySize, GEMM_SMEM);
    cudaFuncSetAttribute(gemm_tf32<1,0>, cudaFuncAttributeMaxDynamicSharedMemorySize, GEMM_SMEM);

    // --- embeddings (zero-padded left by W-1) ---
    zero_pad_k<<<63, 256>>>(emb);
    for (int b = 0; b < BATCH; b++) {
        gemm_tf32<0,0><<<dim3(E/128, SEQ/128), 256, GEMM_SMEM>>>(
            inputs + (size_t)b * SEQ * FIN, FIN, embed_w, FIN, embed_b,
            emb + ((size_t)b * PADS + (WCTX - 1)) * E, E,
            nullptr, 0, SEQ, E);
    }

    // --- layer-0 QKV per global token ---
    gemm_tf32<0,0><<<dim3(3*E/128, (BATCH*PADS + 127)/128), 256, GEMM_SMEM>>>(
        emb, E, qkv_w, E, qkv_b, qkv0, 3*E, nullptr, 0, BATCH*PADS, 3*E);

    // --- layer-0 attention ---
    attn0_k<<<dim3(8, NW), 64>>>(qkv0, octx);

    // --- layer-0 attn-out + residual gather -> LN1 ---
    gemm_tf32<0,2><<<dim3(E/128, NT/128), 256, GEMM_SMEM>>>(
        octx, E, attn_out_w, E, attn_out_b, x1a, E, emb, E, NT, E);
    ln_k<<<NT / 8, 256>>>(x1a, ln1_g, ln1_b, x1, NT);

    // --- layer-0 FFN ---
    gemm_tf32<1,0><<<dim3(FF/128, NT/128), 256, GEMM_SMEM>>>(
        x1, E, ffn1_w, E, ffn1_b, hbuf, FF, nullptr, 0, NT, FF);
    gemm_tf32<0,1><<<dim3(E/128, NT/128), 256, GEMM_SMEM>>>(
        hbuf, FF, ffn2_w, FF, ffn2_b, x1a, E, x1, E, NT, E);
    ln_k<<<NT / 8, 256>>>(x1a, ln2_g, ln2_b, x2, NT);

    // --- layer-1: K,V all tokens; Q last tokens only ---
    gemm_tf32<0,0><<<dim3(2*E/128, NT/128), 256, GEMM_SMEM>>>(
        x2, E, qkv_w + (size_t)3*E*E + (size_t)E*E, E,
        qkv_b + 3*E + E, kv1, 2*E, nullptr, 0, NT, 2*E);
    gemm_tf32<0,0><<<dim3(E/128, NW/128), 256, GEMM_SMEM>>>(
        x2 + (size_t)(WCTX-1)*E, WCTX*E,
        qkv_w + (size_t)3*E*E, E, qkv_b + 3*E,
        q1, E, nullptr, 0, NW, E);

    attn1_k<<<NW, 256>>>(q1, kv1, o1);

    // --- layer-1 tail ---
    gemm_tf32<0,1><<<dim3(E/128, NW/128), 256, GEMM_SMEM>>>(
        o1, E, attn_out_w + (size_t)E*E, E, attn_out_b + E,
        t1a, E, x2 + (size_t)(WCTX-1)*E, WCTX*E, NW, E);
    ln_k<<<NW / 8, 256>>>(t1a, ln1_g + E, ln1_b + E, t1, NW);
    gemm_tf32<1,0><<<dim3(FF/128, NW/128), 256, GEMM_SMEM>>>(
        t1, E, ffn1_w + (size_t)FF*E, E, ffn1_b + FF, th, FF,
        nullptr, 0, NW, FF);
    gemm_tf32<0,1><<<dim3(E/128, NW/128), 256, GEMM_SMEM>>>(
        th, FF, ffn2_w + (size_t)E*FF, FF, ffn2_b + E, t1a, E, t1, E, NW, E);
    ln_k<<<NW / 8, 256>>>(t1a, ln2_g + E, ln2_b + E, t2, NW);

    // --- head (N=10, fp32) ---
    gemm_k<0,0><<<dim3(1, NW/64), 256>>>(
        t2, E, head_w, E, head_b, out, 10, nullptr, 0, NW, 10);
}

// round 5
// speedup vs baseline: 2.7486x; 1.0641x over previous
#include <cuda_runtime.h>
#include <math.h>
#include <stdint.h>

// ---------------------------------------------------------------------------
// Round 5: 4-stage cp.async ring with ONE barrier per K-tile (latency was the
// binder, not throughput), load-ahead issued before compute; attn0 inner loops
// vectorized to float4 broadcasts (4x fewer LDS issues).
// ---------------------------------------------------------------------------

#define BATCH 2
#define SEQ   1024
#define E     256
#define FIN   64
#define FF    1024
#define WCTX  64
#define NW    (BATCH*SEQ)
#define PADS  (SEQ + WCTX - 1)
#define NT    (NW*WCTX)

#define ATTN_SCALE 0.17677669529663687f

// ---------------- scratch ----------------------------------------------------
__device__ __align__(128) float g_emb [BATCH*PADS*E];
__device__ __align__(128) float g_qkv0[BATCH*PADS*3*E];
__device__ __align__(128) float g_octx[NT*E];
__device__ __align__(128) float g_x1a [NT*E];
__device__ __align__(128) float g_x1  [NT*E];
__device__ __align__(128) float g_hbuf[134217728];
__device__ __align__(128) float g_x2  [NT*E];
__device__ __align__(128) float g_kv1 [NT*2*E];
__device__ __align__(128) float g_q1  [NW*E];
__device__ __align__(128) float g_o1  [NW*E];
__device__ __align__(128) float g_t1a [NW*E];
__device__ __align__(128) float g_t1  [NW*E];
__device__ __align__(128) float g_th  [NW*FF];
__device__ __align__(128) float g_t2  [NW*E];

__global__ void zero_pad_k(float* emb) {
    int i = blockIdx.x * 256 + threadIdx.x;
    if (i < (WCTX - 1) * E) {
        emb[i] = 0.f;
        emb[(size_t)PADS * E + i] = 0.f;
    }
}

// ---------------- tf32 tensor-core GEMM --------------------------------------
// C[M,N] = act( A[M,K] @ W[N,K]^T + bias + residual )
// BM=128, BN=128, BK=32, 256 threads, 4-stage cp.async ring, 1 sync/tile.
// k-slot permutation: MMA group kk, slot tig <- k=8kk+2tig, slot tig+4 <- 2tig+1.

#define SMLD 40                      /* smem row stride (floats) */
#define TS   (128*SMLD)              /* floats per tile stage */
#define TSB  (TS*4)                  /* bytes per tile stage (20480) */
#define NSTG 4
#define GEMM_SMEM (2*NSTG*TSB)       /* A0..A3,B0..B3 = 163840 bytes */

#define MMA_TF32(d, a0, a1, a2, a3, b0, b1) \
  asm volatile("mma.sync.aligned.m16n8k8.row.col.f32.tf32.tf32.f32 " \
    "{%0,%1,%2,%3}, {%4,%5,%6,%7}, {%8,%9}, {%0,%1,%2,%3};" \
    : "+f"(d[0]), "+f"(d[1]), "+f"(d[2]), "+f"(d[3]) \
    : "r"(a0), "r"(a1), "r"(a2), "r"(a3), "r"(b0), "r"(b1))

// Load K-tile KT_IDX into ring stage ST; if KT_IDX >= KT, commit empty group
// (keeps cp.async.wait_group accounting uniform).
#define LOAD_TILE(KT_IDX, ST) do {                                            \
    if ((KT_IDX) < KT) {                                                      \
        const unsigned abase_ = smbase + (unsigned)(ST) * TSB;                \
        const unsigned bbase_ = smbase + (unsigned)NSTG * TSB + (unsigned)(ST) * TSB; \
        const float* Ak_ = A + (KT_IDX) * 32;                                 \
        const float* Bk_ = Wt + (KT_IDX) * 32;                                \
        _Pragma("unroll")                                                     \
        for (int i_ = 0; i_ < 4; i_++) {                                      \
            const int c_   = tid + 256 * i_;                                  \
            const int row_ = c_ >> 3;                                         \
            const int col_ = (c_ & 7) << 2;                                   \
            const int am_  = bm0 + row_;                                      \
            const float* sa_ = Ak_ + (size_t)(am_ < M ? am_ : 0) * lda + col_;\
            const int sz_    = (am_ < M) ? 16 : 0;                            \
            asm volatile("cp.async.cg.shared.global [%0], [%1], 16, %2;" ::   \
                "r"(abase_ + (unsigned)(row_ * SMLD + col_) * 4), "l"(sa_), "r"(sz_)); \
            const float* sb_ = Bk_ + (size_t)(bn0 + row_) * K + col_;         \
            asm volatile("cp.async.cg.shared.global [%0], [%1], 16;" ::       \
                "r"(bbase_ + (unsigned)(row_ * SMLD + col_) * 4), "l"(sb_));  \
        }                                                                     \
    }                                                                         \
    asm volatile("cp.async.commit_group;");                                   \
} while (0)

#define COMPUTE_TILE(ST) do {                                                 \
    const float* Asf_ = smf + (ST) * TS;                                      \
    const float* Bsf_ = smf + NSTG * TS + (ST) * TS;                          \
    _Pragma("unroll")                                                         \
    for (int kk_ = 0; kk_ < 4; kk_++) {                                       \
        const int kb_ = 8 * kk_ + 2 * tig;                                    \
        unsigned Areg[4][4];                                                  \
        unsigned Breg[4][2];                                                  \
        _Pragma("unroll")                                                     \
        for (int mt_ = 0; mt_ < 4; mt_++) {                                   \
            const float* p_ = Asf_ + (wm + mt_ * 16 + gid) * SMLD + kb_;      \
            const float2 lo_ = *(const float2*)(p_);                          \
            const float2 hi_ = *(const float2*)(p_ + 8 * SMLD);               \
            Areg[mt_][0] = __float_as_uint(lo_.x);                            \
            Areg[mt_][1] = __float_as_uint(hi_.x);                            \
            Areg[mt_][2] = __float_as_uint(lo_.y);                            \
            Areg[mt_][3] = __float_as_uint(hi_.y);                            \
        }                                                                     \
        _Pragma("unroll")                                                     \
        for (int nt_ = 0; nt_ < 4; nt_++) {                                   \
            const float2 bv_ = *(const float2*)(Bsf_ + (wn + nt_ * 8 + gid) * SMLD + kb_); \
            Breg[nt_][0] = __float_as_uint(bv_.x);                            \
            Breg[nt_][1] = __float_as_uint(bv_.y);                            \
        }                                                                     \
        _Pragma("unroll")                                                     \
        for (int mt_ = 0; mt_ < 4; mt_++)                                     \
            _Pragma("unroll")                                                 \
            for (int nt_ = 0; nt_ < 4; nt_++)                                 \
                MMA_TF32(acc[mt_][nt_], Areg[mt_][0], Areg[mt_][1],           \
                         Areg[mt_][2], Areg[mt_][3], Breg[nt_][0], Breg[nt_][1]); \
    }                                                                         \
} while (0)

template<int ACT, int RES>
__global__ void __launch_bounds__(256, 1) gemm_tf32(
    const float* __restrict__ A, int lda,
    const float* __restrict__ Wt, int K,
    const float* __restrict__ bias,
    float* __restrict__ C, int ldc,
    const float* __restrict__ res, int ldres,
    int M, int N)
{
    extern __shared__ float smf[];
    const int tid  = threadIdx.x;
    const int bm0  = blockIdx.y * 128;
    const int bn0  = blockIdx.x * 128;
    const int lane = tid & 31, warp = tid >> 5;
    const int wm = (warp & 1) * 64;        // 2 warps along M (64 rows each)
    const int wn = (warp >> 1) * 32;       // 4 warps along N (32 cols each)
    const int gid = lane >> 2, tig = lane & 3;

    const unsigned smbase = (unsigned)__cvta_generic_to_shared(smf);

    float acc[4][4][4];
#pragma unroll
    for (int i = 0; i < 4; i++)
#pragma unroll
        for (int j = 0; j < 4; j++)
#pragma unroll
            for (int r = 0; r < 4; r++) acc[i][j][r] = 0.f;

    const int KT = K >> 5;

    // prologue: fill up to 3 stages (empty commits beyond KT keep counts valid)
    LOAD_TILE(0, 0);
    LOAD_TILE(1, 1);
    LOAD_TILE(2, 2);

    for (int kt = 0; kt < KT; kt++) {
        asm volatile("cp.async.wait_group 2;");
        __syncthreads();
        // issue next load BEFORE compute: stage (kt+3)%4 was last read at
        // iteration kt-1, ordered by the barrier above -> safe.
        LOAD_TILE(kt + 3, (kt + 3) & 3);
        COMPUTE_TILE(kt & 3);
    }

    // epilogue
#pragma unroll
    for (int mt = 0; mt < 4; mt++) {
        const int mbase = bm0 + wm + mt * 16 + gid;
#pragma unroll
        for (int half = 0; half < 2; half++) {
            const int m = mbase + half * 8;
            if (m >= M) continue;
#pragma unroll
            for (int nt = 0; nt < 4; nt++) {
                const int n = bn0 + wn + nt * 8 + tig * 2;
                const float2 bv = *(const float2*)(bias + n);
                float v0 = acc[mt][nt][half * 2 + 0] + bv.x;
                float v1 = acc[mt][nt][half * 2 + 1] + bv.y;
                if (RES == 1) {
                    const float2 r = *(const float2*)(res + (size_t)m * ldres + n);
                    v0 += r.x; v1 += r.y;
                }
                if (RES == 2) {
                    const int nw = m >> 6, w = m & 63;
                    const int b = nw >> 10, s = nw & 1023;
                    const float* rp = res + ((size_t)(b * PADS + s + w)) * ldres + n;
                    v0 += rp[0]; v1 += rp[1];
                }
                if (ACT == 1) {
                    v0 = v0 / (1.f + __expf(-v0));
                    v1 = v1 / (1.f + __expf(-v1));
                }
                *(float2*)(C + (size_t)m * ldc + n) = make_float2(v0, v1);
            }
        }
    }
}

// ---------------- small fp32 GEMM (head only, N=10) --------------------------
template<int ACT, int RES>
__global__ void __launch_bounds__(256) gemm_k(
    const float* __restrict__ A, int lda,
    const float* __restrict__ Wt, int K,
    const float* __restrict__ bias,
    float* __restrict__ C, int ldc,
    const float* __restrict__ res, int ldres,
    int M, int N)
{
    __shared__ float As[16][68];
    __shared__ float Bs[16][68];
    const int tid = threadIdx.x;
    const int m0 = blockIdx.y * 64;
    const int n0 = blockIdx.x * 64;
    const int lr = tid >> 2;
    const int lc = (tid & 3) << 2;
    const int ty = tid >> 4;
    const int tx = tid & 15;

    float acc[4][4];
#pragma unroll
    for (int i = 0; i < 4; i++)
#pragma unroll
        for (int j = 0; j < 4; j++) acc[i][j] = 0.f;

    const int am = m0 + lr;
    const int bn = n0 + lr;
    const float* Aptr = A + (size_t)am * lda + lc;
    const float* Wptr = Wt + (size_t)bn * K + lc;
    const bool avalid = (am < M);
    const bool bvalid = (bn < N);

    for (int k0 = 0; k0 < K; k0 += 16) {
        float4 av = make_float4(0.f, 0.f, 0.f, 0.f);
        float4 bv = make_float4(0.f, 0.f, 0.f, 0.f);
        if (avalid) av = *(const float4*)(Aptr + k0);
        if (bvalid) bv = *(const float4*)(Wptr + k0);
        As[lc+0][lr] = av.x; As[lc+1][lr] = av.y;
        As[lc+2][lr] = av.z; As[lc+3][lr] = av.w;
        Bs[lc+0][lr] = bv.x; Bs[lc+1][lr] = bv.y;
        Bs[lc+2][lr] = bv.z; Bs[lc+3][lr] = bv.w;
        __syncthreads();
#pragma unroll
        for (int kk = 0; kk < 16; kk++) {
            float4 a4 = *(const float4*)&As[kk][ty << 2];
            float4 b4 = *(const float4*)&Bs[kk][tx << 2];
            float ar[4] = {a4.x, a4.y, a4.z, a4.w};
            float br[4] = {b4.x, b4.y, b4.z, b4.w};
#pragma unroll
            for (int i = 0; i < 4; i++)
#pragma unroll
                for (int j = 0; j < 4; j++)
                    acc[i][j] = fmaf(ar[i], br[j], acc[i][j]);
        }
        __syncthreads();
    }

#pragma unroll
    for (int i = 0; i < 4; i++) {
        int m = m0 + (ty << 2) + i;
        if (m >= M) continue;
#pragma unroll
        for (int j = 0; j < 4; j++) {
            int n = n0 + (tx << 2) + j;
            if (n >= N) continue;
            float v = acc[i][j] + bias[n];
            if (RES == 1) v += res[(size_t)m * ldres + n];
            if (ACT == 1) v = v / (1.f + __expf(-v));
            C[(size_t)m * ldc + n] = v;
        }
    }
}

// ---------------- layer-0 attention (float4 broadcast loads) -----------------
__global__ void __launch_bounds__(64) attn0_k(const float* __restrict__ qkv0,
                                              float* __restrict__ octx) {
    const int h = blockIdx.x;
    const int n = blockIdx.y;
    const int b = n >> 10, s = n & 1023;
    const int t = threadIdx.x;
    __shared__ float Ks[64][36];
    __shared__ float Vs[64][36];

    const float* row = qkv0 + ((size_t)(b * PADS + s + t)) * (3 * E) + h * 32;
    float4 q4[8];
#pragma unroll
    for (int i = 0; i < 8; i++) {
        q4[i] = *(const float4*)(row + i * 4);
        *(float4*)&Ks[t][i * 4] = *(const float4*)(row + E + i * 4);
        *(float4*)&Vs[t][i * 4] = *(const float4*)(row + 2 * E + i * 4);
    }
    __syncthreads();

    float sc[64];
    float mx = -1e30f;
#pragma unroll 4
    for (int k = 0; k < 64; k++) {
        const float4* k4 = (const float4*)Ks[k];
        float a = 0.f;
#pragma unroll
        for (int i = 0; i < 8; i++) {
            const float4 kv = k4[i];
            a = fmaf(q4[i].x, kv.x, a);
            a = fmaf(q4[i].y, kv.y, a);
            a = fmaf(q4[i].z, kv.z, a);
            a = fmaf(q4[i].w, kv.w, a);
        }
        a *= ATTN_SCALE;
        sc[k] = a;
        mx = fmaxf(mx, a);
    }
    float sum = 0.f;
#pragma unroll 4
    for (int k = 0; k < 64; k++) { sc[k] = __expf(sc[k] - mx); sum += sc[k]; }
    const float inv = 1.f / sum;

    // PV: k-outer, float4 broadcast of V rows, 32 accumulators
    float4 o4[8];
#pragma unroll
    for (int i = 0; i < 8; i++) o4[i] = make_float4(0.f, 0.f, 0.f, 0.f);
#pragma unroll 4
    for (int k = 0; k < 64; k++) {
        const float p = sc[k];
        const float4* v4 = (const float4*)Vs[k];
#pragma unroll
        for (int i = 0; i < 8; i++) {
            const float4 vv = v4[i];
            o4[i].x = fmaf(p, vv.x, o4[i].x);
            o4[i].y = fmaf(p, vv.y, o4[i].y);
            o4[i].z = fmaf(p, vv.z, o4[i].z);
            o4[i].w = fmaf(p, vv.w, o4[i].w);
        }
    }
    float* out = octx + ((size_t)n * 64 + t) * E + h * 32;
#pragma unroll
    for (int i = 0; i < 8; i++) {
        float4 o = o4[i];
        o.x *= inv; o.y *= inv; o.z *= inv; o.w *= inv;
        *(float4*)(out + i * 4) = o;
    }
}

// ---------------- layer-1 attention (single query per window) ----------------
__global__ void __launch_bounds__(256) attn1_k(const float* __restrict__ q1,
                                               const float* __restrict__ kv1,
                                               float* __restrict__ o1) {
    const int n = blockIdx.x;
    const int h = threadIdx.x >> 5, l = threadIdx.x & 31;
    __shared__ float qs[256];
    __shared__ float ps[8][64];
    qs[threadIdx.x] = q1[(size_t)n * E + threadIdx.x];
    __syncthreads();

    const float* kvb = kv1 + (size_t)n * 64 * (2 * E);
    const float* qh  = &qs[h * 32];
    const float* k0p = kvb + (size_t)l * (2 * E) + h * 32;
    const float* k1p = kvb + (size_t)(l + 32) * (2 * E) + h * 32;
    float s0 = 0.f, s1 = 0.f;
#pragma unroll
    for (int d = 0; d < 32; d++) {
        s0 = fmaf(qh[d], k0p[d], s0);
        s1 = fmaf(qh[d], k1p[d], s1);
    }
    s0 *= ATTN_SCALE; s1 *= ATTN_SCALE;
    float m = fmaxf(s0, s1);
#pragma unroll
    for (int o = 16; o; o >>= 1) m = fmaxf(m, __shfl_xor_sync(0xffffffffu, m, o));
    float e0 = __expf(s0 - m), e1 = __expf(s1 - m);
    float sum = e0 + e1;
#pragma unroll
    for (int o = 16; o; o >>= 1) sum += __shfl_xor_sync(0xffffffffu, sum, o);
    const float inv = 1.f / sum;
    ps[h][l] = e0 * inv;
    ps[h][l + 32] = e1 * inv;
    __syncwarp();

    float acc = 0.f;
#pragma unroll 4
    for (int k = 0; k < 64; k++)
        acc = fmaf(ps[h][k], kvb[(size_t)k * (2 * E) + E + h * 32 + l], acc);
    o1[(size_t)n * E + h * 32 + l] = acc;
}

// ---------------- LayerNorm --------------------------------------------------
__global__ void __launch_bounds__(256) ln_k(const float* __restrict__ X,
                                            const float* __restrict__ g,
                                            const float* __restrict__ bb,
                                            float* __restrict__ Y, int M) {
    const int warp = threadIdx.x >> 5, lane = threadIdx.x & 31;
    const int row = blockIdx.x * 8 + warp;
    if (row >= M) return;
    const float* x = X + (size_t)row * E;
    float v[8];
    float s = 0.f;
#pragma unroll
    for (int i = 0; i < 8; i++) { v[i] = x[lane + i * 32]; s += v[i]; }
#pragma unroll
    for (int o = 16; o; o >>= 1) s += __shfl_xor_sync(0xffffffffu, s, o);
    const float mean = s * (1.f / E);
    float var = 0.f;
#pragma unroll
    for (int i = 0; i < 8; i++) { float d = v[i] - mean; var = fmaf(d, d, var); }
#pragma unroll
    for (int o = 16; o; o >>= 1) var += __shfl_xor_sync(0xffffffffu, var, o);
    const float inv = rsqrtf(var * (1.f / E) + 1e-5f);
    float* y = Y + (size_t)row * E;
#pragma unroll
    for (int i = 0; i < 8; i++) {
        int c = lane + i * 32;
        y[c] = (v[i] - mean) * inv * g[c] + bb[c];
    }
}

// ---------------------------------------------------------------------------
extern "C" void kernel_launch(void* const* d_in, const int* in_sizes, int n_in,
                              void* d_out, int out_size) {
    (void)in_sizes; (void)n_in; (void)out_size;
    const float* inputs     = (const float*)d_in[0];
    const float* embed_w    = (const float*)d_in[1];
    const float* embed_b    = (const float*)d_in[2];
    const float* qkv_w      = (const float*)d_in[3];
    const float* qkv_b      = (const float*)d_in[4];
    const float* attn_out_w = (const float*)d_in[5];
    const float* attn_out_b = (const float*)d_in[6];
    const float* ln1_g      = (const float*)d_in[7];
    const float* ln1_b      = (const float*)d_in[8];
    const float* ffn1_w     = (const float*)d_in[9];
    const float* ffn1_b     = (const float*)d_in[10];
    const float* ffn2_w     = (const float*)d_in[11];
    const float* ffn2_b     = (const float*)d_in[12];
    const float* ln2_g      = (const float*)d_in[13];
    const float* ln2_b      = (const float*)d_in[14];
    const float* head_w     = (const float*)d_in[15];
    const float* head_b     = (const float*)d_in[16];
    float* out = (float*)d_out;

    float *emb, *qkv0, *octx, *x1a, *x1, *hbuf, *x2, *kv1;
    float *q1, *o1, *t1a, *t1, *th, *t2;
    cudaGetSymbolAddress((void**)&emb,  g_emb);
    cudaGetSymbolAddress((void**)&qkv0, g_qkv0);
    cudaGetSymbolAddress((void**)&octx, g_octx);
    cudaGetSymbolAddress((void**)&x1a,  g_x1a);
    cudaGetSymbolAddress((void**)&x1,   g_x1);
    cudaGetSymbolAddress((void**)&hbuf, g_hbuf);
    cudaGetSymbolAddress((void**)&x2,   g_x2);
    cudaGetSymbolAddress((void**)&kv1,  g_kv1);
    cudaGetSymbolAddress((void**)&q1,   g_q1);
    cudaGetSymbolAddress((void**)&o1,   g_o1);
    cudaGetSymbolAddress((void**)&t1a,  g_t1a);
    cudaGetSymbolAddress((void**)&t1,   g_t1);
    cudaGetSymbolAddress((void**)&th,   g_th);
    cudaGetSymbolAddress((void**)&t2,   g_t2);

    cudaFuncSetAttribute(gemm_tf32<0,0>, cudaFuncAttributeMaxDynamicSharedMemorySize, GEMM_SMEM);
    cudaFuncSetAttribute(gemm_tf32<0,1>, cudaFuncAttributeMaxDynamicSharedMemorySize, GEMM_SMEM);
    cudaFuncSetAttribute(gemm_tf32<0,2>, cudaFuncAttributeMaxDynamicSharedMemorySize, GEMM_SMEM);
    cudaFuncSetAttribute(gemm_tf32<1,0>, cudaFuncAttributeMaxDynamicSharedMemorySize, GEMM_SMEM);

    // --- embeddings (zero-padded left by W-1) ---
    zero_pad_k<<<63, 256>>>(emb);
    for (int b = 0; b < BATCH; b++) {
        gemm_tf32<0,0><<<dim3(E/128, SEQ/128), 256, GEMM_SMEM>>>(
            inputs + (size_t)b * SEQ * FIN, FIN, embed_w, FIN, embed_b,
            emb + ((size_t)b * PADS + (WCTX - 1)) * E, E,
            nullptr, 0, SEQ, E);
    }

    // --- layer-0 QKV per global token ---
    gemm_tf32<0,0><<<dim3(3*E/128, (BATCH*PADS + 127)/128), 256, GEMM_SMEM>>>(
        emb, E, qkv_w, E, qkv_b, qkv0, 3*E, nullptr, 0, BATCH*PADS, 3*E);

    // --- layer-0 attention ---
    attn0_k<<<dim3(8, NW), 64>>>(qkv0, octx);

    // --- layer-0 attn-out + residual gather -> LN1 ---
    gemm_tf32<0,2><<<dim3(E/128, NT/128), 256, GEMM_SMEM>>>(
        octx, E, attn_out_w, E, attn_out_b, x1a, E, emb, E, NT, E);
    ln_k<<<NT / 8, 256>>>(x1a, ln1_g, ln1_b, x1, NT);

    // --- layer-0 FFN ---
    gemm_tf32<1,0><<<dim3(FF/128, NT/128), 256, GEMM_SMEM>>>(
        x1, E, ffn1_w, E, ffn1_b, hbuf, FF, nullptr, 0, NT, FF);
    gemm_tf32<0,1><<<dim3(E/128, NT/128), 256, GEMM_SMEM>>>(
        hbuf, FF, ffn2_w, FF, ffn2_b, x1a, E, x1, E, NT, E);
    ln_k<<<NT / 8, 256>>>(x1a, ln2_g, ln2_b, x2, NT);

    // --- layer-1: K,V all tokens; Q last tokens only ---
    gemm_tf32<0,0><<<dim3(2*E/128, NT/128), 256, GEMM_SMEM>>>(
        x2, E, qkv_w + (size_t)3*E*E + (size_t)E*E, E,
        qkv_b + 3*E + E, kv1, 2*E, nullptr, 0, NT, 2*E);
    gemm_tf32<0,0><<<dim3(E/128, NW/128), 256, GEMM_SMEM>>>(
        x2 + (size_t)(WCTX-1)*E, WCTX*E,
        qkv_w + (size_t)3*E*E, E, qkv_b + 3*E,
        q1, E, nullptr, 0, NW, E);

    attn1_k<<<NW, 256>>>(q1, kv1, o1);

    // --- layer-1 tail ---
    gemm_tf32<0,1><<<dim3(E/128, NW/128), 256, GEMM_SMEM>>>(
        o1, E, attn_out_w + (size_t)E*E, E, attn_out_b + E,
        t1a, E, x2 + (size_t)(WCTX-1)*E, WCTX*E, NW, E);
    ln_k<<<NW / 8, 256>>>(t1a, ln1_g + E, ln1_b + E, t1, NW);
    gemm_tf32<1,0><<<dim3(FF/128, NW/128), 256, GEMM_SMEM>>>(
        t1, E, ffn1_w + (size_t)FF*E, E, ffn1_b + FF, th, FF,
        nullptr, 0, NW, FF);
    gemm_tf32<0,1><<<dim3(E/128, NW/128), 256, GEMM_SMEM>>>(
        th, FF, ffn2_w + (size_t)E*FF, FF, ffn2_b + E, t1a, E, t1, E, NW, E);
    ln_k<<<NW / 8, 256>>>(t1a, ln2_g + E, ln2_b + E, t2, NW);

    // --- head (N=10, fp32) ---
    gemm_k<0,0><<<dim3(1, NW/64), 256>>>(
        t2, E, head_w, E, head_b, out, 10, nullptr, 0, NW, 10);
}

// round 7
// speedup vs baseline: 2.8420x; 1.0340x over previous
#include <cuda_runtime.h>
#include <math.h>
#include <stdint.h>

// ---------------------------------------------------------------------------
// Round 7: tcgen05 unavailable (harness targets sm_103 without 'a' -> ptxas
// rejects it). Back to mma.sync tf32, but with warp tile 64x64 (CTA 128x256):
// 0.5 LDS.64 per HMMA (was 0.75), doubled B-fragment reuse, 3-stage cp.async
// ring (184KB smem), one barrier per K-tile.
// ---------------------------------------------------------------------------

#define BATCH 2
#define SEQ   1024
#define E     256
#define FIN   64
#define FF    1024
#define WCTX  64
#define NW    (BATCH*SEQ)
#define PADS  (SEQ + WCTX - 1)
#define NT    (NW*WCTX)

#define ATTN_SCALE 0.17677669529663687f

// ---------------- scratch ----------------------------------------------------
__device__ __align__(128) float g_emb [BATCH*PADS*E];
__device__ __align__(128) float g_qkv0[BATCH*PADS*3*E];
__device__ __align__(128) float g_octx[NT*E];
__device__ __align__(128) float g_x1a [NT*E];
__device__ __align__(128) float g_x1  [NT*E];
__device__ __align__(128) float g_hbuf[134217728];
__device__ __align__(128) float g_x2  [NT*E];
__device__ __align__(128) float g_kv1 [NT*2*E];
__device__ __align__(128) float g_q1  [NW*E];
__device__ __align__(128) float g_o1  [NW*E];
__device__ __align__(128) float g_t1a [NW*E];
__device__ __align__(128) float g_t1  [NW*E];
__device__ __align__(128) float g_th  [NW*FF];
__device__ __align__(128) float g_t2  [NW*E];

__global__ void zero_pad_k(float* emb) {
    int i = blockIdx.x * 256 + threadIdx.x;
    if (i < (WCTX - 1) * E) {
        emb[i] = 0.f;
        emb[(size_t)PADS * E + i] = 0.f;
    }
}

// ---------------- tf32 tensor-core GEMM --------------------------------------
// C[M,N] = act( A[M,K] @ W[N,K]^T + bias + residual )
// BM=128, BN=256, BK=32, 256 threads (8 warps, 2Mx4N), warp tile 64x64.
// 3-stage cp.async ring, 1 barrier/tile. Requires N%256==0, K%32==0.

#define SMLD 40                      /* smem row stride (floats) */
#define A_TS (128*SMLD)
#define B_TS (256*SMLD)
#define A_TSB (A_TS*4)               /* 20480 B */
#define B_TSB (B_TS*4)               /* 40960 B */
#define NSTG 3
#define GEMM_SMEM (NSTG*(A_TSB+B_TSB))   /* 184320 B */

#define MMA_TF32(d, a0, a1, a2, a3, b0, b1) \
  asm volatile("mma.sync.aligned.m16n8k8.row.col.f32.tf32.tf32.f32 " \
    "{%0,%1,%2,%3}, {%4,%5,%6,%7}, {%8,%9}, {%0,%1,%2,%3};" \
    : "+f"(d[0]), "+f"(d[1]), "+f"(d[2]), "+f"(d[3]) \
    : "r"(a0), "r"(a1), "r"(a2), "r"(a3), "r"(b0), "r"(b1))

// Load K-tile KT_IDX into ring stage ST (A: 4 float4/thread, B: 8/thread).
#define LOAD_TILE(KT_IDX, ST) do {                                            \
    if ((KT_IDX) < KT) {                                                      \
        const unsigned abase_ = smbase + (unsigned)(ST) * A_TSB;              \
        const unsigned bbase_ = smbase + (unsigned)NSTG * A_TSB + (unsigned)(ST) * B_TSB; \
        const float* Ak_ = A + (KT_IDX) * 32;                                 \
        const float* Bk_ = Wt + (KT_IDX) * 32;                                \
        _Pragma("unroll")                                                     \
        for (int i_ = 0; i_ < 4; i_++) {                                      \
            const int c_   = tid + 256 * i_;                                  \
            const int row_ = c_ >> 3;                                         \
            const int col_ = (c_ & 7) << 2;                                   \
            const int am_  = bm0 + row_;                                      \
            const float* sa_ = Ak_ + (size_t)(am_ < M ? am_ : 0) * lda + col_;\
            const int sz_    = (am_ < M) ? 16 : 0;                            \
            asm volatile("cp.async.cg.shared.global [%0], [%1], 16, %2;" ::   \
                "r"(abase_ + (unsigned)(row_ * SMLD + col_) * 4), "l"(sa_), "r"(sz_)); \
        }                                                                     \
        _Pragma("unroll")                                                     \
        for (int i_ = 0; i_ < 8; i_++) {                                      \
            const int c_   = tid + 256 * i_;                                  \
            const int row_ = c_ >> 3;                                         \
            const int col_ = (c_ & 7) << 2;                                   \
            const float* sb_ = Bk_ + (size_t)(bn0 + row_) * K + col_;         \
            asm volatile("cp.async.cg.shared.global [%0], [%1], 16;" ::       \
                "r"(bbase_ + (unsigned)(row_ * SMLD + col_) * 4), "l"(sb_));  \
        }                                                                     \
    }                                                                         \
    asm volatile("cp.async.commit_group;");                                   \
} while (0)

// k-slot permutation (A,B share it): group kk slot tig <- k=8kk+2tig,
// slot tig+4 <- k=8kk+2tig+1  =>  one float2 per fragment row.
#define COMPUTE_TILE(ST) do {                                                 \
    const float* Asf_ = smf + (ST) * A_TS;                                    \
    const float* Bsf_ = smf + NSTG * A_TS + (ST) * B_TS;                      \
    _Pragma("unroll")                                                         \
    for (int kk_ = 0; kk_ < 4; kk_++) {                                       \
        const int kb_ = 8 * kk_ + 2 * tig;                                    \
        unsigned Areg[4][4];                                                  \
        unsigned Breg[8][2];                                                  \
        _Pragma("unroll")                                                     \
        for (int mt_ = 0; mt_ < 4; mt_++) {                                   \
            const float* p_ = Asf_ + (wm + mt_ * 16 + gid) * SMLD + kb_;      \
            const float2 lo_ = *(const float2*)(p_);                          \
            const float2 hi_ = *(const float2*)(p_ + 8 * SMLD);               \
            Areg[mt_][0] = __float_as_uint(lo_.x);                            \
            Areg[mt_][1] = __float_as_uint(hi_.x);                            \
            Areg[mt_][2] = __float_as_uint(lo_.y);                            \
            Areg[mt_][3] = __float_as_uint(hi_.y);                            \
        }                                                                     \
        _Pragma("unroll")                                                     \
        for (int nt_ = 0; nt_ < 8; nt_++) {                                   \
            const float2 bv_ = *(const float2*)(Bsf_ + (wn + nt_ * 8 + gid) * SMLD + kb_); \
            Breg[nt_][0] = __float_as_uint(bv_.x);                            \
            Breg[nt_][1] = __float_as_uint(bv_.y);                            \
        }                                                                     \
        _Pragma("unroll")                                                     \
        for (int mt_ = 0; mt_ < 4; mt_++)                                     \
            _Pragma("unroll")                                                 \
            for (int nt_ = 0; nt_ < 8; nt_++)                                 \
                MMA_TF32(acc[mt_][nt_], Areg[mt_][0], Areg[mt_][1],           \
                         Areg[mt_][2], Areg[mt_][3], Breg[nt_][0], Breg[nt_][1]); \
    }                                                                         \
} while (0)

template<int ACT, int RES>
__global__ void __launch_bounds__(256) gemm_tf32(
    const float* __restrict__ A, int lda,
    const float* __restrict__ Wt, int K,
    const float* __restrict__ bias,
    float* __restrict__ C, int ldc,
    const float* __restrict__ res, int ldres,
    int M, int N)
{
    extern __shared__ float smf[];
    const int tid  = threadIdx.x;
    const int bm0  = blockIdx.y * 128;
    const int bn0  = blockIdx.x * 256;
    const int lane = tid & 31, warp = tid >> 5;
    const int wm = (warp & 1) * 64;        // 2 warps along M (64 rows each)
    const int wn = (warp >> 1) * 64;       // 4 warps along N (64 cols each)
    const int gid = lane >> 2, tig = lane & 3;

    const unsigned smbase = (unsigned)__cvta_generic_to_shared(smf);

    float acc[4][8][4];
#pragma unroll
    for (int i = 0; i < 4; i++)
#pragma unroll
        for (int j = 0; j < 8; j++)
#pragma unroll
            for (int r = 0; r < 4; r++) acc[i][j][r] = 0.f;

    const int KT = K >> 5;

    // prologue: 2 stages ahead
    LOAD_TILE(0, 0);
    LOAD_TILE(1, 1);

    for (int kt = 0; kt < KT; kt++) {
        asm volatile("cp.async.wait_group 1;");
        __syncthreads();
        // stage (kt+2)%3 was last read at iteration kt-1 -> barrier orders it
        LOAD_TILE(kt + 2, (kt + 2) % 3);
        COMPUTE_TILE(kt % 3);
    }

    // epilogue
#pragma unroll
    for (int mt = 0; mt < 4; mt++) {
        const int mbase = bm0 + wm + mt * 16 + gid;
#pragma unroll
        for (int half = 0; half < 2; half++) {
            const int m = mbase + half * 8;
            if (m >= M) continue;
#pragma unroll
            for (int nt = 0; nt < 8; nt++) {
                const int n = bn0 + wn + nt * 8 + tig * 2;
                const float2 bv = *(const float2*)(bias + n);
                float v0 = acc[mt][nt][half * 2 + 0] + bv.x;
                float v1 = acc[mt][nt][half * 2 + 1] + bv.y;
                if (RES == 1) {
                    const float2 r = *(const float2*)(res + (size_t)m * ldres + n);
                    v0 += r.x; v1 += r.y;
                }
                if (RES == 2) {
                    const int nw = m >> 6, w = m & 63;
                    const int b = nw >> 10, s = nw & 1023;
                    const float* rp = res + ((size_t)(b * PADS + s + w)) * ldres + n;
                    v0 += rp[0]; v1 += rp[1];
                }
                if (ACT == 1) {
                    v0 = v0 / (1.f + __expf(-v0));
                    v1 = v1 / (1.f + __expf(-v1));
                }
                *(float2*)(C + (size_t)m * ldc + n) = make_float2(v0, v1);
            }
        }
    }
}

// ---------------- small fp32 GEMM (head only, N=10) --------------------------
template<int ACT, int RES>
__global__ void __launch_bounds__(256) gemm_k(
    const float* __restrict__ A, int lda,
    const float* __restrict__ Wt, int K,
    const float* __restrict__ bias,
    float* __restrict__ C, int ldc,
    const float* __restrict__ res, int ldres,
    int M, int N)
{
    __shared__ float As[16][68];
    __shared__ float Bs[16][68];
    const int tid = threadIdx.x;
    const int m0 = blockIdx.y * 64;
    const int n0 = blockIdx.x * 64;
    const int lr = tid >> 2;
    const int lc = (tid & 3) << 2;
    const int ty = tid >> 4;
    const int tx = tid & 15;

    float acc[4][4];
#pragma unroll
    for (int i = 0; i < 4; i++)
#pragma unroll
        for (int j = 0; j < 4; j++) acc[i][j] = 0.f;

    const int am = m0 + lr;
    const int bn = n0 + lr;
    const float* Aptr = A + (size_t)am * lda + lc;
    const float* Wptr = Wt + (size_t)bn * K + lc;
    const bool avalid = (am < M);
    const bool bvalid = (bn < N);

    for (int k0 = 0; k0 < K; k0 += 16) {
        float4 av = make_float4(0.f, 0.f, 0.f, 0.f);
        float4 bv = make_float4(0.f, 0.f, 0.f, 0.f);
        if (avalid) av = *(const float4*)(Aptr + k0);
        if (bvalid) bv = *(const float4*)(Wptr + k0);
        As[lc+0][lr] = av.x; As[lc+1][lr] = av.y;
        As[lc+2][lr] = av.z; As[lc+3][lr] = av.w;
        Bs[lc+0][lr] = bv.x; Bs[lc+1][lr] = bv.y;
        Bs[lc+2][lr] = bv.z; Bs[lc+3][lr] = bv.w;
        __syncthreads();
#pragma unroll
        for (int kk = 0; kk < 16; kk++) {
            float4 a4 = *(const float4*)&As[kk][ty << 2];
            float4 b4 = *(const float4*)&Bs[kk][tx << 2];
            float ar[4] = {a4.x, a4.y, a4.z, a4.w};
            float br[4] = {b4.x, b4.y, b4.z, b4.w};
#pragma unroll
            for (int i = 0; i < 4; i++)
#pragma unroll
                for (int j = 0; j < 4; j++)
                    acc[i][j] = fmaf(ar[i], br[j], acc[i][j]);
        }
        __syncthreads();
    }

#pragma unroll
    for (int i = 0; i < 4; i++) {
        int m = m0 + (ty << 2) + i;
        if (m >= M) continue;
#pragma unroll
        for (int j = 0; j < 4; j++) {
            int n = n0 + (tx << 2) + j;
            if (n >= N) continue;
            float v = acc[i][j] + bias[n];
            if (RES == 1) v += res[(size_t)m * ldres + n];
            if (ACT == 1) v = v / (1.f + __expf(-v));
            C[(size_t)m * ldc + n] = v;
        }
    }
}

// ---------------- layer-0 attention (float4 broadcast loads) -----------------
__global__ void __launch_bounds__(64) attn0_k(const float* __restrict__ qkv0,
                                              float* __restrict__ octx) {
    const int h = blockIdx.x;
    const int n = blockIdx.y;
    const int b = n >> 10, s = n & 1023;
    const int t = threadIdx.x;
    __shared__ float Ks[64][36];
    __shared__ float Vs[64][36];

    const float* row = qkv0 + ((size_t)(b * PADS + s + t)) * (3 * E) + h * 32;
    float4 q4[8];
#pragma unroll
    for (int i = 0; i < 8; i++) {
        q4[i] = *(const float4*)(row + i * 4);
        *(float4*)&Ks[t][i * 4] = *(const float4*)(row + E + i * 4);
        *(float4*)&Vs[t][i * 4] = *(const float4*)(row + 2 * E + i * 4);
    }
    __syncthreads();

    float sc[64];
    float mx = -1e30f;
#pragma unroll 4
    for (int k = 0; k < 64; k++) {
        const float4* k4 = (const float4*)Ks[k];
        float a = 0.f;
#pragma unroll
        for (int i = 0; i < 8; i++) {
            const float4 kv = k4[i];
            a = fmaf(q4[i].x, kv.x, a);
            a = fmaf(q4[i].y, kv.y, a);
            a = fmaf(q4[i].z, kv.z, a);
            a = fmaf(q4[i].w, kv.w, a);
        }
        a *= ATTN_SCALE;
        sc[k] = a;
        mx = fmaxf(mx, a);
    }
    float sum = 0.f;
#pragma unroll 4
    for (int k = 0; k < 64; k++) { sc[k] = __expf(sc[k] - mx); sum += sc[k]; }
    const float inv = 1.f / sum;

    float4 o4[8];
#pragma unroll
    for (int i = 0; i < 8; i++) o4[i] = make_float4(0.f, 0.f, 0.f, 0.f);
#pragma unroll 4
    for (int k = 0; k < 64; k++) {
        const float p = sc[k];
        const float4* v4 = (const float4*)Vs[k];
#pragma unroll
        for (int i = 0; i < 8; i++) {
            const float4 vv = v4[i];
            o4[i].x = fmaf(p, vv.x, o4[i].x);
            o4[i].y = fmaf(p, vv.y, o4[i].y);
            o4[i].z = fmaf(p, vv.z, o4[i].z);
            o4[i].w = fmaf(p, vv.w, o4[i].w);
        }
    }
    float* out = octx + ((size_t)n * 64 + t) * E + h * 32;
#pragma unroll
    for (int i = 0; i < 8; i++) {
        float4 o = o4[i];
        o.x *= inv; o.y *= inv; o.z *= inv; o.w *= inv;
        *(float4*)(out + i * 4) = o;
    }
}

// ---------------- layer-1 attention (single query per window) ----------------
__global__ void __launch_bounds__(256) attn1_k(const float* __restrict__ q1,
                                               const float* __restrict__ kv1,
                                               float* __restrict__ o1) {
    const int n = blockIdx.x;
    const int h = threadIdx.x >> 5, l = threadIdx.x & 31;
    __shared__ float qs[256];
    __shared__ float ps[8][64];
    qs[threadIdx.x] = q1[(size_t)n * E + threadIdx.x];
    __syncthreads();

    const float* kvb = kv1 + (size_t)n * 64 * (2 * E);
    const float* qh  = &qs[h * 32];
    const float* k0p = kvb + (size_t)l * (2 * E) + h * 32;
    const float* k1p = kvb + (size_t)(l + 32) * (2 * E) + h * 32;
    float s0 = 0.f, s1 = 0.f;
#pragma unroll
    for (int d = 0; d < 32; d++) {
        s0 = fmaf(qh[d], k0p[d], s0);
        s1 = fmaf(qh[d], k1p[d], s1);
    }
    s0 *= ATTN_SCALE; s1 *= ATTN_SCALE;
    float m = fmaxf(s0, s1);
#pragma unroll
    for (int o = 16; o; o >>= 1) m = fmaxf(m, __shfl_xor_sync(0xffffffffu, m, o));
    float e0 = __expf(s0 - m), e1 = __expf(s1 - m);
    float sum = e0 + e1;
#pragma unroll
    for (int o = 16; o; o >>= 1) sum += __shfl_xor_sync(0xffffffffu, sum, o);
    const float inv = 1.f / sum;
    ps[h][l] = e0 * inv;
    ps[h][l + 32] = e1 * inv;
    __syncwarp();

    float acc = 0.f;
#pragma unroll 4
    for (int k = 0; k < 64; k++)
        acc = fmaf(ps[h][k], kvb[(size_t)k * (2 * E) + E + h * 32 + l], acc);
    o1[(size_t)n * E + h * 32 + l] = acc;
}

// ---------------- LayerNorm --------------------------------------------------
__global__ void __launch_bounds__(256) ln_k(const float* __restrict__ X,
                                            const float* __restrict__ g,
                                            const float* __restrict__ bb,
                                            float* __restrict__ Y, int M) {
    const int warp = threadIdx.x >> 5, lane = threadIdx.x & 31;
    const int row = blockIdx.x * 8 + warp;
    if (row >= M) return;
    const float* x = X + (size_t)row * E;
    float v[8];
    float s = 0.f;
#pragma unroll
    for (int i = 0; i < 8; i++) { v[i] = x[lane + i * 32]; s += v[i]; }
#pragma unroll
    for (int o = 16; o; o >>= 1) s += __shfl_xor_sync(0xffffffffu, s, o);
    const float mean = s * (1.f / E);
    float var = 0.f;
#pragma unroll
    for (int i = 0; i < 8; i++) { float d = v[i] - mean; var = fmaf(d, d, var); }
#pragma unroll
    for (int o = 16; o; o >>= 1) var += __shfl_xor_sync(0xffffffffu, var, o);
    const float inv = rsqrtf(var * (1.f / E) + 1e-5f);
    float* y = Y + (size_t)row * E;
#pragma unroll
    for (int i = 0; i < 8; i++) {
        int c = lane + i * 32;
        y[c] = (v[i] - mean) * inv * g[c] + bb[c];
    }
}

// ---------------------------------------------------------------------------
extern "C" void kernel_launch(void* const* d_in, const int* in_sizes, int n_in,
                              void* d_out, int out_size) {
    (void)in_sizes; (void)n_in; (void)out_size;
    const float* inputs     = (const float*)d_in[0];
    const float* embed_w    = (const float*)d_in[1];
    const float* embed_b    = (const float*)d_in[2];
    const float* qkv_w      = (const float*)d_in[3];
    const float* qkv_b      = (const float*)d_in[4];
    const float* attn_out_w = (const float*)d_in[5];
    const float* attn_out_b = (const float*)d_in[6];
    const float* ln1_g      = (const float*)d_in[7];
    const float* ln1_b      = (const float*)d_in[8];
    const float* ffn1_w     = (const float*)d_in[9];
    const float* ffn1_b     = (const float*)d_in[10];
    const float* ffn2_w     = (const float*)d_in[11];
    const float* ffn2_b     = (const float*)d_in[12];
    const float* ln2_g      = (const float*)d_in[13];
    const float* ln2_b      = (const float*)d_in[14];
    const float* head_w     = (const float*)d_in[15];
    const float* head_b     = (const float*)d_in[16];
    float* out = (float*)d_out;

    float *emb, *qkv0, *octx, *x1a, *x1, *hbuf, *x2, *kv1;
    float *q1, *o1, *t1a, *t1, *th, *t2;
    cudaGetSymbolAddress((void**)&emb,  g_emb);
    cudaGetSymbolAddress((void**)&qkv0, g_qkv0);
    cudaGetSymbolAddress((void**)&octx, g_octx);
    cudaGetSymbolAddress((void**)&x1a,  g_x1a);
    cudaGetSymbolAddress((void**)&x1,   g_x1);
    cudaGetSymbolAddress((void**)&hbuf, g_hbuf);
    cudaGetSymbolAddress((void**)&x2,   g_x2);
    cudaGetSymbolAddress((void**)&kv1,  g_kv1);
    cudaGetSymbolAddress((void**)&q1,   g_q1);
    cudaGetSymbolAddress((void**)&o1,   g_o1);
    cudaGetSymbolAddress((void**)&t1a,  g_t1a);
    cudaGetSymbolAddress((void**)&t1,   g_t1);
    cudaGetSymbolAddress((void**)&th,   g_th);
    cudaGetSymbolAddress((void**)&t2,   g_t2);

    cudaFuncSetAttribute(gemm_tf32<0,0>, cudaFuncAttributeMaxDynamicSharedMemorySize, GEMM_SMEM);
    cudaFuncSetAttribute(gemm_tf32<0,1>, cudaFuncAttributeMaxDynamicSharedMemorySize, GEMM_SMEM);
    cudaFuncSetAttribute(gemm_tf32<0,2>, cudaFuncAttributeMaxDynamicSharedMemorySize, GEMM_SMEM);
    cudaFuncSetAttribute(gemm_tf32<1,0>, cudaFuncAttributeMaxDynamicSharedMemorySize, GEMM_SMEM);

    // --- embeddings (zero-padded left by W-1): M=1024, N=256, K=64 ---
    zero_pad_k<<<63, 256>>>(emb);
    for (int b = 0; b < BATCH; b++) {
        gemm_tf32<0,0><<<dim3(1, SEQ/128), 256, GEMM_SMEM>>>(
            inputs + (size_t)b * SEQ * FIN, FIN, embed_w, FIN, embed_b,
            emb + ((size_t)b * PADS + (WCTX - 1)) * E, E,
            nullptr, 0, SEQ, E);
    }

    // --- layer-0 QKV per global token: M=2174, N=768, K=256 ---
    gemm_tf32<0,0><<<dim3(3, (BATCH*PADS + 127)/128), 256, GEMM_SMEM>>>(
        emb, E, qkv_w, E, qkv_b, qkv0, 3*E, nullptr, 0, BATCH*PADS, 3*E);

    // --- layer-0 attention ---
    attn0_k<<<dim3(8, NW), 64>>>(qkv0, octx);

    // --- layer-0 attn-out + residual gather -> LN1: M=NT, N=256, K=256 ---
    gemm_tf32<0,2><<<dim3(1, NT/128), 256, GEMM_SMEM>>>(
        octx, E, attn_out_w, E, attn_out_b, x1a, E, emb, E, NT, E);
    ln_k<<<NT / 8, 256>>>(x1a, ln1_g, ln1_b, x1, NT);

    // --- layer-0 FFN ---
    gemm_tf32<1,0><<<dim3(FF/256, NT/128), 256, GEMM_SMEM>>>(
        x1, E, ffn1_w, E, ffn1_b, hbuf, FF, nullptr, 0, NT, FF);
    gemm_tf32<0,1><<<dim3(1, NT/128), 256, GEMM_SMEM>>>(
        hbuf, FF, ffn2_w, FF, ffn2_b, x1a, E, x1, E, NT, E);
    ln_k<<<NT / 8, 256>>>(x1a, ln2_g, ln2_b, x2, NT);

    // --- layer-1: K,V all tokens (N=512); Q last tokens only ---
    gemm_tf32<0,0><<<dim3(2, NT/128), 256, GEMM_SMEM>>>(
        x2, E, qkv_w + (size_t)3*E*E + (size_t)E*E, E,
        qkv_b + 3*E + E, kv1, 2*E, nullptr, 0, NT, 2*E);
    gemm_tf32<0,0><<<dim3(1, NW/128), 256, GEMM_SMEM>>>(
        x2 + (size_t)(WCTX-1)*E, WCTX*E,
        qkv_w + (size_t)3*E*E, E, qkv_b + 3*E,
        q1, E, nullptr, 0, NW, E);

    attn1_k<<<NW, 256>>>(q1, kv1, o1);

    // --- layer-1 tail ---
    gemm_tf32<0,1><<<dim3(1, NW/128), 256, GEMM_SMEM>>>(
        o1, E, attn_out_w + (size_t)E*E, E, attn_out_b + E,
        t1a, E, x2 + (size_t)(WCTX-1)*E, WCTX*E, NW, E);
    ln_k<<<NW / 8, 256>>>(t1a, ln1_g + E, ln1_b + E, t1, NW);
    gemm_tf32<1,0><<<dim3(FF/256, NW/128), 256, GEMM_SMEM>>>(
        t1, E, ffn1_w + (size_t)FF*E, E, ffn1_b + FF, th, FF,
        nullptr, 0, NW, FF);
    gemm_tf32<0,1><<<dim3(1, NW/128), 256, GEMM_SMEM>>>(
        th, FF, ffn2_w + (size_t)E*FF, FF, ffn2_b + E, t1a, E, t1, E, NW, E);
    ln_k<<<NW / 8, 256>>>(t1a, ln2_g + E, ln2_b + E, t2, NW);

    // --- head (N=10, fp32) ---
    gemm_k<0,0><<<dim3(1, NW/64), 256>>>(
        t2, E, head_w, E, head_b, out, 10, nullptr, 0, NW, 10);
}

// round 9
// speedup vs baseline: 3.1484x; 1.1078x over previous
#include <cuda_runtime.h>
#include <cuda_fp16.h>
#include <math.h>
#include <stdint.h>

// ---------------------------------------------------------------------------
// Round 8: fp16 operands (same 11-bit significand as tf32) with
// mma.sync.m16n8k16.f16 / fp32 accumulate: 2x FLOPs per MMA instruction,
// half the operand traffic. Within-16 k-permutation makes every thread's
// fragment a single LDS.64; permutation applied consistently to all
// activation/weight tensors (dot products & LN are permutation-invariant).
// Residual/LN paths remain fp32.
// ---------------------------------------------------------------------------

#define BATCH 2
#define SEQ   1024
#define E     256
#define FIN   64
#define FF    1024
#define WCTX  64
#define NW    (BATCH*SEQ)
#define PADS  (SEQ + WCTX - 1)
#define NT    (NW*WCTX)

#define ATTN_SCALE 0.17677669529663687f

// ---------------- scratch ----------------------------------------------------
// fp32 (residual / LN paths)
__device__ __align__(128) float g_emb32[BATCH*PADS*E];
__device__ __align__(128) float g_x1a  [NT*E];
__device__ __align__(128) float g_x1_32[NT*E];
__device__ __align__(128) float g_x2_32[NT*E];
__device__ __align__(128) float g_t1a  [NW*E];
__device__ __align__(128) float g_t1_32[NW*E];
__device__ __align__(128) float g_t2   [NW*E];
// fp16 permuted (GEMM operands)
__device__ __align__(128) __half g_in16  [BATCH*SEQ*FIN];
__device__ __align__(128) __half g_embw16[E*FIN];
__device__ __align__(128) __half g_qkvw16[2*3*E*E];
__device__ __align__(128) __half g_aow16 [2*E*E];
__device__ __align__(128) __half g_f1w16 [2*FF*E];
__device__ __align__(128) __half g_f2w16 [2*E*FF];
__device__ __align__(128) __half g_emb16 [BATCH*PADS*E];
__device__ __align__(128) __half g_qkv16 [BATCH*PADS*3*E];
__device__ __align__(128) __half g_octx16[NT*E];
__device__ __align__(128) __half g_x1_16 [NT*E];
__device__ __align__(128) __half g_h16   [NT*FF];
__device__ __align__(128) __half g_x2_16 [NT*E];
__device__ __align__(128) __half g_kv16  [NT*2*E];
__device__ __align__(128) __half g_q1_16 [NW*E];
__device__ __align__(128) __half g_o1_16 [NW*E];
__device__ __align__(128) __half g_t1_16 [NW*E];
__device__ __align__(128) __half g_th16  [NW*FF];

// within-16 permutation: stored pos for orig k
__device__ __forceinline__ int kperm(int k) {
    int k15 = k & 15;
    int p = (k15 < 8) ? (4 * (k15 >> 1) + (k15 & 1))
                      : (4 * ((k15 - 8) >> 1) + 2 + (k15 & 1));
    return (k & ~15) | p;
}

// fp32 -> fp16 with k-permutation (weights + raw input)
__global__ void conv_perm_k(const float* __restrict__ src, __half* __restrict__ dst,
                            int rows, int cols) {
    int idx = blockIdx.x * 256 + threadIdx.x;
    if (idx >= rows * cols) return;
    int n = idx / cols, k = idx - n * cols;
    dst[n * cols + kperm(k)] = __float2half(src[idx]);
}

__global__ void zero_pad_k(float* emb32, __half* emb16) {
    int i = blockIdx.x * 256 + threadIdx.x;
    if (i < (WCTX - 1) * E) {
        emb32[i] = 0.f;                 emb16[i] = __float2half(0.f);
        emb32[(size_t)PADS * E + i] = 0.f;
        emb16[(size_t)PADS * E + i] = __float2half(0.f);
    }
}

// ---------------- fp16 tensor-core GEMM --------------------------------------
// C[M,N] = act( A[M,K] @ W[N,K]^T + bias + residual )  (A,W fp16 k-permuted)
// BM=128, BN=256, BK=32, 256 threads (8 warps 2Mx4N, warp tile 64x64),
// 4-stage cp.async ring, one barrier per K-tile. N%256==0, K%32==0.

#define SMLD_H 40                            /* smem row stride in halves (80B) */
#define A_TSB (128*SMLD_H*2)                 /* 10240 B */
#define B_TSB (256*SMLD_H*2)                 /* 20480 B */
#define NSTG 4
#define GEMM_SMEM (NSTG*(A_TSB+B_TSB))       /* 122880 B */

#define MMA_F16(d, a0, a1, a2, a3, b0, b1) \
  asm volatile("mma.sync.aligned.m16n8k16.row.col.f32.f16.f16.f32 " \
    "{%0,%1,%2,%3}, {%4,%5,%6,%7}, {%8,%9}, {%0,%1,%2,%3};" \
    : "+f"(d[0]), "+f"(d[1]), "+f"(d[2]), "+f"(d[3]) \
    : "r"(a0), "r"(a1), "r"(a2), "r"(a3), "r"(b0), "r"(b1))

#define LOAD_TILE(KT_IDX, ST) do {                                            \
    if ((KT_IDX) < KT) {                                                      \
        const unsigned abase_ = smbase + (unsigned)(ST) * A_TSB;              \
        const unsigned bbase_ = smbase + (unsigned)NSTG * A_TSB + (unsigned)(ST) * B_TSB; \
        const __half* Ak_ = A + (size_t)(KT_IDX) * 32;                        \
        const __half* Bk_ = Wt + (size_t)(KT_IDX) * 32;                       \
        _Pragma("unroll")                                                     \
        for (int i_ = 0; i_ < 2; i_++) {       /* A: 128 rows x 4 chunks */   \
            const int c_   = tid + 256 * i_;                                  \
            const int row_ = c_ >> 2;                                         \
            const int ch_  = c_ & 3;                                          \
            const int am_  = bm0 + row_;                                      \
            const __half* sa_ = Ak_ + (size_t)(am_ < M ? am_ : 0) * lda + ch_ * 8; \
            const int sz_     = (am_ < M) ? 16 : 0;                           \
            asm volatile("cp.async.cg.shared.global [%0], [%1], 16, %2;" ::   \
                "r"(abase_ + (unsigned)(row_ * 80 + ch_ * 16)), "l"(sa_), "r"(sz_)); \
        }                                                                     \
        _Pragma("unroll")                                                     \
        for (int i_ = 0; i_ < 4; i_++) {       /* B: 256 rows x 4 chunks */   \
            const int c_   = tid + 256 * i_;                                  \
            const int row_ = c_ >> 2;                                         \
            const int ch_  = c_ & 3;                                          \
            const __half* sb_ = Bk_ + (size_t)(bn0 + row_) * K + ch_ * 8;     \
            asm volatile("cp.async.cg.shared.global [%0], [%1], 16;" ::       \
                "r"(bbase_ + (unsigned)(row_ * 80 + ch_ * 16)), "l"(sb_));    \
        }                                                                     \
    }                                                                         \
    asm volatile("cp.async.commit_group;");                                   \
} while (0)

#define COMPUTE_TILE(ST) do {                                                 \
    const __half* Asf_ = smh + (ST) * (A_TSB / 2);                            \
    const __half* Bsf_ = smh + NSTG * (A_TSB / 2) + (ST) * (B_TSB / 2);       \
    _Pragma("unroll")                                                         \
    for (int g_ = 0; g_ < 2; g_++) {                                          \
        const int kb_ = 16 * g_ + 4 * tig;                                    \
        unsigned Ar[4][4];                                                    \
        unsigned Br[8][2];                                                    \
        _Pragma("unroll")                                                     \
        for (int mt_ = 0; mt_ < 4; mt_++) {                                   \
            const __half* p_ = Asf_ + (wm + mt_ * 16 + gid) * SMLD_H + kb_;   \
            const uint2 lo_ = *(const uint2*)(p_);                            \
            const uint2 hi_ = *(const uint2*)(p_ + 8 * SMLD_H);               \
            Ar[mt_][0] = lo_.x;  /* a0: row g,   k 2t,2t+1   */               \
            Ar[mt_][1] = hi_.x;  /* a1: row g+8, k 2t,2t+1   */               \
            Ar[mt_][2] = lo_.y;  /* a2: row g,   k 2t+8,2t+9 */               \
            Ar[mt_][3] = hi_.y;  /* a3: row g+8, k 2t+8,2t+9 */               \
        }                                                                     \
        _Pragma("unroll")                                                     \
        for (int nt_ = 0; nt_ < 8; nt_++) {                                   \
            const uint2 bv_ = *(const uint2*)(Bsf_ + (wn + nt_ * 8 + gid) * SMLD_H + kb_); \
            Br[nt_][0] = bv_.x;                                               \
            Br[nt_][1] = bv_.y;                                               \
        }                                                                     \
        _Pragma("unroll")                                                     \
        for (int mt_ = 0; mt_ < 4; mt_++)                                     \
            _Pragma("unroll")                                                 \
            for (int nt_ = 0; nt_ < 8; nt_++)                                 \
                MMA_F16(acc[mt_][nt_], Ar[mt_][0], Ar[mt_][1],                \
                        Ar[mt_][2], Ar[mt_][3], Br[nt_][0], Br[nt_][1]);      \
    }                                                                         \
} while (0)

template<int ACT, int RES, int O32, int O16>
__global__ void __launch_bounds__(256) gemm_h(
    const __half* __restrict__ A, int lda,
    const __half* __restrict__ Wt, int K,
    const float* __restrict__ bias,
    float* __restrict__ C32, __half* __restrict__ C16, int ldc,
    const float* __restrict__ res, int ldres,
    int M, int N)
{
    extern __shared__ __half smh[];
    const int tid  = threadIdx.x;
    const int bm0  = blockIdx.y * 128;
    const int bn0  = blockIdx.x * 256;
    const int lane = tid & 31, warp = tid >> 5;
    const int wm = (warp & 1) * 64;
    const int wn = (warp >> 1) * 64;
    const int gid = lane >> 2, tig = lane & 3;

    const unsigned smbase = (unsigned)__cvta_generic_to_shared(smh);

    float acc[4][8][4];
#pragma unroll
    for (int i = 0; i < 4; i++)
#pragma unroll
        for (int j = 0; j < 8; j++)
#pragma unroll
            for (int r = 0; r < 4; r++) acc[i][j][r] = 0.f;

    const int KT = K >> 5;

    LOAD_TILE(0, 0);
    LOAD_TILE(1, 1);
    LOAD_TILE(2, 2);

    for (int kt = 0; kt < KT; kt++) {
        asm volatile("cp.async.wait_group 2;");
        __syncthreads();
        LOAD_TILE(kt + 3, (kt + 3) & 3);
        COMPUTE_TILE(kt & 3);
    }

    // epilogue
#pragma unroll
    for (int mt = 0; mt < 4; mt++) {
        const int mbase = bm0 + wm + mt * 16 + gid;
#pragma unroll
        for (int half_ = 0; half_ < 2; half_++) {
            const int m = mbase + half_ * 8;
            if (m >= M) continue;
#pragma unroll
            for (int nt = 0; nt < 8; nt++) {
                const int n = bn0 + wn + nt * 8 + tig * 2;
                const float2 bv = *(const float2*)(bias + n);
                float v0 = acc[mt][nt][half_ * 2 + 0] + bv.x;
                float v1 = acc[mt][nt][half_ * 2 + 1] + bv.y;
                if (RES == 1) {
                    const float2 r = *(const float2*)(res + (size_t)m * ldres + n);
                    v0 += r.x; v1 += r.y;
                }
                if (RES == 2) {
                    const int nw = m >> 6, w = m & 63;
                    const int b = nw >> 10, s = nw & 1023;
                    const float* rp = res + ((size_t)(b * PADS + s + w)) * ldres + n;
                    v0 += rp[0]; v1 += rp[1];
                }
                if (ACT == 1) {
                    v0 = v0 / (1.f + __expf(-v0));
                    v1 = v1 / (1.f + __expf(-v1));
                }
                if (O32)
                    *(float2*)(C32 + (size_t)m * ldc + n) = make_float2(v0, v1);
                if (O16) {
                    // permuted store: pos = base16 + 4*tig + 2*(nt&1)
                    const int p = (bn0 + wn + ((nt >> 1) << 4)) + 4 * tig + 2 * (nt & 1);
                    *(__half2*)(C16 + (size_t)m * ldc + p) =
                        __float22half2_rn(make_float2(v0, v1));
                }
            }
        }
    }
}

// ---------------- small fp32 GEMM (head only, N=10) --------------------------
__global__ void __launch_bounds__(256) gemm_head(
    const float* __restrict__ A, int lda,
    const float* __restrict__ Wt, int K,
    const float* __restrict__ bias,
    float* __restrict__ C, int ldc, int M, int N)
{
    __shared__ float As[16][68];
    __shared__ float Bs[16][68];
    const int tid = threadIdx.x;
    const int m0 = blockIdx.y * 64;
    const int lr = tid >> 2;
    const int lc = (tid & 3) << 2;
    const int ty = tid >> 4;
    const int tx = tid & 15;

    float acc[4][4];
#pragma unroll
    for (int i = 0; i < 4; i++)
#pragma unroll
        for (int j = 0; j < 4; j++) acc[i][j] = 0.f;

    const int am = m0 + lr;
    const float* Aptr = A + (size_t)am * lda + lc;
    const float* Wptr = Wt + (size_t)lr * K + lc;
    const bool avalid = (am < M);
    const bool bvalid = (lr < N);

    for (int k0 = 0; k0 < K; k0 += 16) {
        float4 av = make_float4(0.f, 0.f, 0.f, 0.f);
        float4 bv = make_float4(0.f, 0.f, 0.f, 0.f);
        if (avalid) av = *(const float4*)(Aptr + k0);
        if (bvalid) bv = *(const float4*)(Wptr + k0);
        As[lc+0][lr] = av.x; As[lc+1][lr] = av.y;
        As[lc+2][lr] = av.z; As[lc+3][lr] = av.w;
        Bs[lc+0][lr] = bv.x; Bs[lc+1][lr] = bv.y;
        Bs[lc+2][lr] = bv.z; Bs[lc+3][lr] = bv.w;
        __syncthreads();
#pragma unroll
        for (int kk = 0; kk < 16; kk++) {
            float4 a4 = *(const float4*)&As[kk][ty << 2];
            float4 b4 = *(const float4*)&Bs[kk][tx << 2];
            float ar[4] = {a4.x, a4.y, a4.z, a4.w};
            float br[4] = {b4.x, b4.y, b4.z, b4.w};
#pragma unroll
            for (int i = 0; i < 4; i++)
#pragma unroll
                for (int j = 0; j < 4; j++)
                    acc[i][j] = fmaf(ar[i], br[j], acc[i][j]);
        }
        __syncthreads();
    }

#pragma unroll
    for (int i = 0; i < 4; i++) {
        int m = m0 + (ty << 2) + i;
        if (m >= M) continue;
#pragma unroll
        for (int j = 0; j < 4; j++) {
            int n = (tx << 2) + j;
            if (n >= N) continue;
            C[(size_t)m * ldc + n] = acc[i][j] + bias[n];
        }
    }
}

// ---------------- layer-0 attention (fp16 source, fp32 math) -----------------
__global__ void __launch_bounds__(64) attn0_k(const __half* __restrict__ qkv16,
                                              __half* __restrict__ octx16) {
    const int h = blockIdx.x;
    const int n = blockIdx.y;
    const int b = n >> 10, s = n & 1023;
    const int t = threadIdx.x;
    __shared__ float Ks[64][36];
    __shared__ float Vs[64][36];

    const __half2* rw = (const __half2*)(qkv16 + (size_t)(b * PADS + s + t) * (3 * E) + h * 32);
    float4 q4[8];
#pragma unroll
    for (int i = 0; i < 8; i++) {
        float2 a = __half22float2(rw[2 * i]);
        float2 c = __half22float2(rw[2 * i + 1]);
        q4[i] = make_float4(a.x, a.y, c.x, c.y);
        float2 ka = __half22float2(rw[128 + 2 * i]);
        float2 kb = __half22float2(rw[128 + 2 * i + 1]);
        *(float4*)&Ks[t][i * 4] = make_float4(ka.x, ka.y, kb.x, kb.y);
        float2 va = __half22float2(rw[256 + 2 * i]);
        float2 vb = __half22float2(rw[256 + 2 * i + 1]);
        *(float4*)&Vs[t][i * 4] = make_float4(va.x, va.y, vb.x, vb.y);
    }
    __syncthreads();

    float sc[64];
    float mx = -1e30f;
#pragma unroll 4
    for (int k = 0; k < 64; k++) {
        const float4* k4 = (const float4*)Ks[k];
        float a = 0.f;
#pragma unroll
        for (int i = 0; i < 8; i++) {
            const float4 kv = k4[i];
            a = fmaf(q4[i].x, kv.x, a);
            a = fmaf(q4[i].y, kv.y, a);
            a = fmaf(q4[i].z, kv.z, a);
            a = fmaf(q4[i].w, kv.w, a);
        }
        a *= ATTN_SCALE;
        sc[k] = a;
        mx = fmaxf(mx, a);
    }
    float sum = 0.f;
#pragma unroll 4
    for (int k = 0; k < 64; k++) { sc[k] = __expf(sc[k] - mx); sum += sc[k]; }
    const float inv = 1.f / sum;

    float4 o4[8];
#pragma unroll
    for (int i = 0; i < 8; i++) o4[i] = make_float4(0.f, 0.f, 0.f, 0.f);
#pragma unroll 4
    for (int k = 0; k < 64; k++) {
        const float p = sc[k];
        const float4* v4 = (const float4*)Vs[k];
#pragma unroll
        for (int i = 0; i < 8; i++) {
            const float4 vv = v4[i];
            o4[i].x = fmaf(p, vv.x, o4[i].x);
            o4[i].y = fmaf(p, vv.y, o4[i].y);
            o4[i].z = fmaf(p, vv.z, o4[i].z);
            o4[i].w = fmaf(p, vv.w, o4[i].w);
        }
    }
    __half2* out = (__half2*)(octx16 + ((size_t)n * 64 + t) * E + h * 32);
#pragma unroll
    for (int i = 0; i < 8; i++) {
        out[2 * i]     = __float22half2_rn(make_float2(o4[i].x * inv, o4[i].y * inv));
        out[2 * i + 1] = __float22half2_rn(make_float2(o4[i].z * inv, o4[i].w * inv));
    }
}

// ---------------- layer-1 attention ------------------------------------------
__global__ void __launch_bounds__(256) attn1_k(const __half* __restrict__ q1,
                                               const __half* __restrict__ kv1,
                                               __half* __restrict__ o1) {
    const int n = blockIdx.x;
    const int h = threadIdx.x >> 5, l = threadIdx.x & 31;
    __shared__ float qs[256];
    __shared__ float ps[8][64];
    qs[threadIdx.x] = __half2float(q1[(size_t)n * E + threadIdx.x]);
    __syncthreads();

    const __half* kvb = kv1 + (size_t)n * 64 * (2 * E);
    const float* qh  = &qs[h * 32];
    const __half2* k0p = (const __half2*)(kvb + (size_t)l * (2 * E) + h * 32);
    const __half2* k1p = (const __half2*)(kvb + (size_t)(l + 32) * (2 * E) + h * 32);
    float s0 = 0.f, s1 = 0.f;
#pragma unroll
    for (int d = 0; d < 16; d++) {
        const float2 a = __half22float2(k0p[d]);
        const float2 b = __half22float2(k1p[d]);
        s0 = fmaf(qh[2*d], a.x, s0); s0 = fmaf(qh[2*d+1], a.y, s0);
        s1 = fmaf(qh[2*d], b.x, s1); s1 = fmaf(qh[2*d+1], b.y, s1);
    }
    s0 *= ATTN_SCALE; s1 *= ATTN_SCALE;
    float m = fmaxf(s0, s1);
#pragma unroll
    for (int o = 16; o; o >>= 1) m = fmaxf(m, __shfl_xor_sync(0xffffffffu, m, o));
    float e0 = __expf(s0 - m), e1 = __expf(s1 - m);
    float sum = e0 + e1;
#pragma unroll
    for (int o = 16; o; o >>= 1) sum += __shfl_xor_sync(0xffffffffu, sum, o);
    const float inv = 1.f / sum;
    ps[h][l] = e0 * inv;
    ps[h][l + 32] = e1 * inv;
    __syncwarp();

    float acc = 0.f;
#pragma unroll 4
    for (int k = 0; k < 64; k++)
        acc = fmaf(ps[h][k], __half2float(kvb[(size_t)k * (2 * E) + E + h * 32 + l]), acc);
    o1[(size_t)n * E + h * 32 + l] = __float2half(acc);
}

// ---------------- LayerNorm: fp32 in -> fp32 out + fp16 permuted out ---------
__global__ void __launch_bounds__(256) ln_k(const float* __restrict__ X,
                                            const float* __restrict__ g,
                                            const float* __restrict__ bb,
                                            float* __restrict__ Y32,
                                            __half* __restrict__ Y16, int M) {
    const int warp = threadIdx.x >> 5, lane = threadIdx.x & 31;
    const int row = blockIdx.x * 8 + warp;
    if (row >= M) return;
    const float* x = X + (size_t)row * E;
    float2 v[4];
    int cc[4];
    float s = 0.f;
#pragma unroll
    for (int i = 0; i < 4; i++) {
        const int u = lane + i * 32;          // half2 output index 0..127
        const int q0 = 2 * u;
        const int q15 = q0 & 15;
        const int t = q15 >> 2;
        const int c0 = (q0 & ~15) | (2 * t + ((q15 & 2) ? 8 : 0));
        cc[i] = c0;
        v[i] = *(const float2*)(x + c0);
        s += v[i].x + v[i].y;
    }
#pragma unroll
    for (int o = 16; o; o >>= 1) s += __shfl_xor_sync(0xffffffffu, s, o);
    const float mean = s * (1.f / E);
    float var = 0.f;
#pragma unroll
    for (int i = 0; i < 4; i++) {
        float dx = v[i].x - mean, dy = v[i].y - mean;
        var = fmaf(dx, dx, var); var = fmaf(dy, dy, var);
    }
#pragma unroll
    for (int o = 16; o; o >>= 1) var += __shfl_xor_sync(0xffffffffu, var, o);
    const float inv = rsqrtf(var * (1.f / E) + 1e-5f);
#pragma unroll
    for (int i = 0; i < 4; i++) {
        const int c0 = cc[i];
        const float2 gg = *(const float2*)(g + c0);
        const float2 bv = *(const float2*)(bb + c0);
        float y0 = (v[i].x - mean) * inv * gg.x + bv.x;
        float y1 = (v[i].y - mean) * inv * gg.y + bv.y;
        *(float2*)(Y32 + (size_t)row * E + c0) = make_float2(y0, y1);
        *(__half2*)(Y16 + (size_t)row * E + 2 * (lane + i * 32)) =
            __float22half2_rn(make_float2(y0, y1));
    }
}

// ---------------------------------------------------------------------------
extern "C" void kernel_launch(void* const* d_in, const int* in_sizes, int n_in,
                              void* d_out, int out_size) {
    (void)in_sizes; (void)n_in; (void)out_size;
    const float* inputs     = (const float*)d_in[0];
    const float* embed_w    = (const float*)d_in[1];
    const float* embed_b    = (const float*)d_in[2];
    const float* qkv_w      = (const float*)d_in[3];
    const float* qkv_b      = (const float*)d_in[4];
    const float* attn_out_w = (const float*)d_in[5];
    const float* attn_out_b = (const float*)d_in[6];
    const float* ln1_g      = (const float*)d_in[7];
    const float* ln1_b      = (const float*)d_in[8];
    const float* ffn1_w     = (const float*)d_in[9];
    const float* ffn1_b     = (const float*)d_in[10];
    const float* ffn2_w     = (const float*)d_in[11];
    const float* ffn2_b     = (const float*)d_in[12];
    const float* ln2_g      = (const float*)d_in[13];
    const float* ln2_b      = (const float*)d_in[14];
    const float* head_w     = (const float*)d_in[15];
    const float* head_b     = (const float*)d_in[16];
    float* out = (float*)d_out;

    float *emb32, *x1a, *x1_32, *x2_32, *t1a, *t1_32, *t2;
    __half *in16, *embw16, *qkvw16, *aow16, *f1w16, *f2w16;
    __half *emb16, *qkv16, *octx16, *x1_16, *h16, *x2_16, *kv16;
    __half *q1_16, *o1_16, *t1_16, *th16;
    cudaGetSymbolAddress((void**)&emb32, g_emb32);
    cudaGetSymbolAddress((void**)&x1a,   g_x1a);
    cudaGetSymbolAddress((void**)&x1_32, g_x1_32);
    cudaGetSymbolAddress((void**)&x2_32, g_x2_32);
    cudaGetSymbolAddress((void**)&t1a,   g_t1a);
    cudaGetSymbolAddress((void**)&t1_32, g_t1_32);
    cudaGetSymbolAddress((void**)&t2,    g_t2);
    cudaGetSymbolAddress((void**)&in16,  g_in16);
    cudaGetSymbolAddress((void**)&embw16,g_embw16);
    cudaGetSymbolAddress((void**)&qkvw16,g_qkvw16);
    cudaGetSymbolAddress((void**)&aow16, g_aow16);
    cudaGetSymbolAddress((void**)&f1w16, g_f1w16);
    cudaGetSymbolAddress((void**)&f2w16, g_f2w16);
    cudaGetSymbolAddress((void**)&emb16, g_emb16);
    cudaGetSymbolAddress((void**)&qkv16, g_qkv16);
    cudaGetSymbolAddress((void**)&octx16,g_octx16);
    cudaGetSymbolAddress((void**)&x1_16, g_x1_16);
    cudaGetSymbolAddress((void**)&h16,   g_h16);
    cudaGetSymbolAddress((void**)&x2_16, g_x2_16);
    cudaGetSymbolAddress((void**)&kv16,  g_kv16);
    cudaGetSymbolAddress((void**)&q1_16, g_q1_16);
    cudaGetSymbolAddress((void**)&o1_16, g_o1_16);
    cudaGetSymbolAddress((void**)&t1_16, g_t1_16);
    cudaGetSymbolAddress((void**)&th16,  g_th16);

    cudaFuncSetAttribute(gemm_h<0,0,1,1>, cudaFuncAttributeMaxDynamicSharedMemorySize, GEMM_SMEM);
    cudaFuncSetAttribute(gemm_h<0,0,0,1>, cudaFuncAttributeMaxDynamicSharedMemorySize, GEMM_SMEM);
    cudaFuncSetAttribute(gemm_h<0,2,1,0>, cudaFuncAttributeMaxDynamicSharedMemorySize, GEMM_SMEM);
    cudaFuncSetAttribute(gemm_h<1,0,0,1>, cudaFuncAttributeMaxDynamicSharedMemorySize, GEMM_SMEM);
    cudaFuncSetAttribute(gemm_h<0,1,1,0>, cudaFuncAttributeMaxDynamicSharedMemorySize, GEMM_SMEM);

    // --- weight / input conversion (fp32 -> fp16, k-permuted) ---
    conv_perm_k<<<(BATCH*SEQ*FIN + 255)/256, 256>>>(inputs, in16, BATCH*SEQ, FIN);
    conv_perm_k<<<(E*FIN + 255)/256, 256>>>(embed_w, embw16, E, FIN);
    conv_perm_k<<<(2*3*E*E + 255)/256, 256>>>(qkv_w, qkvw16, 2*3*E, E);
    conv_perm_k<<<(2*E*E + 255)/256, 256>>>(attn_out_w, aow16, 2*E, E);
    conv_perm_k<<<(2*FF*E + 255)/256, 256>>>(ffn1_w, f1w16, 2*FF, E);
    conv_perm_k<<<(2*E*FF + 255)/256, 256>>>(ffn2_w, f2w16, 2*E, FF);

    // --- embeddings (zero-padded left by W-1) ---
    zero_pad_k<<<63, 256>>>(emb32, emb16);
    for (int b = 0; b < BATCH; b++) {
        gemm_h<0,0,1,1><<<dim3(1, SEQ/128), 256, GEMM_SMEM>>>(
            in16 + (size_t)b * SEQ * FIN, FIN, embw16, FIN, embed_b,
            emb32 + ((size_t)b * PADS + (WCTX - 1)) * E,
            emb16 + ((size_t)b * PADS + (WCTX - 1)) * E, E,
            nullptr, 0, SEQ, E);
    }

    // --- layer-0 QKV per global token ---
    gemm_h<0,0,0,1><<<dim3(3, (BATCH*PADS + 127)/128), 256, GEMM_SMEM>>>(
        emb16, E, qkvw16, E, qkv_b, nullptr, qkv16, 3*E, nullptr, 0,
        BATCH*PADS, 3*E);

    // --- layer-0 attention ---
    attn0_k<<<dim3(8, NW), 64>>>(qkv16, octx16);

    // --- layer-0 attn-out + residual gather -> LN1 ---
    gemm_h<0,2,1,0><<<dim3(1, NT/128), 256, GEMM_SMEM>>>(
        octx16, E, aow16, E, attn_out_b, x1a, nullptr, E, emb32, E, NT, E);
    ln_k<<<NT / 8, 256>>>(x1a, ln1_g, ln1_b, x1_32, x1_16, NT);

    // --- layer-0 FFN ---
    gemm_h<1,0,0,1><<<dim3(FF/256, NT/128), 256, GEMM_SMEM>>>(
        x1_16, E, f1w16, E, ffn1_b, nullptr, h16, FF, nullptr, 0, NT, FF);
    gemm_h<0,1,1,0><<<dim3(1, NT/128), 256, GEMM_SMEM>>>(
        h16, FF, f2w16, FF, ffn2_b, x1a, nullptr, E, x1_32, E, NT, E);
    ln_k<<<NT / 8, 256>>>(x1a, ln2_g, ln2_b, x2_32, x2_16, NT);

    // --- layer-1: K,V all tokens; Q last tokens only ---
    gemm_h<0,0,0,1><<<dim3(2, NT/128), 256, GEMM_SMEM>>>(
        x2_16, E, qkvw16 + (size_t)3*E*E + (size_t)E*E, E,
        qkv_b + 3*E + E, nullptr, kv16, 2*E, nullptr, 0, NT, 2*E);
    gemm_h<0,0,0,1><<<dim3(1, NW/128), 256, GEMM_SMEM>>>(
        x2_16 + (size_t)(WCTX-1)*E, WCTX*E,
        qkvw16 + (size_t)3*E*E, E, qkv_b + 3*E,
        nullptr, q1_16, E, nullptr, 0, NW, E);

    attn1_k<<<NW, 256>>>(q1_16, kv16, o1_16);

    // --- layer-1 tail ---
    gemm_h<0,1,1,0><<<dim3(1, NW/128), 256, GEMM_SMEM>>>(
        o1_16, E, aow16 + (size_t)E*E, E, attn_out_b + E,
        t1a, nullptr, E, x2_32 + (size_t)(WCTX-1)*E, WCTX*E, NW, E);
    ln_k<<<NW / 8, 256>>>(t1a, ln1_g + E, ln1_b + E, t1_32, t1_16, NW);
    gemm_h<1,0,0,1><<<dim3(FF/256, NW/128), 256, GEMM_SMEM>>>(
        t1_16, E, f1w16 + (size_t)FF*E, E, ffn1_b + FF,
        nullptr, th16, FF, nullptr, 0, NW, FF);
    gemm_h<0,1,1,0><<<dim3(1, NW/128), 256, GEMM_SMEM>>>(
        th16, FF, f2w16 + (size_t)E*FF, FF, ffn2_b + E,
        t1a, nullptr, E, t1_32, E, NW, E);
    ln_k<<<NW / 8, 256>>>(t1a, ln2_g + E, ln2_b + E, t2, th16 /*dummy*/, NW);

    // --- head (N=10, fp32, unpermuted t2) ---
    gemm_head<<<dim3(1, NW/64), 256>>>(
        t2, E, head_w, E, head_b, out, 10, NW, 10);
}

// round 10
// speedup vs baseline: 3.5762x; 1.1359x over previous
#include <cuda_runtime.h>
#include <cuda_fp16.h>
#include <math.h>
#include <stdint.h>

// ---------------------------------------------------------------------------
// Round 10: fp16 GEMM reshaped for occupancy: BN=128, warp tile 64x32,
// <=128 regs, launch_bounds(256,2) -> 2 CTAs/SM = 16 warps (4/SMSP), double
// the latency-hiding of every prior config. Everything else as R8.
// ---------------------------------------------------------------------------

#define BATCH 2
#define SEQ   1024
#define E     256
#define FIN   64
#define FF    1024
#define WCTX  64
#define NW    (BATCH*SEQ)
#define PADS  (SEQ + WCTX - 1)
#define NT    (NW*WCTX)

#define ATTN_SCALE 0.17677669529663687f

// ---------------- scratch ----------------------------------------------------
__device__ __align__(128) float g_emb32[BATCH*PADS*E];
__device__ __align__(128) float g_x1a  [NT*E];
__device__ __align__(128) float g_x1_32[NT*E];
__device__ __align__(128) float g_x2_32[NT*E];
__device__ __align__(128) float g_t1a  [NW*E];
__device__ __align__(128) float g_t1_32[NW*E];
__device__ __align__(128) float g_t2   [NW*E];
__device__ __align__(128) __half g_in16  [BATCH*SEQ*FIN];
__device__ __align__(128) __half g_embw16[E*FIN];
__device__ __align__(128) __half g_qkvw16[2*3*E*E];
__device__ __align__(128) __half g_aow16 [2*E*E];
__device__ __align__(128) __half g_f1w16 [2*FF*E];
__device__ __align__(128) __half g_f2w16 [2*E*FF];
__device__ __align__(128) __half g_emb16 [BATCH*PADS*E];
__device__ __align__(128) __half g_qkv16 [BATCH*PADS*3*E];
__device__ __align__(128) __half g_octx16[NT*E];
__device__ __align__(128) __half g_x1_16 [NT*E];
__device__ __align__(128) __half g_h16   [NT*FF];
__device__ __align__(128) __half g_x2_16 [NT*E];
__device__ __align__(128) __half g_kv16  [NT*2*E];
__device__ __align__(128) __half g_q1_16 [NW*E];
__device__ __align__(128) __half g_o1_16 [NW*E];
__device__ __align__(128) __half g_t1_16 [NW*E];
__device__ __align__(128) __half g_th16  [NW*FF];

// within-16 permutation: stored pos for orig k
__device__ __forceinline__ int kperm(int k) {
    int k15 = k & 15;
    int p = (k15 < 8) ? (4 * (k15 >> 1) + (k15 & 1))
                      : (4 * ((k15 - 8) >> 1) + 2 + (k15 & 1));
    return (k & ~15) | p;
}

__global__ void conv_perm_k(const float* __restrict__ src, __half* __restrict__ dst,
                            int rows, int cols) {
    int idx = blockIdx.x * 256 + threadIdx.x;
    if (idx >= rows * cols) return;
    int n = idx / cols, k = idx - n * cols;
    dst[n * cols + kperm(k)] = __float2half(src[idx]);
}

__global__ void zero_pad_k(float* emb32, __half* emb16) {
    int i = blockIdx.x * 256 + threadIdx.x;
    if (i < (WCTX - 1) * E) {
        emb32[i] = 0.f;                 emb16[i] = __float2half(0.f);
        emb32[(size_t)PADS * E + i] = 0.f;
        emb16[(size_t)PADS * E + i] = __float2half(0.f);
    }
}

// ---------------- fp16 tensor-core GEMM --------------------------------------
// C[M,N] = act( A[M,K] @ W[N,K]^T + bias + residual )  (A,W fp16 k-permuted)
// BM=128, BN=128, BK=32, 256 threads (8 warps 2Mx4N, warp tile 64x32),
// 4-stage cp.async ring, one barrier/K-tile, 2 CTAs/SM. N%128==0, K%32==0.

#define SMLD_H 40
#define A_TSB (128*SMLD_H*2)                 /* 10240 B */
#define B_TSB (128*SMLD_H*2)                 /* 10240 B */
#define NSTG 4
#define GEMM_SMEM (NSTG*(A_TSB+B_TSB))       /* 81920 B -> 2 CTAs/SM */

#define MMA_F16(d, a0, a1, a2, a3, b0, b1) \
  asm volatile("mma.sync.aligned.m16n8k16.row.col.f32.f16.f16.f32 " \
    "{%0,%1,%2,%3}, {%4,%5,%6,%7}, {%8,%9}, {%0,%1,%2,%3};" \
    : "+f"(d[0]), "+f"(d[1]), "+f"(d[2]), "+f"(d[3]) \
    : "r"(a0), "r"(a1), "r"(a2), "r"(a3), "r"(b0), "r"(b1))

#define LOAD_TILE(KT_IDX, ST) do {                                            \
    if ((KT_IDX) < KT) {                                                      \
        const unsigned abase_ = smbase + (unsigned)(ST) * A_TSB;              \
        const unsigned bbase_ = smbase + (unsigned)NSTG * A_TSB + (unsigned)(ST) * B_TSB; \
        const __half* Ak_ = A + (size_t)(KT_IDX) * 32;                        \
        const __half* Bk_ = Wt + (size_t)(KT_IDX) * 32;                       \
        _Pragma("unroll")                                                     \
        for (int i_ = 0; i_ < 2; i_++) {                                      \
            const int c_   = tid + 256 * i_;                                  \
            const int row_ = c_ >> 2;                                         \
            const int ch_  = c_ & 3;                                          \
            const int am_  = bm0 + row_;                                      \
            const __half* sa_ = Ak_ + (size_t)(am_ < M ? am_ : 0) * lda + ch_ * 8; \
            const int sz_     = (am_ < M) ? 16 : 0;                           \
            asm volatile("cp.async.cg.shared.global [%0], [%1], 16, %2;" ::   \
                "r"(abase_ + (unsigned)(row_ * 80 + ch_ * 16)), "l"(sa_), "r"(sz_)); \
            const __half* sb_ = Bk_ + (size_t)(bn0 + row_) * K + ch_ * 8;     \
            asm volatile("cp.async.cg.shared.global [%0], [%1], 16;" ::       \
                "r"(bbase_ + (unsigned)(row_ * 80 + ch_ * 16)), "l"(sb_));    \
        }                                                                     \
    }                                                                         \
    asm volatile("cp.async.commit_group;");                                   \
} while (0)

#define COMPUTE_TILE(ST) do {                                                 \
    const __half* Asf_ = smh + (ST) * (A_TSB / 2);                            \
    const __half* Bsf_ = smh + NSTG * (A_TSB / 2) + (ST) * (B_TSB / 2);       \
    _Pragma("unroll")                                                         \
    for (int g_ = 0; g_ < 2; g_++) {                                          \
        const int kb_ = 16 * g_ + 4 * tig;                                    \
        unsigned Ar[4][4];                                                    \
        unsigned Br[4][2];                                                    \
        _Pragma("unroll")                                                     \
        for (int mt_ = 0; mt_ < 4; mt_++) {                                   \
            const __half* p_ = Asf_ + (wm + mt_ * 16 + gid) * SMLD_H + kb_;   \
            const uint2 lo_ = *(const uint2*)(p_);                            \
            const uint2 hi_ = *(const uint2*)(p_ + 8 * SMLD_H);               \
            Ar[mt_][0] = lo_.x;                                               \
            Ar[mt_][1] = hi_.x;                                               \
            Ar[mt_][2] = lo_.y;                                               \
            Ar[mt_][3] = hi_.y;                                               \
        }                                                                     \
        _Pragma("unroll")                                                     \
        for (int nt_ = 0; nt_ < 4; nt_++) {                                   \
            const uint2 bv_ = *(const uint2*)(Bsf_ + (wn + nt_ * 8 + gid) * SMLD_H + kb_); \
            Br[nt_][0] = bv_.x;                                               \
            Br[nt_][1] = bv_.y;                                               \
        }                                                                     \
        _Pragma("unroll")                                                     \
        for (int mt_ = 0; mt_ < 4; mt_++)                                     \
            _Pragma("unroll")                                                 \
            for (int nt_ = 0; nt_ < 4; nt_++)                                 \
                MMA_F16(acc[mt_][nt_], Ar[mt_][0], Ar[mt_][1],                \
                        Ar[mt_][2], Ar[mt_][3], Br[nt_][0], Br[nt_][1]);      \
    }                                                                         \
} while (0)

template<int ACT, int RES, int O32, int O16>
__global__ void __launch_bounds__(256, 2) gemm_h(
    const __half* __restrict__ A, int lda,
    const __half* __restrict__ Wt, int K,
    const float* __restrict__ bias,
    float* __restrict__ C32, __half* __restrict__ C16, int ldc,
    const float* __restrict__ res, int ldres,
    int M, int N)
{
    extern __shared__ __half smh[];
    const int tid  = threadIdx.x;
    const int bm0  = blockIdx.y * 128;
    const int bn0  = blockIdx.x * 128;
    const int lane = tid & 31, warp = tid >> 5;
    const int wm = (warp & 1) * 64;        // 2 warps along M
    const int wn = (warp >> 1) * 32;       // 4 warps along N
    const int gid = lane >> 2, tig = lane & 3;

    const unsigned smbase = (unsigned)__cvta_generic_to_shared(smh);

    float acc[4][4][4];
#pragma unroll
    for (int i = 0; i < 4; i++)
#pragma unroll
        for (int j = 0; j < 4; j++)
#pragma unroll
            for (int r = 0; r < 4; r++) acc[i][j][r] = 0.f;

    const int KT = K >> 5;

    LOAD_TILE(0, 0);
    LOAD_TILE(1, 1);
    LOAD_TILE(2, 2);

    for (int kt = 0; kt < KT; kt++) {
        asm volatile("cp.async.wait_group 2;");
        __syncthreads();
        LOAD_TILE(kt + 3, (kt + 3) & 3);
        COMPUTE_TILE(kt & 3);
    }

    // epilogue
#pragma unroll
    for (int mt = 0; mt < 4; mt++) {
        const int mbase = bm0 + wm + mt * 16 + gid;
#pragma unroll
        for (int half_ = 0; half_ < 2; half_++) {
            const int m = mbase + half_ * 8;
            if (m >= M) continue;
#pragma unroll
            for (int nt = 0; nt < 4; nt++) {
                const int n = bn0 + wn + nt * 8 + tig * 2;
                const float2 bv = *(const float2*)(bias + n);
                float v0 = acc[mt][nt][half_ * 2 + 0] + bv.x;
                float v1 = acc[mt][nt][half_ * 2 + 1] + bv.y;
                if (RES == 1) {
                    const float2 r = *(const float2*)(res + (size_t)m * ldres + n);
                    v0 += r.x; v1 += r.y;
                }
                if (RES == 2) {
                    const int nw = m >> 6, w = m & 63;
                    const int b = nw >> 10, s = nw & 1023;
                    const float* rp = res + ((size_t)(b * PADS + s + w)) * ldres + n;
                    v0 += rp[0]; v1 += rp[1];
                }
                if (ACT == 1) {
                    v0 = v0 / (1.f + __expf(-v0));
                    v1 = v1 / (1.f + __expf(-v1));
                }
                if (O32)
                    *(float2*)(C32 + (size_t)m * ldc + n) = make_float2(v0, v1);
                if (O16) {
                    const int p = (bn0 + wn + ((nt >> 1) << 4)) + 4 * tig + 2 * (nt & 1);
                    *(__half2*)(C16 + (size_t)m * ldc + p) =
                        __float22half2_rn(make_float2(v0, v1));
                }
            }
        }
    }
}

// ---------------- small fp32 GEMM (head only, N=10) --------------------------
__global__ void __launch_bounds__(256) gemm_head(
    const float* __restrict__ A, int lda,
    const float* __restrict__ Wt, int K,
    const float* __restrict__ bias,
    float* __restrict__ C, int ldc, int M, int N)
{
    __shared__ float As[16][68];
    __shared__ float Bs[16][68];
    const int tid = threadIdx.x;
    const int m0 = blockIdx.y * 64;
    const int lr = tid >> 2;
    const int lc = (tid & 3) << 2;
    const int ty = tid >> 4;
    const int tx = tid & 15;

    float acc[4][4];
#pragma unroll
    for (int i = 0; i < 4; i++)
#pragma unroll
        for (int j = 0; j < 4; j++) acc[i][j] = 0.f;

    const int am = m0 + lr;
    const float* Aptr = A + (size_t)am * lda + lc;
    const float* Wptr = Wt + (size_t)lr * K + lc;
    const bool avalid = (am < M);
    const bool bvalid = (lr < N);

    for (int k0 = 0; k0 < K; k0 += 16) {
        float4 av = make_float4(0.f, 0.f, 0.f, 0.f);
        float4 bv = make_float4(0.f, 0.f, 0.f, 0.f);
        if (avalid) av = *(const float4*)(Aptr + k0);
        if (bvalid) bv = *(const float4*)(Wptr + k0);
        As[lc+0][lr] = av.x; As[lc+1][lr] = av.y;
        As[lc+2][lr] = av.z; As[lc+3][lr] = av.w;
        Bs[lc+0][lr] = bv.x; Bs[lc+1][lr] = bv.y;
        Bs[lc+2][lr] = bv.z; Bs[lc+3][lr] = bv.w;
        __syncthreads();
#pragma unroll
        for (int kk = 0; kk < 16; kk++) {
            float4 a4 = *(const float4*)&As[kk][ty << 2];
            float4 b4 = *(const float4*)&Bs[kk][tx << 2];
            float ar[4] = {a4.x, a4.y, a4.z, a4.w};
            float br[4] = {b4.x, b4.y, b4.z, b4.w};
#pragma unroll
            for (int i = 0; i < 4; i++)
#pragma unroll
                for (int j = 0; j < 4; j++)
                    acc[i][j] = fmaf(ar[i], br[j], acc[i][j]);
        }
        __syncthreads();
    }

#pragma unroll
    for (int i = 0; i < 4; i++) {
        int m = m0 + (ty << 2) + i;
        if (m >= M) continue;
#pragma unroll
        for (int j = 0; j < 4; j++) {
            int n = (tx << 2) + j;
            if (n >= N) continue;
            C[(size_t)m * ldc + n] = acc[i][j] + bias[n];
        }
    }
}

// ---------------- layer-0 attention (fp16 source, fp32 math) -----------------
__global__ void __launch_bounds__(64) attn0_k(const __half* __restrict__ qkv16,
                                              __half* __restrict__ octx16) {
    const int h = blockIdx.x;
    const int n = blockIdx.y;
    const int b = n >> 10, s = n & 1023;
    const int t = threadIdx.x;
    __shared__ float Ks[64][36];
    __shared__ float Vs[64][36];

    const __half2* rw = (const __half2*)(qkv16 + (size_t)(b * PADS + s + t) * (3 * E) + h * 32);
    float4 q4[8];
#pragma unroll
    for (int i = 0; i < 8; i++) {
        float2 a = __half22float2(rw[2 * i]);
        float2 c = __half22float2(rw[2 * i + 1]);
        q4[i] = make_float4(a.x, a.y, c.x, c.y);
        float2 ka = __half22float2(rw[128 + 2 * i]);
        float2 kb = __half22float2(rw[128 + 2 * i + 1]);
        *(float4*)&Ks[t][i * 4] = make_float4(ka.x, ka.y, kb.x, kb.y);
        float2 va = __half22float2(rw[256 + 2 * i]);
        float2 vb = __half22float2(rw[256 + 2 * i + 1]);
        *(float4*)&Vs[t][i * 4] = make_float4(va.x, va.y, vb.x, vb.y);
    }
    __syncthreads();

    float sc[64];
    float mx = -1e30f;
#pragma unroll 4
    for (int k = 0; k < 64; k++) {
        const float4* k4 = (const float4*)Ks[k];
        float a = 0.f;
#pragma unroll
        for (int i = 0; i < 8; i++) {
            const float4 kv = k4[i];
            a = fmaf(q4[i].x, kv.x, a);
            a = fmaf(q4[i].y, kv.y, a);
            a = fmaf(q4[i].z, kv.z, a);
            a = fmaf(q4[i].w, kv.w, a);
        }
        a *= ATTN_SCALE;
        sc[k] = a;
        mx = fmaxf(mx, a);
    }
    float sum = 0.f;
#pragma unroll 4
    for (int k = 0; k < 64; k++) { sc[k] = __expf(sc[k] - mx); sum += sc[k]; }
    const float inv = 1.f / sum;

    float4 o4[8];
#pragma unroll
    for (int i = 0; i < 8; i++) o4[i] = make_float4(0.f, 0.f, 0.f, 0.f);
#pragma unroll 4
    for (int k = 0; k < 64; k++) {
        const float p = sc[k];
        const float4* v4 = (const float4*)Vs[k];
#pragma unroll
        for (int i = 0; i < 8; i++) {
            const float4 vv = v4[i];
            o4[i].x = fmaf(p, vv.x, o4[i].x);
            o4[i].y = fmaf(p, vv.y, o4[i].y);
            o4[i].z = fmaf(p, vv.z, o4[i].z);
            o4[i].w = fmaf(p, vv.w, o4[i].w);
        }
    }
    __half2* out = (__half2*)(octx16 + ((size_t)n * 64 + t) * E + h * 32);
#pragma unroll
    for (int i = 0; i < 8; i++) {
        out[2 * i]     = __float22half2_rn(make_float2(o4[i].x * inv, o4[i].y * inv));
        out[2 * i + 1] = __float22half2_rn(make_float2(o4[i].z * inv, o4[i].w * inv));
    }
}

// ---------------- layer-1 attention ------------------------------------------
__global__ void __launch_bounds__(256) attn1_k(const __half* __restrict__ q1,
                                               const __half* __restrict__ kv1,
                                               __half* __restrict__ o1) {
    const int n = blockIdx.x;
    const int h = threadIdx.x >> 5, l = threadIdx.x & 31;
    __shared__ float qs[256];
    __shared__ float ps[8][64];
    qs[threadIdx.x] = __half2float(q1[(size_t)n * E + threadIdx.x]);
    __syncthreads();

    const __half* kvb = kv1 + (size_t)n * 64 * (2 * E);
    const float* qh  = &qs[h * 32];
    const __half2* k0p = (const __half2*)(kvb + (size_t)l * (2 * E) + h * 32);
    const __half2* k1p = (const __half2*)(kvb + (size_t)(l + 32) * (2 * E) + h * 32);
    float s0 = 0.f, s1 = 0.f;
#pragma unroll
    for (int d = 0; d < 16; d++) {
        const float2 a = __half22float2(k0p[d]);
        const float2 b = __half22float2(k1p[d]);
        s0 = fmaf(qh[2*d], a.x, s0); s0 = fmaf(qh[2*d+1], a.y, s0);
        s1 = fmaf(qh[2*d], b.x, s1); s1 = fmaf(qh[2*d+1], b.y, s1);
    }
    s0 *= ATTN_SCALE; s1 *= ATTN_SCALE;
    float m = fmaxf(s0, s1);
#pragma unroll
    for (int o = 16; o; o >>= 1) m = fmaxf(m, __shfl_xor_sync(0xffffffffu, m, o));
    float e0 = __expf(s0 - m), e1 = __expf(s1 - m);
    float sum = e0 + e1;
#pragma unroll
    for (int o = 16; o; o >>= 1) sum += __shfl_xor_sync(0xffffffffu, sum, o);
    const float inv = 1.f / sum;
    ps[h][l] = e0 * inv;
    ps[h][l + 32] = e1 * inv;
    __syncwarp();

    float acc = 0.f;
#pragma unroll 4
    for (int k = 0; k < 64; k++)
        acc = fmaf(ps[h][k], __half2float(kvb[(size_t)k * (2 * E) + E + h * 32 + l]), acc);
    o1[(size_t)n * E + h * 32 + l] = __float2half(acc);
}

// ---------------- LayerNorm: fp32 in -> fp32 out + fp16 permuted out ---------
__global__ void __launch_bounds__(256) ln_k(const float* __restrict__ X,
                                            const float* __restrict__ g,
                                            const float* __restrict__ bb,
                                            float* __restrict__ Y32,
                                            __half* __restrict__ Y16, int M) {
    const int warp = threadIdx.x >> 5, lane = threadIdx.x & 31;
    const int row = blockIdx.x * 8 + warp;
    if (row >= M) return;
    const float* x = X + (size_t)row * E;
    float2 v[4];
    int cc[4];
    float s = 0.f;
#pragma unroll
    for (int i = 0; i < 4; i++) {
        const int u = lane + i * 32;
        const int q0 = 2 * u;
        const int q15 = q0 & 15;
        const int t = q15 >> 2;
        const int c0 = (q0 & ~15) | (2 * t + ((q15 & 2) ? 8 : 0));
        cc[i] = c0;
        v[i] = *(const float2*)(x + c0);
        s += v[i].x + v[i].y;
    }
#pragma unroll
    for (int o = 16; o; o >>= 1) s += __shfl_xor_sync(0xffffffffu, s, o);
    const float mean = s * (1.f / E);
    float var = 0.f;
#pragma unroll
    for (int i = 0; i < 4; i++) {
        float dx = v[i].x - mean, dy = v[i].y - mean;
        var = fmaf(dx, dx, var); var = fmaf(dy, dy, var);
    }
#pragma unroll
    for (int o = 16; o; o >>= 1) var += __shfl_xor_sync(0xffffffffu, var, o);
    const float inv = rsqrtf(var * (1.f / E) + 1e-5f);
#pragma unroll
    for (int i = 0; i < 4; i++) {
        const int c0 = cc[i];
        const float2 gg = *(const float2*)(g + c0);
        const float2 bv = *(const float2*)(bb + c0);
        float y0 = (v[i].x - mean) * inv * gg.x + bv.x;
        float y1 = (v[i].y - mean) * inv * gg.y + bv.y;
        *(float2*)(Y32 + (size_t)row * E + c0) = make_float2(y0, y1);
        *(__half2*)(Y16 + (size_t)row * E + 2 * (lane + i * 32)) =
            __float22half2_rn(make_float2(y0, y1));
    }
}

// ---------------------------------------------------------------------------
extern "C" void kernel_launch(void* const* d_in, const int* in_sizes, int n_in,
                              void* d_out, int out_size) {
    (void)in_sizes; (void)n_in; (void)out_size;
    const float* inputs     = (const float*)d_in[0];
    const float* embed_w    = (const float*)d_in[1];
    const float* embed_b    = (const float*)d_in[2];
    const float* qkv_w      = (const float*)d_in[3];
    const float* qkv_b      = (const float*)d_in[4];
    const float* attn_out_w = (const float*)d_in[5];
    const float* attn_out_b = (const float*)d_in[6];
    const float* ln1_g      = (const float*)d_in[7];
    const float* ln1_b      = (const float*)d_in[8];
    const float* ffn1_w     = (const float*)d_in[9];
    const float* ffn1_b     = (const float*)d_in[10];
    const float* ffn2_w     = (const float*)d_in[11];
    const float* ffn2_b     = (const float*)d_in[12];
    const float* ln2_g      = (const float*)d_in[13];
    const float* ln2_b      = (const float*)d_in[14];
    const float* head_w     = (const float*)d_in[15];
    const float* head_b     = (const float*)d_in[16];
    float* out = (float*)d_out;

    float *emb32, *x1a, *x1_32, *x2_32, *t1a, *t1_32, *t2;
    __half *in16, *embw16, *qkvw16, *aow16, *f1w16, *f2w16;
    __half *emb16, *qkv16, *octx16, *x1_16, *h16, *x2_16, *kv16;
    __half *q1_16, *o1_16, *t1_16, *th16;
    cudaGetSymbolAddress((void**)&emb32, g_emb32);
    cudaGetSymbolAddress((void**)&x1a,   g_x1a);
    cudaGetSymbolAddress((void**)&x1_32, g_x1_32);
    cudaGetSymbolAddress((void**)&x2_32, g_x2_32);
    cudaGetSymbolAddress((void**)&t1a,   g_t1a);
    cudaGetSymbolAddress((void**)&t1_32, g_t1_32);
    cudaGetSymbolAddress((void**)&t2,    g_t2);
    cudaGetSymbolAddress((void**)&in16,  g_in16);
    cudaGetSymbolAddress((void**)&embw16,g_embw16);
    cudaGetSymbolAddress((void**)&qkvw16,g_qkvw16);
    cudaGetSymbolAddress((void**)&aow16, g_aow16);
    cudaGetSymbolAddress((void**)&f1w16, g_f1w16);
    cudaGetSymbolAddress((void**)&f2w16, g_f2w16);
    cudaGetSymbolAddress((void**)&emb16, g_emb16);
    cudaGetSymbolAddress((void**)&qkv16, g_qkv16);
    cudaGetSymbolAddress((void**)&octx16,g_octx16);
    cudaGetSymbolAddress((void**)&x1_16, g_x1_16);
    cudaGetSymbolAddress((void**)&h16,   g_h16);
    cudaGetSymbolAddress((void**)&x2_16, g_x2_16);
    cudaGetSymbolAddress((void**)&kv16,  g_kv16);
    cudaGetSymbolAddress((void**)&q1_16, g_q1_16);
    cudaGetSymbolAddress((void**)&o1_16, g_o1_16);
    cudaGetSymbolAddress((void**)&t1_16, g_t1_16);
    cudaGetSymbolAddress((void**)&th16,  g_th16);

    cudaFuncSetAttribute(gemm_h<0,0,1,1>, cudaFuncAttributeMaxDynamicSharedMemorySize, GEMM_SMEM);
    cudaFuncSetAttribute(gemm_h<0,0,0,1>, cudaFuncAttributeMaxDynamicSharedMemorySize, GEMM_SMEM);
    cudaFuncSetAttribute(gemm_h<0,2,1,0>, cudaFuncAttributeMaxDynamicSharedMemorySize, GEMM_SMEM);
    cudaFuncSetAttribute(gemm_h<1,0,0,1>, cudaFuncAttributeMaxDynamicSharedMemorySize, GEMM_SMEM);
    cudaFuncSetAttribute(gemm_h<0,1,1,0>, cudaFuncAttributeMaxDynamicSharedMemorySize, GEMM_SMEM);

    // --- weight / input conversion (fp32 -> fp16, k-permuted) ---
    conv_perm_k<<<(BATCH*SEQ*FIN + 255)/256, 256>>>(inputs, in16, BATCH*SEQ, FIN);
    conv_perm_k<<<(E*FIN + 255)/256, 256>>>(embed_w, embw16, E, FIN);
    conv_perm_k<<<(2*3*E*E + 255)/256, 256>>>(qkv_w, qkvw16, 2*3*E, E);
    conv_perm_k<<<(2*E*E + 255)/256, 256>>>(attn_out_w, aow16, 2*E, E);
    conv_perm_k<<<(2*FF*E + 255)/256, 256>>>(ffn1_w, f1w16, 2*FF, E);
    conv_perm_k<<<(2*E*FF + 255)/256, 256>>>(ffn2_w, f2w16, 2*E, FF);

    // --- embeddings (zero-padded left by W-1) ---
    zero_pad_k<<<63, 256>>>(emb32, emb16);
    for (int b = 0; b < BATCH; b++) {
        gemm_h<0,0,1,1><<<dim3(E/128, SEQ/128), 256, GEMM_SMEM>>>(
            in16 + (size_t)b * SEQ * FIN, FIN, embw16, FIN, embed_b,
            emb32 + ((size_t)b * PADS + (WCTX - 1)) * E,
            emb16 + ((size_t)b * PADS + (WCTX - 1)) * E, E,
            nullptr, 0, SEQ, E);
    }

    // --- layer-0 QKV per global token ---
    gemm_h<0,0,0,1><<<dim3(3*E/128, (BATCH*PADS + 127)/128), 256, GEMM_SMEM>>>(
        emb16, E, qkvw16, E, qkv_b, nullptr, qkv16, 3*E, nullptr, 0,
        BATCH*PADS, 3*E);

    // --- layer-0 attention ---
    attn0_k<<<dim3(8, NW), 64>>>(qkv16, octx16);

    // --- layer-0 attn-out + residual gather -> LN1 ---
    gemm_h<0,2,1,0><<<dim3(E/128, NT/128), 256, GEMM_SMEM>>>(
        octx16, E, aow16, E, attn_out_b, x1a, nullptr, E, emb32, E, NT, E);
    ln_k<<<NT / 8, 256>>>(x1a, ln1_g, ln1_b, x1_32, x1_16, NT);

    // --- layer-0 FFN ---
    gemm_h<1,0,0,1><<<dim3(FF/128, NT/128), 256, GEMM_SMEM>>>(
        x1_16, E, f1w16, E, ffn1_b, nullptr, h16, FF, nullptr, 0, NT, FF);
    gemm_h<0,1,1,0><<<dim3(E/128, NT/128), 256, GEMM_SMEM>>>(
        h16, FF, f2w16, FF, ffn2_b, x1a, nullptr, E, x1_32, E, NT, E);
    ln_k<<<NT / 8, 256>>>(x1a, ln2_g, ln2_b, x2_32, x2_16, NT);

    // --- layer-1: K,V all tokens; Q last tokens only ---
    gemm_h<0,0,0,1><<<dim3(2*E/128, NT/128), 256, GEMM_SMEM>>>(
        x2_16, E, qkvw16 + (size_t)3*E*E + (size_t)E*E, E,
        qkv_b + 3*E + E, nullptr, kv16, 2*E, nullptr, 0, NT, 2*E);
    gemm_h<0,0,0,1><<<dim3(E/128, NW/128), 256, GEMM_SMEM>>>(
        x2_16 + (size_t)(WCTX-1)*E, WCTX*E,
        qkvw16 + (size_t)3*E*E, E, qkv_b + 3*E,
        nullptr, q1_16, E, nullptr, 0, NW, E);

    attn1_k<<<NW, 256>>>(q1_16, kv16, o1_16);

    // --- layer-1 tail ---
    gemm_h<0,1,1,0><<<dim3(E/128, NW/128), 256, GEMM_SMEM>>>(
        o1_16, E, aow16 + (size_t)E*E, E, attn_out_b + E,
        t1a, nullptr, E, x2_32 + (size_t)(WCTX-1)*E, WCTX*E, NW, E);
    ln_k<<<NW / 8, 256>>>(t1a, ln1_g + E, ln1_b + E, t1_32, t1_16, NW);
    gemm_h<1,0,0,1><<<dim3(FF/128, NW/128), 256, GEMM_SMEM>>>(
        t1_16, E, f1w16 + (size_t)FF*E, E, ffn1_b + FF,
        nullptr, th16, FF, nullptr, 0, NW, FF);
    gemm_h<0,1,1,0><<<dim3(E/128, NW/128), 256, GEMM_SMEM>>>(
        th16, FF, f2w16 + (size_t)E*FF, FF, ffn2_b + E,
        t1a, nullptr, E, t1_32, E, NW, E);
    ln_k<<<NW / 8, 256>>>(t1a, ln2_g + E, ln2_b + E, t2, th16 /*scratch*/, NW);

    // --- head (N=10, fp32, unpermuted t2) ---
    gemm_head<<<dim3(1, NW/64), 256>>>(
        t2, E, head_w, E, head_b, out, 10, NW, 10);
}

// round 11
// speedup vs baseline: 4.2409x; 1.1859x over previous
#include <cuda_runtime.h>
#include <cuda_fp16.h>
#include <math.h>
#include <stdint.h>

// ---------------------------------------------------------------------------
// Round 11: fp16 GEMM with ldmatrix fragment loads (4x payload per smem op),
// BK=64 (half the barriers), SW128 XOR swizzle (no padding), natural layout
// everywhere (k-permutation removed). 2 CTAs/SM retained from R10.
// ---------------------------------------------------------------------------

#define BATCH 2
#define SEQ   1024
#define E     256
#define FIN   64
#define FF    1024
#define WCTX  64
#define NW    (BATCH*SEQ)
#define PADS  (SEQ + WCTX - 1)
#define NT    (NW*WCTX)

#define ATTN_SCALE 0.17677669529663687f

// ---------------- scratch ----------------------------------------------------
__device__ __align__(128) float g_emb32[BATCH*PADS*E];
__device__ __align__(128) float g_x1a  [NT*E];
__device__ __align__(128) float g_x1_32[NT*E];
__device__ __align__(128) float g_x2_32[NT*E];
__device__ __align__(128) float g_t1a  [NW*E];
__device__ __align__(128) float g_t1_32[NW*E];
__device__ __align__(128) float g_t2   [NW*E];
__device__ __align__(128) __half g_in16  [BATCH*SEQ*FIN];
__device__ __align__(128) __half g_embw16[E*FIN];
__device__ __align__(128) __half g_qkvw16[2*3*E*E];
__device__ __align__(128) __half g_aow16 [2*E*E];
__device__ __align__(128) __half g_f1w16 [2*FF*E];
__device__ __align__(128) __half g_f2w16 [2*E*FF];
__device__ __align__(128) __half g_emb16 [BATCH*PADS*E];
__device__ __align__(128) __half g_qkv16 [BATCH*PADS*3*E];
__device__ __align__(128) __half g_octx16[NT*E];
__device__ __align__(128) __half g_x1_16 [NT*E];
__device__ __align__(128) __half g_h16   [NT*FF];
__device__ __align__(128) __half g_x2_16 [NT*E];
__device__ __align__(128) __half g_kv16  [NT*2*E];
__device__ __align__(128) __half g_q1_16 [NW*E];
__device__ __align__(128) __half g_o1_16 [NW*E];
__device__ __align__(128) __half g_t1_16 [NW*E];
__device__ __align__(128) __half g_th16  [NW*FF];

// plain fp32 -> fp16 convert (natural layout)
__global__ void conv_k(const float* __restrict__ src, __half* __restrict__ dst,
                       int total) {
    int idx = blockIdx.x * 256 + threadIdx.x;
    if (idx < total) dst[idx] = __float2half(src[idx]);
}

__global__ void zero_pad_k(float* emb32, __half* emb16) {
    int i = blockIdx.x * 256 + threadIdx.x;
    if (i < (WCTX - 1) * E) {
        emb32[i] = 0.f;                 emb16[i] = __float2half(0.f);
        emb32[(size_t)PADS * E + i] = 0.f;
        emb16[(size_t)PADS * E + i] = __float2half(0.f);
    }
}

// ---------------- fp16 tensor-core GEMM --------------------------------------
// C[M,N] = act( A[M,K] @ W[N,K]^T + bias + residual )  (A,W fp16 natural)
// BM=128, BN=128, BK=64, 256 threads (8 warps 2Mx4N, warp tile 64x32),
// 3-stage cp.async ring, SW128 swizzle, ldmatrix fragments. N%128, K%64.

#define T_TSB 16384                 /* 128 rows x 128 B per tile */
#define NSTG 3
#define GEMM_SMEM (2*NSTG*T_TSB)    /* 98304 B -> 2 CTAs/SM */

#define MMA_F16(d, a0, a1, a2, a3, b0, b1) \
  asm volatile("mma.sync.aligned.m16n8k16.row.col.f32.f16.f16.f32 " \
    "{%0,%1,%2,%3}, {%4,%5,%6,%7}, {%8,%9}, {%0,%1,%2,%3};" \
    : "+f"(d[0]), "+f"(d[1]), "+f"(d[2]), "+f"(d[3]) \
    : "r"(a0), "r"(a1), "r"(a2), "r"(a3), "r"(b0), "r"(b1))

#define LDSM_X4(r0, r1, r2, r3, ad) \
  asm volatile("ldmatrix.sync.aligned.m8n8.x4.shared.b16 {%0,%1,%2,%3}, [%4];" \
    : "=r"(r0), "=r"(r1), "=r"(r2), "=r"(r3) : "r"(ad))

// Load K-tile KT_IDX (64 wide) into ring stage ST. Swizzle: ch ^= row&7.
#define LOAD_TILE(KT_IDX, ST) do {                                            \
    if ((KT_IDX) < KT) {                                                      \
        const unsigned abase_ = smbase + (unsigned)(ST) * T_TSB;              \
        const unsigned bbase_ = smbase + (unsigned)NSTG * T_TSB + (unsigned)(ST) * T_TSB; \
        const __half* Ak_ = A + (size_t)(KT_IDX) * 64;                        \
        const __half* Bk_ = Wt + (size_t)(KT_IDX) * 64;                       \
        _Pragma("unroll")                                                     \
        for (int i_ = 0; i_ < 4; i_++) {                                      \
            const int c_   = tid + 256 * i_;                                  \
            const int row_ = c_ >> 3;                                         \
            const int ch_  = c_ & 7;                                          \
            const unsigned soff_ = (unsigned)(row_ * 128 + ((ch_ ^ (row_ & 7)) * 16)); \
            const int am_  = bm0 + row_;                                      \
            const __half* sa_ = Ak_ + (size_t)(am_ < M ? am_ : 0) * lda + ch_ * 8; \
            const int sz_     = (am_ < M) ? 16 : 0;                           \
            asm volatile("cp.async.cg.shared.global [%0], [%1], 16, %2;" ::   \
                "r"(abase_ + soff_), "l"(sa_), "r"(sz_));                     \
            const __half* sb_ = Bk_ + (size_t)(bn0 + row_) * K + ch_ * 8;     \
            asm volatile("cp.async.cg.shared.global [%0], [%1], 16;" ::       \
                "r"(bbase_ + soff_), "l"(sb_));                               \
        }                                                                     \
    }                                                                         \
    asm volatile("cp.async.commit_group;");                                   \
} while (0)

#define COMPUTE_TILE(ST) do {                                                 \
    const unsigned abase_ = smbase + (unsigned)(ST) * T_TSB;                  \
    const unsigned bbase_ = smbase + (unsigned)NSTG * T_TSB + (unsigned)(ST) * T_TSB; \
    _Pragma("unroll")                                                         \
    for (int kk_ = 0; kk_ < 4; kk_++) {                                       \
        const int chl_ = 2 * kk_ + (lane >> 4);                               \
        unsigned Ar[4][4];                                                    \
        unsigned Br[2][4];                                                    \
        _Pragma("unroll")                                                     \
        for (int mt_ = 0; mt_ < 4; mt_++) {                                   \
            const int r_ = wm + mt_ * 16 + (lane & 15);                       \
            LDSM_X4(Ar[mt_][0], Ar[mt_][1], Ar[mt_][2], Ar[mt_][3],           \
                    abase_ + (unsigned)(r_ * 128 + ((chl_ ^ (r_ & 7)) * 16)));\
        }                                                                     \
        _Pragma("unroll")                                                     \
        for (int np_ = 0; np_ < 2; np_++) {                                   \
            const int r_ = wn + np_ * 16 + (lane & 15);                       \
            LDSM_X4(Br[np_][0], Br[np_][1], Br[np_][2], Br[np_][3],           \
                    bbase_ + (unsigned)(r_ * 128 + ((chl_ ^ (r_ & 7)) * 16)));\
        }                                                                     \
        _Pragma("unroll")                                                     \
        for (int mt_ = 0; mt_ < 4; mt_++)                                     \
            _Pragma("unroll")                                                 \
            for (int np_ = 0; np_ < 2; np_++) {                               \
                MMA_F16(acc[mt_][np_ * 2 + 0], Ar[mt_][0], Ar[mt_][1],        \
                        Ar[mt_][2], Ar[mt_][3], Br[np_][0], Br[np_][2]);      \
                MMA_F16(acc[mt_][np_ * 2 + 1], Ar[mt_][0], Ar[mt_][1],        \
                        Ar[mt_][2], Ar[mt_][3], Br[np_][1], Br[np_][3]);      \
            }                                                                 \
    }                                                                         \
} while (0)

template<int ACT, int RES, int O32, int O16>
__global__ void __launch_bounds__(256, 2) gemm_h(
    const __half* __restrict__ A, int lda,
    const __half* __restrict__ Wt, int K,
    const float* __restrict__ bias,
    float* __restrict__ C32, __half* __restrict__ C16, int ldc,
    const float* __restrict__ res, int ldres,
    int M, int N)
{
    extern __shared__ __half smh[];
    const int tid  = threadIdx.x;
    const int bm0  = blockIdx.y * 128;
    const int bn0  = blockIdx.x * 128;
    const int lane = tid & 31, warp = tid >> 5;
    const int wm = (warp & 1) * 64;        // 2 warps along M
    const int wn = (warp >> 1) * 32;       // 4 warps along N
    const int gid = lane >> 2, tig = lane & 3;

    const unsigned smbase = (unsigned)__cvta_generic_to_shared(smh);

    float acc[4][4][4];
#pragma unroll
    for (int i = 0; i < 4; i++)
#pragma unroll
        for (int j = 0; j < 4; j++)
#pragma unroll
            for (int r = 0; r < 4; r++) acc[i][j][r] = 0.f;

    const int KT = K >> 6;

    LOAD_TILE(0, 0);
    LOAD_TILE(1, 1);

    for (int kt = 0; kt < KT; kt++) {
        asm volatile("cp.async.wait_group 1;");
        __syncthreads();
        LOAD_TILE(kt + 2, (kt + 2) % 3);
        COMPUTE_TILE(kt % 3);
    }

    // epilogue
#pragma unroll
    for (int mt = 0; mt < 4; mt++) {
        const int mbase = bm0 + wm + mt * 16 + gid;
#pragma unroll
        for (int half_ = 0; half_ < 2; half_++) {
            const int m = mbase + half_ * 8;
            if (m >= M) continue;
#pragma unroll
            for (int nt = 0; nt < 4; nt++) {
                const int n = bn0 + wn + nt * 8 + tig * 2;
                const float2 bv = *(const float2*)(bias + n);
                float v0 = acc[mt][nt][half_ * 2 + 0] + bv.x;
                float v1 = acc[mt][nt][half_ * 2 + 1] + bv.y;
                if (RES == 1) {
                    const float2 r = *(const float2*)(res + (size_t)m * ldres + n);
                    v0 += r.x; v1 += r.y;
                }
                if (RES == 2) {
                    const int nw = m >> 6, w = m & 63;
                    const int b = nw >> 10, s = nw & 1023;
                    const float* rp = res + ((size_t)(b * PADS + s + w)) * ldres + n;
                    v0 += rp[0]; v1 += rp[1];
                }
                if (ACT == 1) {
                    v0 = v0 / (1.f + __expf(-v0));
                    v1 = v1 / (1.f + __expf(-v1));
                }
                if (O32)
                    *(float2*)(C32 + (size_t)m * ldc + n) = make_float2(v0, v1);
                if (O16)
                    *(__half2*)(C16 + (size_t)m * ldc + n) =
                        __float22half2_rn(make_float2(v0, v1));
            }
        }
    }
}

// ---------------- small fp32 GEMM (head only, N=10) --------------------------
__global__ void __launch_bounds__(256) gemm_head(
    const float* __restrict__ A, int lda,
    const float* __restrict__ Wt, int K,
    const float* __restrict__ bias,
    float* __restrict__ C, int ldc, int M, int N)
{
    __shared__ float As[16][68];
    __shared__ float Bs[16][68];
    const int tid = threadIdx.x;
    const int m0 = blockIdx.y * 64;
    const int lr = tid >> 2;
    const int lc = (tid & 3) << 2;
    const int ty = tid >> 4;
    const int tx = tid & 15;

    float acc[4][4];
#pragma unroll
    for (int i = 0; i < 4; i++)
#pragma unroll
        for (int j = 0; j < 4; j++) acc[i][j] = 0.f;

    const int am = m0 + lr;
    const float* Aptr = A + (size_t)am * lda + lc;
    const float* Wptr = Wt + (size_t)lr * K + lc;
    const bool avalid = (am < M);
    const bool bvalid = (lr < N);

    for (int k0 = 0; k0 < K; k0 += 16) {
        float4 av = make_float4(0.f, 0.f, 0.f, 0.f);
        float4 bv = make_float4(0.f, 0.f, 0.f, 0.f);
        if (avalid) av = *(const float4*)(Aptr + k0);
        if (bvalid) bv = *(const float4*)(Wptr + k0);
        As[lc+0][lr] = av.x; As[lc+1][lr] = av.y;
        As[lc+2][lr] = av.z; As[lc+3][lr] = av.w;
        Bs[lc+0][lr] = bv.x; Bs[lc+1][lr] = bv.y;
        Bs[lc+2][lr] = bv.z; Bs[lc+3][lr] = bv.w;
        __syncthreads();
#pragma unroll
        for (int kk = 0; kk < 16; kk++) {
            float4 a4 = *(const float4*)&As[kk][ty << 2];
            float4 b4 = *(const float4*)&Bs[kk][tx << 2];
            float ar[4] = {a4.x, a4.y, a4.z, a4.w};
            float br[4] = {b4.x, b4.y, b4.z, b4.w};
#pragma unroll
            for (int i = 0; i < 4; i++)
#pragma unroll
                for (int j = 0; j < 4; j++)
                    acc[i][j] = fmaf(ar[i], br[j], acc[i][j]);
        }
        __syncthreads();
    }

#pragma unroll
    for (int i = 0; i < 4; i++) {
        int m = m0 + (ty << 2) + i;
        if (m >= M) continue;
#pragma unroll
        for (int j = 0; j < 4; j++) {
            int n = (tx << 2) + j;
            if (n >= N) continue;
            C[(size_t)m * ldc + n] = acc[i][j] + bias[n];
        }
    }
}

// ---------------- layer-0 attention (fp16 source, fp32 math) -----------------
__global__ void __launch_bounds__(64) attn0_k(const __half* __restrict__ qkv16,
                                              __half* __restrict__ octx16) {
    const int h = blockIdx.x;
    const int n = blockIdx.y;
    const int b = n >> 10, s = n & 1023;
    const int t = threadIdx.x;
    __shared__ float Ks[64][36];
    __shared__ float Vs[64][36];

    const __half2* rw = (const __half2*)(qkv16 + (size_t)(b * PADS + s + t) * (3 * E) + h * 32);
    float4 q4[8];
#pragma unroll
    for (int i = 0; i < 8; i++) {
        float2 a = __half22float2(rw[2 * i]);
        float2 c = __half22float2(rw[2 * i + 1]);
        q4[i] = make_float4(a.x, a.y, c.x, c.y);
        float2 ka = __half22float2(rw[128 + 2 * i]);
        float2 kb = __half22float2(rw[128 + 2 * i + 1]);
        *(float4*)&Ks[t][i * 4] = make_float4(ka.x, ka.y, kb.x, kb.y);
        float2 va = __half22float2(rw[256 + 2 * i]);
        float2 vb = __half22float2(rw[256 + 2 * i + 1]);
        *(float4*)&Vs[t][i * 4] = make_float4(va.x, va.y, vb.x, vb.y);
    }
    __syncthreads();

    float sc[64];
    float mx = -1e30f;
#pragma unroll 4
    for (int k = 0; k < 64; k++) {
        const float4* k4 = (const float4*)Ks[k];
        float a = 0.f;
#pragma unroll
        for (int i = 0; i < 8; i++) {
            const float4 kv = k4[i];
            a = fmaf(q4[i].x, kv.x, a);
            a = fmaf(q4[i].y, kv.y, a);
            a = fmaf(q4[i].z, kv.z, a);
            a = fmaf(q4[i].w, kv.w, a);
        }
        a *= ATTN_SCALE;
        sc[k] = a;
        mx = fmaxf(mx, a);
    }
    float sum = 0.f;
#pragma unroll 4
    for (int k = 0; k < 64; k++) { sc[k] = __expf(sc[k] - mx); sum += sc[k]; }
    const float inv = 1.f / sum;

    float4 o4[8];
#pragma unroll
    for (int i = 0; i < 8; i++) o4[i] = make_float4(0.f, 0.f, 0.f, 0.f);
#pragma unroll 4
    for (int k = 0; k < 64; k++) {
        const float p = sc[k];
        const float4* v4 = (const float4*)Vs[k];
#pragma unroll
        for (int i = 0; i < 8; i++) {
            const float4 vv = v4[i];
            o4[i].x = fmaf(p, vv.x, o4[i].x);
            o4[i].y = fmaf(p, vv.y, o4[i].y);
            o4[i].z = fmaf(p, vv.z, o4[i].z);
            o4[i].w = fmaf(p, vv.w, o4[i].w);
        }
    }
    __half2* out = (__half2*)(octx16 + ((size_t)n * 64 + t) * E + h * 32);
#pragma unroll
    for (int i = 0; i < 8; i++) {
        out[2 * i]     = __float22half2_rn(make_float2(o4[i].x * inv, o4[i].y * inv));
        out[2 * i + 1] = __float22half2_rn(make_float2(o4[i].z * inv, o4[i].w * inv));
    }
}

// ---------------- layer-1 attention ------------------------------------------
__global__ void __launch_bounds__(256) attn1_k(const __half* __restrict__ q1,
                                               const __half* __restrict__ kv1,
                                               __half* __restrict__ o1) {
    const int n = blockIdx.x;
    const int h = threadIdx.x >> 5, l = threadIdx.x & 31;
    __shared__ float qs[256];
    __shared__ float ps[8][64];
    qs[threadIdx.x] = __half2float(q1[(size_t)n * E + threadIdx.x]);
    __syncthreads();

    const __half* kvb = kv1 + (size_t)n * 64 * (2 * E);
    const float* qh  = &qs[h * 32];
    const __half2* k0p = (const __half2*)(kvb + (size_t)l * (2 * E) + h * 32);
    const __half2* k1p = (const __half2*)(kvb + (size_t)(l + 32) * (2 * E) + h * 32);
    float s0 = 0.f, s1 = 0.f;
#pragma unroll
    for (int d = 0; d < 16; d++) {
        const float2 a = __half22float2(k0p[d]);
        const float2 b = __half22float2(k1p[d]);
        s0 = fmaf(qh[2*d], a.x, s0); s0 = fmaf(qh[2*d+1], a.y, s0);
        s1 = fmaf(qh[2*d], b.x, s1); s1 = fmaf(qh[2*d+1], b.y, s1);
    }
    s0 *= ATTN_SCALE; s1 *= ATTN_SCALE;
    float m = fmaxf(s0, s1);
#pragma unroll
    for (int o = 16; o; o >>= 1) m = fmaxf(m, __shfl_xor_sync(0xffffffffu, m, o));
    float e0 = __expf(s0 - m), e1 = __expf(s1 - m);
    float sum = e0 + e1;
#pragma unroll
    for (int o = 16; o; o >>= 1) sum += __shfl_xor_sync(0xffffffffu, sum, o);
    const float inv = 1.f / sum;
    ps[h][l] = e0 * inv;
    ps[h][l + 32] = e1 * inv;
    __syncwarp();

    float acc = 0.f;
#pragma unroll 4
    for (int k = 0; k < 64; k++)
        acc = fmaf(ps[h][k], __half2float(kvb[(size_t)k * (2 * E) + E + h * 32 + l]), acc);
    o1[(size_t)n * E + h * 32 + l] = __float2half(acc);
}

// ---------------- LayerNorm: fp32 in -> fp32 + fp16 out ----------------------
__global__ void __launch_bounds__(256) ln_k(const float* __restrict__ X,
                                            const float* __restrict__ g,
                                            const float* __restrict__ bb,
                                            float* __restrict__ Y32,
                                            __half* __restrict__ Y16, int M) {
    const int warp = threadIdx.x >> 5, lane = threadIdx.x & 31;
    const int row = blockIdx.x * 8 + warp;
    if (row >= M) return;
    const float* x = X + (size_t)row * E;
    float2 v[4];
    float s = 0.f;
#pragma unroll
    for (int i = 0; i < 4; i++) {
        v[i] = *(const float2*)(x + 2 * (lane + i * 32));
        s += v[i].x + v[i].y;
    }
#pragma unroll
    for (int o = 16; o; o >>= 1) s += __shfl_xor_sync(0xffffffffu, s, o);
    const float mean = s * (1.f / E);
    float var = 0.f;
#pragma unroll
    for (int i = 0; i < 4; i++) {
        float dx = v[i].x - mean, dy = v[i].y - mean;
        var = fmaf(dx, dx, var); var = fmaf(dy, dy, var);
    }
#pragma unroll
    for (int o = 16; o; o >>= 1) var += __shfl_xor_sync(0xffffffffu, var, o);
    const float inv = rsqrtf(var * (1.f / E) + 1e-5f);
#pragma unroll
    for (int i = 0; i < 4; i++) {
        const int c0 = 2 * (lane + i * 32);
        const float2 gg = *(const float2*)(g + c0);
        const float2 bv = *(const float2*)(bb + c0);
        float y0 = (v[i].x - mean) * inv * gg.x + bv.x;
        float y1 = (v[i].y - mean) * inv * gg.y + bv.y;
        *(float2*)(Y32 + (size_t)row * E + c0) = make_float2(y0, y1);
        *(__half2*)(Y16 + (size_t)row * E + c0) =
            __float22half2_rn(make_float2(y0, y1));
    }
}

// ---------------------------------------------------------------------------
extern "C" void kernel_launch(void* const* d_in, const int* in_sizes, int n_in,
                              void* d_out, int out_size) {
    (void)in_sizes; (void)n_in; (void)out_size;
    const float* inputs     = (const float*)d_in[0];
    const float* embed_w    = (const float*)d_in[1];
    const float* embed_b    = (const float*)d_in[2];
    const float* qkv_w      = (const float*)d_in[3];
    const float* qkv_b      = (const float*)d_in[4];
    const float* attn_out_w = (const float*)d_in[5];
    const float* attn_out_b = (const float*)d_in[6];
    const float* ln1_g      = (const float*)d_in[7];
    const float* ln1_b      = (const float*)d_in[8];
    const float* ffn1_w     = (const float*)d_in[9];
    const float* ffn1_b     = (const float*)d_in[10];
    const float* ffn2_w     = (const float*)d_in[11];
    const float* ffn2_b     = (const float*)d_in[12];
    const float* ln2_g      = (const float*)d_in[13];
    const float* ln2_b      = (const float*)d_in[14];
    const float* head_w     = (const float*)d_in[15];
    const float* head_b     = (const float*)d_in[16];
    float* out = (float*)d_out;

    float *emb32, *x1a, *x1_32, *x2_32, *t1a, *t1_32, *t2;
    __half *in16, *embw16, *qkvw16, *aow16, *f1w16, *f2w16;
    __half *emb16, *qkv16, *octx16, *x1_16, *h16, *x2_16, *kv16;
    __half *q1_16, *o1_16, *t1_16, *th16;
    cudaGetSymbolAddress((void**)&emb32, g_emb32);
    cudaGetSymbolAddress((void**)&x1a,   g_x1a);
    cudaGetSymbolAddress((void**)&x1_32, g_x1_32);
    cudaGetSymbolAddress((void**)&x2_32, g_x2_32);
    cudaGetSymbolAddress((void**)&t1a,   g_t1a);
    cudaGetSymbolAddress((void**)&t1_32, g_t1_32);
    cudaGetSymbolAddress((void**)&t2,    g_t2);
    cudaGetSymbolAddress((void**)&in16,  g_in16);
    cudaGetSymbolAddress((void**)&embw16,g_embw16);
    cudaGetSymbolAddress((void**)&qkvw16,g_qkvw16);
    cudaGetSymbolAddress((void**)&aow16, g_aow16);
    cudaGetSymbolAddress((void**)&f1w16, g_f1w16);
    cudaGetSymbolAddress((void**)&f2w16, g_f2w16);
    cudaGetSymbolAddress((void**)&emb16, g_emb16);
    cudaGetSymbolAddress((void**)&qkv16, g_qkv16);
    cudaGetSymbolAddress((void**)&octx16,g_octx16);
    cudaGetSymbolAddress((void**)&x1_16, g_x1_16);
    cudaGetSymbolAddress((void**)&h16,   g_h16);
    cudaGetSymbolAddress((void**)&x2_16, g_x2_16);
    cudaGetSymbolAddress((void**)&kv16,  g_kv16);
    cudaGetSymbolAddress((void**)&q1_16, g_q1_16);
    cudaGetSymbolAddress((void**)&o1_16, g_o1_16);
    cudaGetSymbolAddress((void**)&t1_16, g_t1_16);
    cudaGetSymbolAddress((void**)&th16,  g_th16);

    cudaFuncSetAttribute(gemm_h<0,0,1,1>, cudaFuncAttributeMaxDynamicSharedMemorySize, GEMM_SMEM);
    cudaFuncSetAttribute(gemm_h<0,0,0,1>, cudaFuncAttributeMaxDynamicSharedMemorySize, GEMM_SMEM);
    cudaFuncSetAttribute(gemm_h<0,2,1,0>, cudaFuncAttributeMaxDynamicSharedMemorySize, GEMM_SMEM);
    cudaFuncSetAttribute(gemm_h<1,0,0,1>, cudaFuncAttributeMaxDynamicSharedMemorySize, GEMM_SMEM);
    cudaFuncSetAttribute(gemm_h<0,1,1,0>, cudaFuncAttributeMaxDynamicSharedMemorySize, GEMM_SMEM);

    // --- weight / input conversion ---
    conv_k<<<(BATCH*SEQ*FIN + 255)/256, 256>>>(inputs, in16, BATCH*SEQ*FIN);
    conv_k<<<(E*FIN + 255)/256, 256>>>(embed_w, embw16, E*FIN);
    conv_k<<<(2*3*E*E + 255)/256, 256>>>(qkv_w, qkvw16, 2*3*E*E);
    conv_k<<<(2*E*E + 255)/256, 256>>>(attn_out_w, aow16, 2*E*E);
    conv_k<<<(2*FF*E + 255)/256, 256>>>(ffn1_w, f1w16, 2*FF*E);
    conv_k<<<(2*E*FF + 255)/256, 256>>>(ffn2_w, f2w16, 2*E*FF);

    // --- embeddings (zero-padded left by W-1) ---
    zero_pad_k<<<63, 256>>>(emb32, emb16);
    for (int b = 0; b < BATCH; b++) {
        gemm_h<0,0,1,1><<<dim3(E/128, SEQ/128), 256, GEMM_SMEM>>>(
            in16 + (size_t)b * SEQ * FIN, FIN, embw16, FIN, embed_b,
            emb32 + ((size_t)b * PADS + (WCTX - 1)) * E,
            emb16 + ((size_t)b * PADS + (WCTX - 1)) * E, E,
            nullptr, 0, SEQ, E);
    }

    // --- layer-0 QKV per global token ---
    gemm_h<0,0,0,1><<<dim3(3*E/128, (BATCH*PADS + 127)/128), 256, GEMM_SMEM>>>(
        emb16, E, qkvw16, E, qkv_b, nullptr, qkv16, 3*E, nullptr, 0,
        BATCH*PADS, 3*E);

    // --- layer-0 attention ---
    attn0_k<<<dim3(8, NW), 64>>>(qkv16, octx16);

    // --- layer-0 attn-out + residual gather -> LN1 ---
    gemm_h<0,2,1,0><<<dim3(E/128, NT/128), 256, GEMM_SMEM>>>(
        octx16, E, aow16, E, attn_out_b, x1a, nullptr, E, emb32, E, NT, E);
    ln_k<<<NT / 8, 256>>>(x1a, ln1_g, ln1_b, x1_32, x1_16, NT);

    // --- layer-0 FFN ---
    gemm_h<1,0,0,1><<<dim3(FF/128, NT/128), 256, GEMM_SMEM>>>(
        x1_16, E, f1w16, E, ffn1_b, nullptr, h16, FF, nullptr, 0, NT, FF);
    gemm_h<0,1,1,0><<<dim3(E/128, NT/128), 256, GEMM_SMEM>>>(
        h16, FF, f2w16, FF, ffn2_b, x1a, nullptr, E, x1_32, E, NT, E);
    ln_k<<<NT / 8, 256>>>(x1a, ln2_g, ln2_b, x2_32, x2_16, NT);

    // --- layer-1: K,V all tokens; Q last tokens only ---
    gemm_h<0,0,0,1><<<dim3(2*E/128, NT/128), 256, GEMM_SMEM>>>(
        x2_16, E, qkvw16 + (size_t)3*E*E + (size_t)E*E, E,
        qkv_b + 3*E + E, nullptr, kv16, 2*E, nullptr, 0, NT, 2*E);
    gemm_h<0,0,0,1><<<dim3(E/128, NW/128), 256, GEMM_SMEM>>>(
        x2_16 + (size_t)(WCTX-1)*E, WCTX*E,
        qkvw16 + (size_t)3*E*E, E, qkv_b + 3*E,
        nullptr, q1_16, E, nullptr, 0, NW, E);

    attn1_k<<<NW, 256>>>(q1_16, kv16, o1_16);

    // --- layer-1 tail ---
    gemm_h<0,1,1,0><<<dim3(E/128, NW/128), 256, GEMM_SMEM>>>(
        o1_16, E, aow16 + (size_t)E*E, E, attn_out_b + E,
        t1a, nullptr, E, x2_32 + (size_t)(WCTX-1)*E, WCTX*E, NW, E);
    ln_k<<<NW / 8, 256>>>(t1a, ln1_g + E, ln1_b + E, t1_32, t1_16, NW);
    gemm_h<1,0,0,1><<<dim3(FF/128, NW/128), 256, GEMM_SMEM>>>(
        t1_16, E, f1w16 + (size_t)FF*E, E, ffn1_b + FF,
        nullptr, th16, FF, nullptr, 0, NW, FF);
    gemm_h<0,1,1,0><<<dim3(E/128, NW/128), 256, GEMM_SMEM>>>(
        th16, FF, f2w16 + (size_t)E*FF, FF, ffn2_b + E,
        t1a, nullptr, E, t1_32, E, NW, E);
    ln_k<<<NW / 8, 256>>>(t1a, ln2_g + E, ln2_b + E, t2, th16 /*scratch*/, NW);

    // --- head (N=10, fp32) ---
    gemm_head<<<dim3(1, NW/64), 256>>>(
        t2, E, head_w, E, head_b, out, 10, NW, 10);
}

// round 12
// speedup vs baseline: 5.7571x; 1.3575x over previous
#include <cuda_runtime.h>
#include <cuda_fp16.h>
#include <math.h>
#include <stdint.h>

// ---------------------------------------------------------------------------
// Round 12: tensor-core attn0 (warp = head, CTA = window). S=QK^T via mma,
// register softmax, S-accumulators reused in-register as PV A-fragments,
// V through ldmatrix.trans. GEMM pipeline unchanged from R11.
// ---------------------------------------------------------------------------

#define BATCH 2
#define SEQ   1024
#define E     256
#define FIN   64
#define FF    1024
#define WCTX  64
#define NW    (BATCH*SEQ)
#define PADS  (SEQ + WCTX - 1)
#define NT    (NW*WCTX)

#define ATTN_SCALE 0.17677669529663687f

// ---------------- scratch ----------------------------------------------------
__device__ __align__(128) float g_emb32[BATCH*PADS*E];
__device__ __align__(128) float g_x1a  [NT*E];
__device__ __align__(128) float g_x1_32[NT*E];
__device__ __align__(128) float g_x2_32[NT*E];
__device__ __align__(128) float g_t1a  [NW*E];
__device__ __align__(128) float g_t1_32[NW*E];
__device__ __align__(128) float g_t2   [NW*E];
__device__ __align__(128) __half g_in16  [BATCH*SEQ*FIN];
__device__ __align__(128) __half g_embw16[E*FIN];
__device__ __align__(128) __half g_qkvw16[2*3*E*E];
__device__ __align__(128) __half g_aow16 [2*E*E];
__device__ __align__(128) __half g_f1w16 [2*FF*E];
__device__ __align__(128) __half g_f2w16 [2*E*FF];
__device__ __align__(128) __half g_emb16 [BATCH*PADS*E];
__device__ __align__(128) __half g_qkv16 [BATCH*PADS*3*E];
__device__ __align__(128) __half g_octx16[NT*E];
__device__ __align__(128) __half g_x1_16 [NT*E];
__device__ __align__(128) __half g_h16   [NT*FF];
__device__ __align__(128) __half g_x2_16 [NT*E];
__device__ __align__(128) __half g_kv16  [NT*2*E];
__device__ __align__(128) __half g_q1_16 [NW*E];
__device__ __align__(128) __half g_o1_16 [NW*E];
__device__ __align__(128) __half g_t1_16 [NW*E];
__device__ __align__(128) __half g_th16  [NW*FF];

__global__ void conv_k(const float* __restrict__ src, __half* __restrict__ dst,
                       int total) {
    int idx = blockIdx.x * 256 + threadIdx.x;
    if (idx < total) dst[idx] = __float2half(src[idx]);
}

__global__ void zero_pad_k(float* emb32, __half* emb16) {
    int i = blockIdx.x * 256 + threadIdx.x;
    if (i < (WCTX - 1) * E) {
        emb32[i] = 0.f;                 emb16[i] = __float2half(0.f);
        emb32[(size_t)PADS * E + i] = 0.f;
        emb16[(size_t)PADS * E + i] = __float2half(0.f);
    }
}

// ---------------- shared MMA / ldmatrix macros --------------------------------
#define MMA_F16(d, a0, a1, a2, a3, b0, b1) \
  asm volatile("mma.sync.aligned.m16n8k16.row.col.f32.f16.f16.f32 " \
    "{%0,%1,%2,%3}, {%4,%5,%6,%7}, {%8,%9}, {%0,%1,%2,%3};" \
    : "+f"(d[0]), "+f"(d[1]), "+f"(d[2]), "+f"(d[3]) \
    : "r"(a0), "r"(a1), "r"(a2), "r"(a3), "r"(b0), "r"(b1))

#define LDSM_X4(r0, r1, r2, r3, ad) \
  asm volatile("ldmatrix.sync.aligned.m8n8.x4.shared.b16 {%0,%1,%2,%3}, [%4];" \
    : "=r"(r0), "=r"(r1), "=r"(r2), "=r"(r3) : "r"(ad))

#define LDSM_X4T(r0, r1, r2, r3, ad) \
  asm volatile("ldmatrix.sync.aligned.m8n8.x4.trans.shared.b16 {%0,%1,%2,%3}, [%4];" \
    : "=r"(r0), "=r"(r1), "=r"(r2), "=r"(r3) : "r"(ad))

// ---------------- fp16 tensor-core GEMM (R11, unchanged) ----------------------
#define T_TSB 16384
#define NSTG 3
#define GEMM_SMEM (2*NSTG*T_TSB)

#define LOAD_TILE(KT_IDX, ST) do {                                            \
    if ((KT_IDX) < KT) {                                                      \
        const unsigned abase_ = smbase + (unsigned)(ST) * T_TSB;              \
        const unsigned bbase_ = smbase + (unsigned)NSTG * T_TSB + (unsigned)(ST) * T_TSB; \
        const __half* Ak_ = A + (size_t)(KT_IDX) * 64;                        \
        const __half* Bk_ = Wt + (size_t)(KT_IDX) * 64;                       \
        _Pragma("unroll")                                                     \
        for (int i_ = 0; i_ < 4; i_++) {                                      \
            const int c_   = tid + 256 * i_;                                  \
            const int row_ = c_ >> 3;                                         \
            const int ch_  = c_ & 7;                                          \
            const unsigned soff_ = (unsigned)(row_ * 128 + ((ch_ ^ (row_ & 7)) * 16)); \
            const int am_  = bm0 + row_;                                      \
            const __half* sa_ = Ak_ + (size_t)(am_ < M ? am_ : 0) * lda + ch_ * 8; \
            const int sz_     = (am_ < M) ? 16 : 0;                           \
            asm volatile("cp.async.cg.shared.global [%0], [%1], 16, %2;" ::   \
                "r"(abase_ + soff_), "l"(sa_), "r"(sz_));                     \
            const __half* sb_ = Bk_ + (size_t)(bn0 + row_) * K + ch_ * 8;     \
            asm volatile("cp.async.cg.shared.global [%0], [%1], 16;" ::       \
                "r"(bbase_ + soff_), "l"(sb_));                               \
        }                                                                     \
    }                                                                         \
    asm volatile("cp.async.commit_group;");                                   \
} while (0)

#define COMPUTE_TILE(ST) do {                                                 \
    const unsigned abase_ = smbase + (unsigned)(ST) * T_TSB;                  \
    const unsigned bbase_ = smbase + (unsigned)NSTG * T_TSB + (unsigned)(ST) * T_TSB; \
    _Pragma("unroll")                                                         \
    for (int kk_ = 0; kk_ < 4; kk_++) {                                       \
        const int chl_ = 2 * kk_ + (lane >> 4);                               \
        unsigned Ar[4][4];                                                    \
        unsigned Br[2][4];                                                    \
        _Pragma("unroll")                                                     \
        for (int mt_ = 0; mt_ < 4; mt_++) {                                   \
            const int r_ = wm + mt_ * 16 + (lane & 15);                       \
            LDSM_X4(Ar[mt_][0], Ar[mt_][1], Ar[mt_][2], Ar[mt_][3],           \
                    abase_ + (unsigned)(r_ * 128 + ((chl_ ^ (r_ & 7)) * 16)));\
        }                                                                     \
        _Pragma("unroll")                                                     \
        for (int np_ = 0; np_ < 2; np_++) {                                   \
            const int r_ = wn + np_ * 16 + (lane & 15);                       \
            LDSM_X4(Br[np_][0], Br[np_][1], Br[np_][2], Br[np_][3],           \
                    bbase_ + (unsigned)(r_ * 128 + ((chl_ ^ (r_ & 7)) * 16)));\
        }                                                                     \
        _Pragma("unroll")                                                     \
        for (int mt_ = 0; mt_ < 4; mt_++)                                     \
            _Pragma("unroll")                                                 \
            for (int np_ = 0; np_ < 2; np_++) {                               \
                MMA_F16(acc[mt_][np_ * 2 + 0], Ar[mt_][0], Ar[mt_][1],        \
                        Ar[mt_][2], Ar[mt_][3], Br[np_][0], Br[np_][2]);      \
                MMA_F16(acc[mt_][np_ * 2 + 1], Ar[mt_][0], Ar[mt_][1],        \
                        Ar[mt_][2], Ar[mt_][3], Br[np_][1], Br[np_][3]);      \
            }                                                                 \
    }                                                                         \
} while (0)

template<int ACT, int RES, int O32, int O16>
__global__ void __launch_bounds__(256, 2) gemm_h(
    const __half* __restrict__ A, int lda,
    const __half* __restrict__ Wt, int K,
    const float* __restrict__ bias,
    float* __restrict__ C32, __half* __restrict__ C16, int ldc,
    const float* __restrict__ res, int ldres,
    int M, int N)
{
    extern __shared__ __half smh[];
    const int tid  = threadIdx.x;
    const int bm0  = blockIdx.y * 128;
    const int bn0  = blockIdx.x * 128;
    const int lane = tid & 31, warp = tid >> 5;
    const int wm = (warp & 1) * 64;
    const int wn = (warp >> 1) * 32;
    const int gid = lane >> 2, tig = lane & 3;

    const unsigned smbase = (unsigned)__cvta_generic_to_shared(smh);

    float acc[4][4][4];
#pragma unroll
    for (int i = 0; i < 4; i++)
#pragma unroll
        for (int j = 0; j < 4; j++)
#pragma unroll
            for (int r = 0; r < 4; r++) acc[i][j][r] = 0.f;

    const int KT = K >> 6;

    LOAD_TILE(0, 0);
    LOAD_TILE(1, 1);

    for (int kt = 0; kt < KT; kt++) {
        asm volatile("cp.async.wait_group 1;");
        __syncthreads();
        LOAD_TILE(kt + 2, (kt + 2) % 3);
        COMPUTE_TILE(kt % 3);
    }

#pragma unroll
    for (int mt = 0; mt < 4; mt++) {
        const int mbase = bm0 + wm + mt * 16 + gid;
#pragma unroll
        for (int half_ = 0; half_ < 2; half_++) {
            const int m = mbase + half_ * 8;
            if (m >= M) continue;
#pragma unroll
            for (int nt = 0; nt < 4; nt++) {
                const int n = bn0 + wn + nt * 8 + tig * 2;
                const float2 bv = *(const float2*)(bias + n);
                float v0 = acc[mt][nt][half_ * 2 + 0] + bv.x;
                float v1 = acc[mt][nt][half_ * 2 + 1] + bv.y;
                if (RES == 1) {
                    const float2 r = *(const float2*)(res + (size_t)m * ldres + n);
                    v0 += r.x; v1 += r.y;
                }
                if (RES == 2) {
                    const int nw = m >> 6, w = m & 63;
                    const int b = nw >> 10, s = nw & 1023;
                    const float* rp = res + ((size_t)(b * PADS + s + w)) * ldres + n;
                    v0 += rp[0]; v1 += rp[1];
                }
                if (ACT == 1) {
                    v0 = v0 / (1.f + __expf(-v0));
                    v1 = v1 / (1.f + __expf(-v1));
                }
                if (O32)
                    *(float2*)(C32 + (size_t)m * ldc + n) = make_float2(v0, v1);
                if (O16)
                    *(__half2*)(C16 + (size_t)m * ldc + n) =
                        __float22half2_rn(make_float2(v0, v1));
            }
        }
    }
}

// ---------------- small fp32 GEMM (head only, N=10) --------------------------
__global__ void __launch_bounds__(256) gemm_head(
    const float* __restrict__ A, int lda,
    const float* __restrict__ Wt, int K,
    const float* __restrict__ bias,
    float* __restrict__ C, int ldc, int M, int N)
{
    __shared__ float As[16][68];
    __shared__ float Bs[16][68];
    const int tid = threadIdx.x;
    const int m0 = blockIdx.y * 64;
    const int lr = tid >> 2;
    const int lc = (tid & 3) << 2;
    const int ty = tid >> 4;
    const int tx = tid & 15;

    float acc[4][4];
#pragma unroll
    for (int i = 0; i < 4; i++)
#pragma unroll
        for (int j = 0; j < 4; j++) acc[i][j] = 0.f;

    const int am = m0 + lr;
    const float* Aptr = A + (size_t)am * lda + lc;
    const float* Wptr = Wt + (size_t)lr * K + lc;
    const bool avalid = (am < M);
    const bool bvalid = (lr < N);

    for (int k0 = 0; k0 < K; k0 += 16) {
        float4 av = make_float4(0.f, 0.f, 0.f, 0.f);
        float4 bv = make_float4(0.f, 0.f, 0.f, 0.f);
        if (avalid) av = *(const float4*)(Aptr + k0);
        if (bvalid) bv = *(const float4*)(Wptr + k0);
        As[lc+0][lr] = av.x; As[lc+1][lr] = av.y;
        As[lc+2][lr] = av.z; As[lc+3][lr] = av.w;
        Bs[lc+0][lr] = bv.x; Bs[lc+1][lr] = bv.y;
        Bs[lc+2][lr] = bv.z; Bs[lc+3][lr] = bv.w;
        __syncthreads();
#pragma unroll
        for (int kk = 0; kk < 16; kk++) {
            float4 a4 = *(const float4*)&As[kk][ty << 2];
            float4 b4 = *(const float4*)&Bs[kk][tx << 2];
            float ar[4] = {a4.x, a4.y, a4.z, a4.w};
            float br[4] = {b4.x, b4.y, b4.z, b4.w};
#pragma unroll
            for (int i = 0; i < 4; i++)
#pragma unroll
                for (int j = 0; j < 4; j++)
                    acc[i][j] = fmaf(ar[i], br[j], acc[i][j]);
        }
        __syncthreads();
    }

#pragma unroll
    for (int i = 0; i < 4; i++) {
        int m = m0 + (ty << 2) + i;
        if (m >= M) continue;
#pragma unroll
        for (int j = 0; j < 4; j++) {
            int n = (tx << 2) + j;
            if (n >= N) continue;
            C[(size_t)m * ldc + n] = acc[i][j] + bias[n];
        }
    }
}

// ---------------- tensor-core layer-0 attention -------------------------------
// CTA = one window (64 tokens), warp = one head. QKV rows staged once in smem
// ([64][776] halves; odd 16B stride -> conflict-free ldmatrix, no swizzle).
#define ATT_STR 776
#define ATT_SMEM (64*ATT_STR*2)     /* 99328 B */

__global__ void __launch_bounds__(256) attn0_tc(const __half* __restrict__ qkv16,
                                                __half* __restrict__ octx16) {
    extern __shared__ __half sma[];
    const unsigned smb = (unsigned)__cvta_generic_to_shared(sma);
    const int n = blockIdx.x, b = n >> 10, s = n & 1023;
    const int tid = threadIdx.x, lane = tid & 31, h = tid >> 5;
    const int gid = lane >> 2, tig = lane & 3;
    const int lrow = lane & 15, lch = lane >> 4;

    // stage 64 rows x 768 halves (96 x 16B chunks per row)
#pragma unroll
    for (int i = 0; i < 24; i++) {
        const int c = tid + 256 * i;
        const int row = c / 96, ch = c - row * 96;
        const __half* src = qkv16 + (size_t)(b * PADS + s + row) * 768 + ch * 8;
        asm volatile("cp.async.cg.shared.global [%0], [%1], 16;" ::
            "r"(smb + (unsigned)((row * ATT_STR + ch * 8) * 2)), "l"(src));
    }
    asm volatile("cp.async.commit_group;");
    asm volatile("cp.async.wait_group 0;");
    __syncthreads();

    // ---- S = Q K^T  (64x64, K=32) ----
    float sacc[4][8][4];
#pragma unroll
    for (int i = 0; i < 4; i++)
#pragma unroll
        for (int j = 0; j < 8; j++)
#pragma unroll
            for (int r = 0; r < 4; r++) sacc[i][j][r] = 0.f;

#pragma unroll
    for (int kk = 0; kk < 2; kk++) {
        unsigned qa[4][4], kb[4][4];
        const int kcol = h * 32 + kk * 16 + lch * 8;
#pragma unroll
        for (int mt = 0; mt < 4; mt++)
            LDSM_X4(qa[mt][0], qa[mt][1], qa[mt][2], qa[mt][3],
                    smb + (unsigned)(((mt * 16 + lrow) * ATT_STR + kcol) * 2));
#pragma unroll
        for (int kt = 0; kt < 4; kt++)
            LDSM_X4(kb[kt][0], kb[kt][1], kb[kt][2], kb[kt][3],
                    smb + (unsigned)(((kt * 16 + lrow) * ATT_STR + 256 + kcol) * 2));
#pragma unroll
        for (int mt = 0; mt < 4; mt++)
#pragma unroll
            for (int kt = 0; kt < 4; kt++) {
                MMA_F16(sacc[mt][kt * 2 + 0], qa[mt][0], qa[mt][1], qa[mt][2], qa[mt][3],
                        kb[kt][0], kb[kt][2]);
                MMA_F16(sacc[mt][kt * 2 + 1], qa[mt][0], qa[mt][1], qa[mt][2], qa[mt][3],
                        kb[kt][1], kb[kt][3]);
            }
    }

    // ---- register softmax (rows live in 4-lane quads) ----
#pragma unroll
    for (int mt = 0; mt < 4; mt++)
#pragma unroll
        for (int rh = 0; rh < 2; rh++) {
            float mx = -1e30f;
#pragma unroll
            for (int nt = 0; nt < 8; nt++)
                mx = fmaxf(mx, fmaxf(sacc[mt][nt][rh * 2], sacc[mt][nt][rh * 2 + 1]));
            mx = fmaxf(mx, __shfl_xor_sync(0xffffffffu, mx, 1));
            mx = fmaxf(mx, __shfl_xor_sync(0xffffffffu, mx, 2));
            float sum = 0.f;
#pragma unroll
            for (int nt = 0; nt < 8; nt++) {
                float e0 = __expf((sacc[mt][nt][rh * 2 + 0] - mx) * ATTN_SCALE);
                float e1 = __expf((sacc[mt][nt][rh * 2 + 1] - mx) * ATTN_SCALE);
                sacc[mt][nt][rh * 2 + 0] = e0;
                sacc[mt][nt][rh * 2 + 1] = e1;
                sum += e0 + e1;
            }
            sum += __shfl_xor_sync(0xffffffffu, sum, 1);
            sum += __shfl_xor_sync(0xffffffffu, sum, 2);
            const float inv = 1.f / sum;
#pragma unroll
            for (int nt = 0; nt < 8; nt++) {
                sacc[mt][nt][rh * 2 + 0] *= inv;
                sacc[mt][nt][rh * 2 + 1] *= inv;
            }
        }

    // ---- O = P V  (64x32, K=64); P packed in-register as A-fragments ----
    float oacc[4][4][4];
#pragma unroll
    for (int i = 0; i < 4; i++)
#pragma unroll
        for (int j = 0; j < 4; j++)
#pragma unroll
            for (int r = 0; r < 4; r++) oacc[i][j][r] = 0.f;

#pragma unroll
    for (int j = 0; j < 4; j++) {
        unsigned vb[2][4];
#pragma unroll
        for (int dc = 0; dc < 2; dc++)
            LDSM_X4T(vb[dc][0], vb[dc][1], vb[dc][2], vb[dc][3],
                     smb + (unsigned)(((j * 16 + lrow) * ATT_STR + 512 + h * 32
                                       + dc * 16 + lch * 8) * 2));
#pragma unroll
        for (int mt = 0; mt < 4; mt++) {
            __half2 h0 = __float22half2_rn(make_float2(sacc[mt][2*j][0],   sacc[mt][2*j][1]));
            __half2 h1 = __float22half2_rn(make_float2(sacc[mt][2*j][2],   sacc[mt][2*j][3]));
            __half2 h2 = __float22half2_rn(make_float2(sacc[mt][2*j+1][0], sacc[mt][2*j+1][1]));
            __half2 h3 = __float22half2_rn(make_float2(sacc[mt][2*j+1][2], sacc[mt][2*j+1][3]));
            const unsigned a0 = *(unsigned*)&h0, a1 = *(unsigned*)&h1;
            const unsigned a2 = *(unsigned*)&h2, a3 = *(unsigned*)&h3;
#pragma unroll
            for (int dc = 0; dc < 2; dc++) {
                MMA_F16(oacc[mt][dc * 2 + 0], a0, a1, a2, a3, vb[dc][0], vb[dc][1]);
                MMA_F16(oacc[mt][dc * 2 + 1], a0, a1, a2, a3, vb[dc][2], vb[dc][3]);
            }
        }
    }

    // ---- write O (head slice, fp16) ----
#pragma unroll
    for (int mt = 0; mt < 4; mt++)
#pragma unroll
        for (int rh = 0; rh < 2; rh++) {
            const int q = mt * 16 + gid + rh * 8;
            __half* orow = octx16 + ((size_t)n * 64 + q) * E + h * 32;
#pragma unroll
            for (int on = 0; on < 4; on++) {
                __half2 o = __float22half2_rn(
                    make_float2(oacc[mt][on][rh * 2 + 0], oacc[mt][on][rh * 2 + 1]));
                *(__half2*)(orow + on * 8 + tig * 2) = o;
            }
        }
}

// ---------------- layer-1 attention ------------------------------------------
__global__ void __launch_bounds__(256) attn1_k(const __half* __restrict__ q1,
                                               const __half* __restrict__ kv1,
                                               __half* __restrict__ o1) {
    const int n = blockIdx.x;
    const int h = threadIdx.x >> 5, l = threadIdx.x & 31;
    __shared__ float qs[256];
    __shared__ float ps[8][64];
    qs[threadIdx.x] = __half2float(q1[(size_t)n * E + threadIdx.x]);
    __syncthreads();

    const __half* kvb = kv1 + (size_t)n * 64 * (2 * E);
    const float* qh  = &qs[h * 32];
    const __half2* k0p = (const __half2*)(kvb + (size_t)l * (2 * E) + h * 32);
    const __half2* k1p = (const __half2*)(kvb + (size_t)(l + 32) * (2 * E) + h * 32);
    float s0 = 0.f, s1 = 0.f;
#pragma unroll
    for (int d = 0; d < 16; d++) {
        const float2 a = __half22float2(k0p[d]);
        const float2 b = __half22float2(k1p[d]);
        s0 = fmaf(qh[2*d], a.x, s0); s0 = fmaf(qh[2*d+1], a.y, s0);
        s1 = fmaf(qh[2*d], b.x, s1); s1 = fmaf(qh[2*d+1], b.y, s1);
    }
    s0 *= ATTN_SCALE; s1 *= ATTN_SCALE;
    float m = fmaxf(s0, s1);
#pragma unroll
    for (int o = 16; o; o >>= 1) m = fmaxf(m, __shfl_xor_sync(0xffffffffu, m, o));
    float e0 = __expf(s0 - m), e1 = __expf(s1 - m);
    float sum = e0 + e1;
#pragma unroll
    for (int o = 16; o; o >>= 1) sum += __shfl_xor_sync(0xffffffffu, sum, o);
    const float inv = 1.f / sum;
    ps[h][l] = e0 * inv;
    ps[h][l + 32] = e1 * inv;
    __syncwarp();

    float acc = 0.f;
#pragma unroll 4
    for (int k = 0; k < 64; k++)
        acc = fmaf(ps[h][k], __half2float(kvb[(size_t)k * (2 * E) + E + h * 32 + l]), acc);
    o1[(size_t)n * E + h * 32 + l] = __float2half(acc);
}

// ---------------- LayerNorm: fp32 in -> fp32 + fp16 out ----------------------
__global__ void __launch_bounds__(256) ln_k(const float* __restrict__ X,
                                            const float* __restrict__ g,
                                            const float* __restrict__ bb,
                                            float* __restrict__ Y32,
                                            __half* __restrict__ Y16, int M) {
    const int warp = threadIdx.x >> 5, lane = threadIdx.x & 31;
    const int row = blockIdx.x * 8 + warp;
    if (row >= M) return;
    const float* x = X + (size_t)row * E;
    float2 v[4];
    float s = 0.f;
#pragma unroll
    for (int i = 0; i < 4; i++) {
        v[i] = *(const float2*)(x + 2 * (lane + i * 32));
        s += v[i].x + v[i].y;
    }
#pragma unroll
    for (int o = 16; o; o >>= 1) s += __shfl_xor_sync(0xffffffffu, s, o);
    const float mean = s * (1.f / E);
    float var = 0.f;
#pragma unroll
    for (int i = 0; i < 4; i++) {
        float dx = v[i].x - mean, dy = v[i].y - mean;
        var = fmaf(dx, dx, var); var = fmaf(dy, dy, var);
    }
#pragma unroll
    for (int o = 16; o; o >>= 1) var += __shfl_xor_sync(0xffffffffu, var, o);
    const float inv = rsqrtf(var * (1.f / E) + 1e-5f);
#pragma unroll
    for (int i = 0; i < 4; i++) {
        const int c0 = 2 * (lane + i * 32);
        const float2 gg = *(const float2*)(g + c0);
        const float2 bv = *(const float2*)(bb + c0);
        float y0 = (v[i].x - mean) * inv * gg.x + bv.x;
        float y1 = (v[i].y - mean) * inv * gg.y + bv.y;
        *(float2*)(Y32 + (size_t)row * E + c0) = make_float2(y0, y1);
        *(__half2*)(Y16 + (size_t)row * E + c0) =
            __float22half2_rn(make_float2(y0, y1));
    }
}

// ---------------------------------------------------------------------------
extern "C" void kernel_launch(void* const* d_in, const int* in_sizes, int n_in,
                              void* d_out, int out_size) {
    (void)in_sizes; (void)n_in; (void)out_size;
    const float* inputs     = (const float*)d_in[0];
    const float* embed_w    = (const float*)d_in[1];
    const float* embed_b    = (const float*)d_in[2];
    const float* qkv_w      = (const float*)d_in[3];
    const float* qkv_b      = (const float*)d_in[4];
    const float* attn_out_w = (const float*)d_in[5];
    const float* attn_out_b = (const float*)d_in[6];
    const float* ln1_g      = (const float*)d_in[7];
    const float* ln1_b      = (const float*)d_in[8];
    const float* ffn1_w     = (const float*)d_in[9];
    const float* ffn1_b     = (const float*)d_in[10];
    const float* ffn2_w     = (const float*)d_in[11];
    const float* ffn2_b     = (const float*)d_in[12];
    const float* ln2_g      = (const float*)d_in[13];
    const float* ln2_b      = (const float*)d_in[14];
    const float* head_w     = (const float*)d_in[15];
    const float* head_b     = (const float*)d_in[16];
    float* out = (float*)d_out;

    float *emb32, *x1a, *x1_32, *x2_32, *t1a, *t1_32, *t2;
    __half *in16, *embw16, *qkvw16, *aow16, *f1w16, *f2w16;
    __half *emb16, *qkv16, *octx16, *x1_16, *h16, *x2_16, *kv16;
    __half *q1_16, *o1_16, *t1_16, *th16;
    cudaGetSymbolAddress((void**)&emb32, g_emb32);
    cudaGetSymbolAddress((void**)&x1a,   g_x1a);
    cudaGetSymbolAddress((void**)&x1_32, g_x1_32);
    cudaGetSymbolAddress((void**)&x2_32, g_x2_32);
    cudaGetSymbolAddress((void**)&t1a,   g_t1a);
    cudaGetSymbolAddress((void**)&t1_32, g_t1_32);
    cudaGetSymbolAddress((void**)&t2,    g_t2);
    cudaGetSymbolAddress((void**)&in16,  g_in16);
    cudaGetSymbolAddress((void**)&embw16,g_embw16);
    cudaGetSymbolAddress((void**)&qkvw16,g_qkvw16);
    cudaGetSymbolAddress((void**)&aow16, g_aow16);
    cudaGetSymbolAddress((void**)&f1w16, g_f1w16);
    cudaGetSymbolAddress((void**)&f2w16, g_f2w16);
    cudaGetSymbolAddress((void**)&emb16, g_emb16);
    cudaGetSymbolAddress((void**)&qkv16, g_qkv16);
    cudaGetSymbolAddress((void**)&octx16,g_octx16);
    cudaGetSymbolAddress((void**)&x1_16, g_x1_16);
    cudaGetSymbolAddress((void**)&h16,   g_h16);
    cudaGetSymbolAddress((void**)&x2_16, g_x2_16);
    cudaGetSymbolAddress((void**)&kv16,  g_kv16);
    cudaGetSymbolAddress((void**)&q1_16, g_q1_16);
    cudaGetSymbolAddress((void**)&o1_16, g_o1_16);
    cudaGetSymbolAddress((void**)&t1_16, g_t1_16);
    cudaGetSymbolAddress((void**)&th16,  g_th16);

    cudaFuncSetAttribute(gemm_h<0,0,1,1>, cudaFuncAttributeMaxDynamicSharedMemorySize, GEMM_SMEM);
    cudaFuncSetAttribute(gemm_h<0,0,0,1>, cudaFuncAttributeMaxDynamicSharedMemorySize, GEMM_SMEM);
    cudaFuncSetAttribute(gemm_h<0,2,1,0>, cudaFuncAttributeMaxDynamicSharedMemorySize, GEMM_SMEM);
    cudaFuncSetAttribute(gemm_h<1,0,0,1>, cudaFuncAttributeMaxDynamicSharedMemorySize, GEMM_SMEM);
    cudaFuncSetAttribute(gemm_h<0,1,1,0>, cudaFuncAttributeMaxDynamicSharedMemorySize, GEMM_SMEM);
    cudaFuncSetAttribute(attn0_tc, cudaFuncAttributeMaxDynamicSharedMemorySize, ATT_SMEM);

    // --- weight / input conversion ---
    conv_k<<<(BATCH*SEQ*FIN + 255)/256, 256>>>(inputs, in16, BATCH*SEQ*FIN);
    conv_k<<<(E*FIN + 255)/256, 256>>>(embed_w, embw16, E*FIN);
    conv_k<<<(2*3*E*E + 255)/256, 256>>>(qkv_w, qkvw16, 2*3*E*E);
    conv_k<<<(2*E*E + 255)/256, 256>>>(attn_out_w, aow16, 2*E*E);
    conv_k<<<(2*FF*E + 255)/256, 256>>>(ffn1_w, f1w16, 2*FF*E);
    conv_k<<<(2*E*FF + 255)/256, 256>>>(ffn2_w, f2w16, 2*E*FF);

    // --- embeddings (zero-padded left by W-1) ---
    zero_pad_k<<<63, 256>>>(emb32, emb16);
    for (int b = 0; b < BATCH; b++) {
        gemm_h<0,0,1,1><<<dim3(E/128, SEQ/128), 256, GEMM_SMEM>>>(
            in16 + (size_t)b * SEQ * FIN, FIN, embw16, FIN, embed_b,
            emb32 + ((size_t)b * PADS + (WCTX - 1)) * E,
            emb16 + ((size_t)b * PADS + (WCTX - 1)) * E, E,
            nullptr, 0, SEQ, E);
    }

    // --- layer-0 QKV per global token ---
    gemm_h<0,0,0,1><<<dim3(3*E/128, (BATCH*PADS + 127)/128), 256, GEMM_SMEM>>>(
        emb16, E, qkvw16, E, qkv_b, nullptr, qkv16, 3*E, nullptr, 0,
        BATCH*PADS, 3*E);

    // --- layer-0 attention (tensor cores) ---
    attn0_tc<<<NW, 256, ATT_SMEM>>>(qkv16, octx16);

    // --- layer-0 attn-out + residual gather -> LN1 ---
    gemm_h<0,2,1,0><<<dim3(E/128, NT/128), 256, GEMM_SMEM>>>(
        octx16, E, aow16, E, attn_out_b, x1a, nullptr, E, emb32, E, NT, E);
    ln_k<<<NT / 8, 256>>>(x1a, ln1_g, ln1_b, x1_32, x1_16, NT);

    // --- layer-0 FFN ---
    gemm_h<1,0,0,1><<<dim3(FF/128, NT/128), 256, GEMM_SMEM>>>(
        x1_16, E, f1w16, E, ffn1_b, nullptr, h16, FF, nullptr, 0, NT, FF);
    gemm_h<0,1,1,0><<<dim3(E/128, NT/128), 256, GEMM_SMEM>>>(
        h16, FF, f2w16, FF, ffn2_b, x1a, nullptr, E, x1_32, E, NT, E);
    ln_k<<<NT / 8, 256>>>(x1a, ln2_g, ln2_b, x2_32, x2_16, NT);

    // --- layer-1: K,V all tokens; Q last tokens only ---
    gemm_h<0,0,0,1><<<dim3(2*E/128, NT/128), 256, GEMM_SMEM>>>(
        x2_16, E, qkvw16 + (size_t)3*E*E + (size_t)E*E, E,
        qkv_b + 3*E + E, nullptr, kv16, 2*E, nullptr, 0, NT, 2*E);
    gemm_h<0,0,0,1><<<dim3(E/128, NW/128), 256, GEMM_SMEM>>>(
        x2_16 + (size_t)(WCTX-1)*E, WCTX*E,
        qkvw16 + (size_t)3*E*E, E, qkv_b + 3*E,
        nullptr, q1_16, E, nullptr, 0, NW, E);

    attn1_k<<<NW, 256>>>(q1_16, kv16, o1_16);

    // --- layer-1 tail ---
    gemm_h<0,1,1,0><<<dim3(E/128, NW/128), 256, GEMM_SMEM>>>(
        o1_16, E, aow16 + (size_t)E*E, E, attn_out_b + E,
        t1a, nullptr, E, x2_32 + (size_t)(WCTX-1)*E, WCTX*E, NW, E);
    ln_k<<<NW / 8, 256>>>(t1a, ln1_g + E, ln1_b + E, t1_32, t1_16, NW);
    gemm_h<1,0,0,1><<<dim3(FF/128, NW/128), 256, GEMM_SMEM>>>(
        t1_16, E, f1w16 + (size_t)FF*E, E, ffn1_b + FF,
        nullptr, th16, FF, nullptr, 0, NW, FF);
    gemm_h<0,1,1,0><<<dim3(E/128, NW/128), 256, GEMM_SMEM>>>(
        th16, FF, f2w16 + (size_t)E*FF, FF, ffn2_b + E,
        t1a, nullptr, E, t1_32, E, NW, E);
    ln_k<<<NW / 8, 256>>>(t1a, ln2_g + E, ln2_b + E, t2, th16 /*scratch*/, NW);

    // --- head (N=10, fp32) ---
    gemm_head<<<dim3(1, NW/64), 256>>>(
        t2, E, head_w, E, head_b, out, 10, NW, 10);
}